// round 7
// baseline (speedup 1.0000x reference)
#include <cuda_runtime.h>
#include <cuda_bf16.h>
#include <cstdint>

#define B_  16
#define L_  1024
#define U_  512
#define M_  (B_*L_)      // 16384

typedef __nv_bfloat16  bf16;
typedef __nv_bfloat162 bf162;

// ---------------------------------------------------------------------------
// Scratch (device globals; no allocation allowed)
// ---------------------------------------------------------------------------
__device__ float g_x0[M_*U_];
__device__ float g_x1[M_*U_];
__device__ float g_t [M_*U_];           // t / z
__device__ float g_A [(size_t)B_*L_*L_];
__device__ float g_s1[M_];
__device__ float g_s2[M_];

__device__ bf16 g_ib  [M_*U_];          // inputs bf16
__device__ bf16 g_x0b [M_*U_];
__device__ bf16 g_x1b [M_*U_];
__device__ bf16 g_xw3 [M_*U_];          // x1 * w3 (bf16)
__device__ bf16 g_x1t [M_*U_];          // per-batch [U][L]
__device__ bf16 g_cat [(size_t)M_*2*U_];
__device__ bf16 g_Ab  [(size_t)B_*L_*L_];
__device__ bf16 g_tWt [2*U_*U_];
__device__ bf16 g_cWt [2*U_*U_];
__device__ bf16 g_ffWt[2*U_*U_];        // [512][1024]
__device__ bf16 g_frWt[2*U_*U_];        // [512][1024]

// ---------------------------------------------------------------------------
// PTX helpers (baseline PTX; compile at compute_103)
// ---------------------------------------------------------------------------
__device__ __forceinline__ uint32_t smem_u32(const void* p) {
    uint32_t a;
    asm("{ .reg .u64 t; cvta.to.shared.u64 t, %1; cvt.u32.u64 %0, t; }"
        : "=r"(a) : "l"(p));
    return a;
}
__device__ __forceinline__ void cpasync16(uint32_t dst, const void* src) {
    asm volatile("cp.async.cg.shared.global [%0], [%1], 16;"
                 :: "r"(dst), "l"(src));
}
#define CP_COMMIT() asm volatile("cp.async.commit_group;" ::: "memory")
#define CP_WAIT(n)  asm volatile("cp.async.wait_group %0;" :: "n"(n) : "memory")

#define LDSM4(r0, r1, r2, r3, addr) \
    asm volatile("ldmatrix.sync.aligned.m8n8.x4.shared.b16 {%0,%1,%2,%3}, [%4];" \
        : "=r"(r0), "=r"(r1), "=r"(r2), "=r"(r3) : "r"(addr))

__device__ __forceinline__ void mma_bf16(float* c, const uint32_t* a,
                                         uint32_t b0, uint32_t b1) {
    asm volatile(
        "mma.sync.aligned.m16n8k16.row.col.f32.bf16.bf16.f32 "
        "{%0,%1,%2,%3}, {%4,%5,%6,%7}, {%8,%9}, {%0,%1,%2,%3};"
        : "+f"(c[0]), "+f"(c[1]), "+f"(c[2]), "+f"(c[3])
        : "r"(a[0]), "r"(a[1]), "r"(a[2]), "r"(a[3]), "r"(b0), "r"(b1));
}

__device__ __forceinline__ float sigm(float v) {
    return 1.f / (1.f + __expf(-v));
}

// ---------------------------------------------------------------------------
// bf16 tensor-core GEMM with fused epilogues.
//   acc[m,n] = sum_k A[m,k]*Bt[n,k] + rowbias[m] + colbias[n] + addc
// mode 0: v = act(acc); store C fp32 (if) / Cb bf16 (if)
// mode 1: c = sigmoid(acc); x = e1*c + e2*(1-c); store C fp32 + Cb bf16
// mode 2: r = sigmoid(acc); o = r*e2 + e1*e1;    store C fp32
// Grid (N/128, M/128, batch), 256 threads, warp tile 64x32.
// 3-stage cp.async pipeline, KC=64, SW128 swizzle, ldmatrix frags.
// __launch_bounds__(256,2): cap regs at 128 so 2 CTAs/SM are resident
// (96KB smem x2 = 192KB <= 228KB) -> 4 warps/SMSP to hide HMMA latency.
// ---------------------------------------------------------------------------
#define KC 64
#define RB 128                 // row bytes (KC bf16)
#define STAGE_B (128*RB)       // 16 KB
#define NSTG 3

__global__ __launch_bounds__(256, 2) void gemm_bf(
    const bf16* __restrict__ A,  long lda, long sA,
    const bf16* __restrict__ Bt, long ldb, long sB,
    float* __restrict__ C, long ldc, long sC,
    bf16* __restrict__ Cb, long ldcb, long sCb,
    int K,
    const float* __restrict__ rowbias, long srb,
    const float* __restrict__ colbias, long scb,
    const float* __restrict__ addc,
    int act, int mode,
    const float* __restrict__ e1, const float* __restrict__ e2)
{
    extern __shared__ char smc[];
    const uint32_t as0 = smem_u32(smc);              // A: NSTG stages
    const uint32_t bs0 = as0 + NSTG * STAGE_B;       // B: NSTG stages

    const int tid  = threadIdx.x;
    const int wid  = tid >> 5;
    const int lane = tid & 31;
    const int li   = lane & 7;
    const int q    = lane >> 3;
    const int ql   = q & 1;
    const int qh   = q >> 1;
    const int m0   = (wid >> 2) * 64;
    const int n0   = (wid & 3)  * 32;

    const int bz = blockIdx.z;
    const int bm = blockIdx.y * 128;
    const int bn = blockIdx.x * 128;

    const bf16* Ag = A  + (long)bz * sA;
    const bf16* Bg = Bt + (long)bz * sB;

    const int lrow = tid >> 1;              // 0..127
    const int lcb  = (tid & 1) * 4;         // chunk base (of 8 per row)
    const int nch  = K / KC;

    float acc[4][4][4];
    #pragma unroll
    for (int i = 0; i < 4; i++)
        #pragma unroll
        for (int j = 0; j < 4; j++)
            #pragma unroll
            for (int k = 0; k < 4; k++) acc[i][j][k] = 0.f;

    auto load_chunk = [&](int c) {
        const int st = c % NSTG;
        const bf16* ap = Ag + (long)(bm + lrow) * lda + c * KC;
        const bf16* bp = Bg + (long)(bn + lrow) * ldb + c * KC;
        const uint32_t ad = as0 + st * STAGE_B + lrow * RB;
        const uint32_t bd = bs0 + st * STAGE_B + lrow * RB;
        const int sw = lrow & 7;
        #pragma unroll
        for (int j = 0; j < 4; j++) {
            const int ch = lcb + j;
            const int cho = (ch ^ sw) * 16;
            cpasync16(ad + cho, ap + ch * 8);
            cpasync16(bd + cho, bp + ch * 8);
        }
        CP_COMMIT();
    };

    load_chunk(0);
    if (nch > 1) load_chunk(1);

    // precomputed fragment rows
    int rA[4], nB[2];
    #pragma unroll
    for (int mt = 0; mt < 4; mt++) rA[mt] = m0 + mt * 16 + li + ql * 8;
    #pragma unroll
    for (int p = 0; p < 2; p++)    nB[p] = n0 + p * 16 + qh * 8 + li;

    for (int c = 0; c < nch; c++) {
        const int st = c % NSTG;
        if (c + 1 < nch) CP_WAIT(1); else CP_WAIT(0);
        __syncthreads();
        if (c + 2 < nch) load_chunk(c + 2);

        const uint32_t asb = as0 + st * STAGE_B;
        const uint32_t bsb = bs0 + st * STAGE_B;

        #pragma unroll
        for (int ks = 0; ks < 4; ks++) {
            uint32_t a[4][4];
            #pragma unroll
            for (int mt = 0; mt < 4; mt++) {
                const int r = rA[mt];
                const int ch = (ks * 2 + qh) ^ (r & 7);
                LDSM4(a[mt][0], a[mt][1], a[mt][2], a[mt][3],
                      asb + r * RB + ch * 16);
            }
            uint32_t b[2][4];
            #pragma unroll
            for (int p = 0; p < 2; p++) {
                const int n = nB[p];
                const int ch = (ks * 2 + ql) ^ (n & 7);
                LDSM4(b[p][0], b[p][1], b[p][2], b[p][3],
                      bsb + n * RB + ch * 16);
            }
            #pragma unroll
            for (int nt = 0; nt < 4; nt++) {
                const uint32_t b0 = b[nt >> 1][(nt & 1) * 2];
                const uint32_t b1 = b[nt >> 1][(nt & 1) * 2 + 1];
                #pragma unroll
                for (int mt = 0; mt < 4; mt++)
                    mma_bf16(acc[mt][nt], a[mt], b0, b1);
            }
        }
        __syncthreads();
    }

    // ---- epilogue ----
    const int grp = lane >> 2;     // 0..7
    const int tig = lane & 3;      // 0..3
    float* Cp  = C  ? C  + (long)bz * sC  : nullptr;
    bf16*  Cbp = Cb ? Cb + (long)bz * sCb : nullptr;
    const float a0 = addc ? addc[0] : 0.f;

    #pragma unroll
    for (int mt = 0; mt < 4; mt++) {
        const int row = bm + m0 + mt * 16 + grp;
        float rb0 = a0, rb8 = a0;
        if (rowbias) {
            rb0 += rowbias[(long)bz * srb + row];
            rb8 += rowbias[(long)bz * srb + row + 8];
        }
        #pragma unroll
        for (int nt = 0; nt < 4; nt++) {
            const int col = bn + n0 + nt * 8 + tig * 2;
            float cb0 = 0.f, cb1 = 0.f;
            if (colbias) {
                cb0 = colbias[(long)bz * scb + col];
                cb1 = colbias[(long)bz * scb + col + 1];
            }
            float v0 = acc[mt][nt][0] + rb0 + cb0;
            float v1 = acc[mt][nt][1] + rb0 + cb1;
            float v2 = acc[mt][nt][2] + rb8 + cb0;
            float v3 = acc[mt][nt][3] + rb8 + cb1;

            const long i0 = (long)row * ldc + col;
            const long i8 = (long)(row + 8) * ldc + col;

            if (mode == 0) {
                if (act == 1) {
                    v0 = fmaxf(v0, 0.f); v1 = fmaxf(v1, 0.f);
                    v2 = fmaxf(v2, 0.f); v3 = fmaxf(v3, 0.f);
                } else if (act == 2) {
                    v0 = sigm(v0); v1 = sigm(v1);
                    v2 = sigm(v2); v3 = sigm(v3);
                }
                if (Cp) {
                    *(float2*)(Cp + i0) = make_float2(v0, v1);
                    *(float2*)(Cp + i8) = make_float2(v2, v3);
                }
                if (Cbp) {
                    *(bf162*)(Cbp + (long)row * ldcb + col)       = __floats2bfloat162_rn(v0, v1);
                    *(bf162*)(Cbp + (long)(row + 8) * ldcb + col) = __floats2bfloat162_rn(v2, v3);
                }
            } else if (mode == 1) {
                // highway: x = t*c + xin*(1-c)
                v0 = sigm(v0); v1 = sigm(v1); v2 = sigm(v2); v3 = sigm(v3);
                const float2 t0 = *(const float2*)(e1 + i0);
                const float2 t8 = *(const float2*)(e1 + i8);
                const float2 x0v = *(const float2*)(e2 + i0);
                const float2 x8v = *(const float2*)(e2 + i8);
                const float o0 = t0.x * v0 + x0v.x * (1.f - v0);
                const float o1 = t0.y * v1 + x0v.y * (1.f - v1);
                const float o2 = t8.x * v2 + x8v.x * (1.f - v2);
                const float o3 = t8.y * v3 + x8v.y * (1.f - v3);
                *(float2*)(Cp + i0) = make_float2(o0, o1);
                *(float2*)(Cp + i8) = make_float2(o2, o3);
                *(bf162*)(Cbp + (long)row * ldcb + col)       = __floats2bfloat162_rn(o0, o1);
                *(bf162*)(Cbp + (long)(row + 8) * ldcb + col) = __floats2bfloat162_rn(o2, o3);
            } else {
                // final: out = r*inputs + z*z
                v0 = sigm(v0); v1 = sigm(v1); v2 = sigm(v2); v3 = sigm(v3);
                const float2 z0 = *(const float2*)(e1 + i0);
                const float2 z8 = *(const float2*)(e1 + i8);
                const float2 x0v = *(const float2*)(e2 + i0);
                const float2 x8v = *(const float2*)(e2 + i8);
                const float o0 = v0 * x0v.x + z0.x * z0.x;
                const float o1 = v1 * x0v.y + z0.y * z0.y;
                const float o2 = v2 * x8v.x + z8.x * z8.x;
                const float o3 = v3 * x8v.y + z8.y * z8.y;
                *(float2*)(Cp + i0) = make_float2(o0, o1);
                *(float2*)(Cp + i8) = make_float2(o2, o3);
            }
        }
    }
}

// ---------------------------------------------------------------------------
// fp32 -> bf16 transpose: dst[c][r] = src[r][c]; grid (C/32, R/32, batch)
// ---------------------------------------------------------------------------
__global__ __launch_bounds__(256) void transpose_b(
    const float* __restrict__ src, bf16* __restrict__ dst,
    int R, int Cc, long ssrc, long sdst)
{
    __shared__ float tile[32][33];
    src += (long)blockIdx.z * ssrc;
    dst += (long)blockIdx.z * sdst;
    const int r0 = blockIdx.y * 32, c0 = blockIdx.x * 32;
    const int tx = threadIdx.x & 31, ty = threadIdx.x >> 5;
    #pragma unroll
    for (int i = 0; i < 32; i += 8)
        tile[ty + i][tx] = src[(long)(r0 + ty + i) * Cc + c0 + tx];
    __syncthreads();
    #pragma unroll
    for (int i = 0; i < 32; i += 8)
        dst[(long)(c0 + ty + i) * R + r0 + tx] = __float2bfloat16(tile[tx][ty + i]);
}

// ---------------------------------------------------------------------------
// Small kernels
// ---------------------------------------------------------------------------
__global__ __launch_bounds__(256) void conv_inputs(
    const float* __restrict__ in, bf16* __restrict__ ib, bf16* __restrict__ cat)
{
    const int i = blockIdx.x * 256 + threadIdx.x;    // over M*U/4
    const float4 v = ((const float4*)in)[i];
    const bf162 p0 = __floats2bfloat162_rn(v.x, v.y);
    const bf162 p1 = __floats2bfloat162_rn(v.z, v.w);
    *(bf162*)(ib + (long)i * 4)     = p0;
    *(bf162*)(ib + (long)i * 4 + 2) = p1;
    const int m  = i >> 7;          // U/4 = 128
    const int c4 = i & 127;
    bf16* cr = cat + (long)m * (2 * U_) + c4 * 4;
    *(bf162*)cr       = p0;
    *(bf162*)(cr + 2) = p1;
}

__global__ __launch_bounds__(256) void mulw3_kernel(
    const float* __restrict__ x, const float* __restrict__ w3,
    bf16* __restrict__ y, int n4)
{
    const int i = blockIdx.x * blockDim.x + threadIdx.x;
    if (i >= n4) return;
    const int d4 = i & (U_ / 4 - 1);
    float4 v = ((const float4*)x)[i];
    const float4 w = *(const float4*)(w3 + d4 * 4);
    v.x *= w.x; v.y *= w.y; v.z *= w.z; v.w *= w.w;
    *(bf162*)(y + (long)i * 4)     = __floats2bfloat162_rn(v.x, v.y);
    *(bf162*)(y + (long)i * 4 + 2) = __floats2bfloat162_rn(v.z, v.w);
}

__global__ __launch_bounds__(256) void s1s2_kernel(
    const float* __restrict__ x, const float* __restrict__ aW,
    float* __restrict__ s1, float* __restrict__ s2)
{
    const int row  = blockIdx.x * 8 + (threadIdx.x >> 5);
    const int lane = threadIdx.x & 31;
    const float* xr = x + (long)row * U_;
    float a = 0.f, b = 0.f;
    for (int d = lane; d < U_; d += 32) {
        const float xv = xr[d];
        a += xv * aW[d];
        b += xv * aW[U_ + d];
    }
    #pragma unroll
    for (int o = 16; o > 0; o >>= 1) {
        a += __shfl_xor_sync(0xffffffffu, a, o);
        b += __shfl_xor_sync(0xffffffffu, b, o);
    }
    if (lane == 0) { s1[row] = a; s2[row] = b; }
}

__global__ __launch_bounds__(256) void softmax_b(
    const float* __restrict__ A, bf16* __restrict__ Ab)
{
    const float* row = A  + (long)blockIdx.x * L_;
    bf16*        orow = Ab + (long)blockIdx.x * L_;
    const int tid = threadIdx.x;
    __shared__ float red[256];

    float4 v = ((const float4*)row)[tid];
    float m = fmaxf(fmaxf(v.x, v.y), fmaxf(v.z, v.w));
    red[tid] = m; __syncthreads();
    for (int s = 128; s > 0; s >>= 1) {
        if (tid < s) red[tid] = fmaxf(red[tid], red[tid + s]);
        __syncthreads();
    }
    m = red[0]; __syncthreads();

    v.x = __expf(v.x - m); v.y = __expf(v.y - m);
    v.z = __expf(v.z - m); v.w = __expf(v.w - m);
    red[tid] = v.x + v.y + v.z + v.w; __syncthreads();
    for (int s = 128; s > 0; s >>= 1) {
        if (tid < s) red[tid] += red[tid + s];
        __syncthreads();
    }
    const float inv = 1.f / red[0];
    *(bf162*)(orow + (long)tid * 4)     = __floats2bfloat162_rn(v.x * inv, v.y * inv);
    *(bf162*)(orow + (long)tid * 4 + 2) = __floats2bfloat162_rn(v.z * inv, v.w * inv);
}

// ---------------------------------------------------------------------------
// Launch
// ---------------------------------------------------------------------------
#define GEMM_SMEM (2 * NSTG * STAGE_B)   // 96 KB

extern "C" void kernel_launch(void* const* d_in, const int* in_sizes, int n_in,
                              void* d_out, int out_size)
{
    (void)in_sizes; (void)n_in; (void)out_size;
    const float* inputs = (const float*)d_in[0];
    const float* tW     = (const float*)d_in[1];
    const float* tb     = (const float*)d_in[2];
    const float* cW     = (const float*)d_in[3];
    const float* cb     = (const float*)d_in[4];
    const float* aW     = (const float*)d_in[5];
    const float* ab     = (const float*)d_in[6];
    const float* frW    = (const float*)d_in[7];
    const float* frb    = (const float*)d_in[8];
    const float* ffW    = (const float*)d_in[9];
    const float* ffb    = (const float*)d_in[10];
    float* out = (float*)d_out;

    float *x0, *x1, *t, *Amat, *s1, *s2;
    bf16 *ib, *x0b, *x1b, *xw3, *x1t, *cat, *Ab, *tWt, *cWt, *ffWt, *frWt;
    cudaGetSymbolAddress((void**)&x0,   g_x0);
    cudaGetSymbolAddress((void**)&x1,   g_x1);
    cudaGetSymbolAddress((void**)&t,    g_t);
    cudaGetSymbolAddress((void**)&Amat, g_A);
    cudaGetSymbolAddress((void**)&s1,   g_s1);
    cudaGetSymbolAddress((void**)&s2,   g_s2);
    cudaGetSymbolAddress((void**)&ib,   g_ib);
    cudaGetSymbolAddress((void**)&x0b,  g_x0b);
    cudaGetSymbolAddress((void**)&x1b,  g_x1b);
    cudaGetSymbolAddress((void**)&xw3,  g_xw3);
    cudaGetSymbolAddress((void**)&x1t,  g_x1t);
    cudaGetSymbolAddress((void**)&cat,  g_cat);
    cudaGetSymbolAddress((void**)&Ab,   g_Ab);
    cudaGetSymbolAddress((void**)&tWt,  g_tWt);
    cudaGetSymbolAddress((void**)&cWt,  g_cWt);
    cudaGetSymbolAddress((void**)&ffWt, g_ffWt);
    cudaGetSymbolAddress((void**)&frWt, g_frWt);

    cudaFuncSetAttribute(gemm_bf, cudaFuncAttributeMaxDynamicSharedMemorySize,
                         GEMM_SMEM);

    const int n4  = M_ * U_ / 4;
    const int ewg = (n4 + 255) / 256;

    // weight conversions (fp32 -> bf16, transposed)
    transpose_b<<<dim3(16,16,2), 256>>>(tW, tWt, U_, U_, (long)U_*U_, (long)U_*U_);
    transpose_b<<<dim3(16,16,2), 256>>>(cW, cWt, U_, U_, (long)U_*U_, (long)U_*U_);
    transpose_b<<<dim3(16,32,1), 256>>>(ffW, ffWt, 2*U_, U_, 0, 0);
    transpose_b<<<dim3(16,32,1), 256>>>(frW, frWt, 2*U_, U_, 0, 0);
    conv_inputs<<<ewg, 256>>>(inputs, ib, cat);

    dim3 gHW(U_/128, M_/128, 1);   // (4,128)
    // highway layer 0: t-GEMM then fused sigmoid+combine GEMM
    gemm_bf<<<gHW, 256, GEMM_SMEM>>>(ib, U_, 0, tWt, U_, 0,
                                     t, U_, 0, nullptr, 0, 0, U_,
                                     nullptr, 0, tb, 0, nullptr, 1, 0, nullptr, nullptr);
    gemm_bf<<<gHW, 256, GEMM_SMEM>>>(ib, U_, 0, cWt, U_, 0,
                                     x0, U_, 0, x0b, U_, 0, U_,
                                     nullptr, 0, cb, 0, nullptr, 2, 1, t, inputs);
    // highway layer 1
    gemm_bf<<<gHW, 256, GEMM_SMEM>>>(x0b, U_, 0, tWt + U_*U_, U_, 0,
                                     t, U_, 0, nullptr, 0, 0, U_,
                                     nullptr, 0, tb + U_, 0, nullptr, 1, 0, nullptr, nullptr);
    gemm_bf<<<gHW, 256, GEMM_SMEM>>>(x0b, U_, 0, cWt + U_*U_, U_, 0,
                                     x1, U_, 0, x1b, U_, 0, U_,
                                     nullptr, 0, cb + U_, 0, nullptr, 2, 1, t, x0);

    // s1, s2, xw3, x1^T
    s1s2_kernel<<<M_/8, 256>>>(x1, aW, s1, s2);
    mulw3_kernel<<<ewg, 256>>>(x1, aW + 2*U_, xw3, n4);
    transpose_b<<<dim3(16,32,B_), 256>>>(x1, x1t, L_, U_, (long)L_*U_, (long)U_*L_);

    // scores: A[b] = relu( (x1*w3) @ x1^T + s1 + s2 + ab ) -> fp32 Amat
    dim3 gS(L_/128, L_/128, B_);
    gemm_bf<<<gS, 256, GEMM_SMEM>>>(xw3, U_, (long)L_*U_, x1b, U_, (long)L_*U_,
                                    Amat, L_, (long)L_*L_, nullptr, 0, 0, U_,
                                    s1, L_, s2, L_, ab, 1, 0, nullptr, nullptr);

    // softmax -> bf16 Ab
    softmax_b<<<M_, 256>>>(Amat, Ab);

    // att = P @ x1 -> bf16 directly into cat second half
    dim3 gAtt(U_/128, L_/128, B_);
    gemm_bf<<<gAtt, 256, GEMM_SMEM>>>(Ab, L_, (long)L_*L_, x1t, L_, (long)U_*L_,
                                      nullptr, 0, 0,
                                      cat + U_, 2*U_, (long)L_*2*U_, L_,
                                      nullptr, 0, nullptr, 0, nullptr, 0, 0,
                                      nullptr, nullptr);

    // z -> t (fp32)
    gemm_bf<<<gHW, 256, GEMM_SMEM>>>(cat, 2*U_, 0, ffWt, 2*U_, 0,
                                     t, U_, 0, nullptr, 0, 0, 2*U_,
                                     nullptr, 0, ffb, 0, nullptr, 2, 0, nullptr, nullptr);
    // r-GEMM fused with final gating: out = r*inputs + z*z
    gemm_bf<<<gHW, 256, GEMM_SMEM>>>(cat, 2*U_, 0, frWt, 2*U_, 0,
                                     out, U_, 0, nullptr, 0, 0, 2*U_,
                                     nullptr, 0, frb, 0, nullptr, 2, 2, t, inputs);
}

// round 8
// speedup vs baseline: 1.0691x; 1.0691x over previous
#include <cuda_runtime.h>
#include <cuda_bf16.h>
#include <cstdint>

#define B_  16
#define L_  1024
#define U_  512
#define M_  (B_*L_)      // 16384

typedef __nv_bfloat16  bf16;
typedef __nv_bfloat162 bf162;

// ---------------------------------------------------------------------------
// Scratch (device globals; no allocation allowed) — all-bf16 activations
// ---------------------------------------------------------------------------
__device__ float g_s1[M_];
__device__ float g_s2[M_];

__device__ bf16 g_ib  [M_*U_];          // inputs bf16
__device__ bf16 g_x0b [M_*U_];
__device__ bf16 g_x1b [M_*U_];
__device__ bf16 g_xw3 [M_*U_];          // x1 * w3
__device__ bf16 g_x1t [M_*U_];          // per-batch [U][L]
__device__ bf16 g_cat [(size_t)M_*2*U_];
__device__ bf16 g_As  [(size_t)B_*L_*L_];  // scores (pre-softmax)
__device__ bf16 g_Ab  [(size_t)B_*L_*L_];  // probabilities
__device__ bf16 g_tWt [2*U_*U_];
__device__ bf16 g_cWt [2*U_*U_];
__device__ bf16 g_ffWt[2*U_*U_];        // [512][1024]
__device__ bf16 g_frWt[2*U_*U_];        // [512][1024]

// ---------------------------------------------------------------------------
// PTX helpers (baseline PTX; compile at compute_103)
// ---------------------------------------------------------------------------
__device__ __forceinline__ uint32_t smem_u32(const void* p) {
    uint32_t a;
    asm("{ .reg .u64 t; cvta.to.shared.u64 t, %1; cvt.u32.u64 %0, t; }"
        : "=r"(a) : "l"(p));
    return a;
}
__device__ __forceinline__ void cpasync16(uint32_t dst, const void* src) {
    asm volatile("cp.async.cg.shared.global [%0], [%1], 16;"
                 :: "r"(dst), "l"(src));
}
#define CP_COMMIT() asm volatile("cp.async.commit_group;" ::: "memory")
#define CP_WAIT(n)  asm volatile("cp.async.wait_group %0;" :: "n"(n) : "memory")

#define LDSM4(r0, r1, r2, r3, addr) \
    asm volatile("ldmatrix.sync.aligned.m8n8.x4.shared.b16 {%0,%1,%2,%3}, [%4];" \
        : "=r"(r0), "=r"(r1), "=r"(r2), "=r"(r3) : "r"(addr))

__device__ __forceinline__ void mma_bf16(float* c, const uint32_t* a,
                                         uint32_t b0, uint32_t b1) {
    asm volatile(
        "mma.sync.aligned.m16n8k16.row.col.f32.bf16.bf16.f32 "
        "{%0,%1,%2,%3}, {%4,%5,%6,%7}, {%8,%9}, {%0,%1,%2,%3};"
        : "+f"(c[0]), "+f"(c[1]), "+f"(c[2]), "+f"(c[3])
        : "r"(a[0]), "r"(a[1]), "r"(a[2]), "r"(a[3]), "r"(b0), "r"(b1));
}

__device__ __forceinline__ float sigm(float v) {
    return 1.f / (1.f + __expf(-v));
}
__device__ __forceinline__ float2 b2f(bf162 p) {
    return make_float2(__bfloat162float(p.x), __bfloat162float(p.y));
}

#define KC 64
#define RB 128                 // row bytes (KC bf16)
#define STAGE_B (128*RB)       // 16 KB
#define NSTG 3

// ---------------------------------------------------------------------------
// DUAL bf16 GEMM: two GEMMs sharing the A operand, fused combine epilogue.
//   acc1[m,n] = sum_k A[m,k]*B1[n,k] + b1[n]
//   acc2[m,n] = sum_k A[m,k]*B2[n,k] + b2[n]
// mode 0 (highway): t=relu(acc1); c=sig(acc2); o = t*c + e*(1-c) -> Xbout bf16
//                   (e read from e2f fp32 if non-null, else e2b bf16)
// mode 1 (final):   z=sig(acc1);  r=sig(acc2); o = r*e2f + z*z -> Xout fp32
// Output/e stride is always U_ (the [M,512] activation layout).
// ---------------------------------------------------------------------------
__global__ __launch_bounds__(256, 1) void gemm_dual(
    const bf16* __restrict__ A,  long lda,
    const bf16* __restrict__ B1, const bf16* __restrict__ B2, long ldb,
    float* __restrict__ Xout, bf16* __restrict__ Xbout,
    const float* __restrict__ e2f, const bf16* __restrict__ e2b,
    int K,
    const float* __restrict__ b1, const float* __restrict__ b2,
    int mode)
{
    extern __shared__ char smc[];
    const uint32_t as0  = smem_u32(smc);
    const uint32_t b1s0 = as0  + NSTG * STAGE_B;
    const uint32_t b2s0 = b1s0 + NSTG * STAGE_B;

    const int tid  = threadIdx.x;
    const int wid  = tid >> 5;
    const int lane = tid & 31;
    const int li   = lane & 7;
    const int q    = lane >> 3;
    const int ql   = q & 1;
    const int qh   = q >> 1;
    const int m0   = (wid >> 2) * 64;
    const int n0   = (wid & 3)  * 32;

    const int bm = blockIdx.y * 128;
    const int bn = blockIdx.x * 128;

    const int lrow = tid >> 1;
    const int lcb  = (tid & 1) * 4;
    const int nch  = K / KC;

    float acc1[4][4][4], acc2[4][4][4];
    #pragma unroll
    for (int i = 0; i < 4; i++)
        #pragma unroll
        for (int j = 0; j < 4; j++)
            #pragma unroll
            for (int k = 0; k < 4; k++) { acc1[i][j][k] = 0.f; acc2[i][j][k] = 0.f; }

    auto load_chunk = [&](int c) {
        const int st = c % NSTG;
        const bf16* ap  = A  + (long)(bm + lrow) * lda + c * KC;
        const bf16* b1p = B1 + (long)(bn + lrow) * ldb + c * KC;
        const bf16* b2p = B2 + (long)(bn + lrow) * ldb + c * KC;
        const uint32_t ad  = as0  + st * STAGE_B + lrow * RB;
        const uint32_t bd1 = b1s0 + st * STAGE_B + lrow * RB;
        const uint32_t bd2 = b2s0 + st * STAGE_B + lrow * RB;
        const int sw = lrow & 7;
        #pragma unroll
        for (int j = 0; j < 4; j++) {
            const int ch  = lcb + j;
            const int cho = (ch ^ sw) * 16;
            cpasync16(ad  + cho, ap  + ch * 8);
            cpasync16(bd1 + cho, b1p + ch * 8);
            cpasync16(bd2 + cho, b2p + ch * 8);
        }
        CP_COMMIT();
    };

    load_chunk(0);
    if (nch > 1) load_chunk(1);

    int rA[4], nB[2];
    #pragma unroll
    for (int mt = 0; mt < 4; mt++) rA[mt] = m0 + mt * 16 + li + ql * 8;
    #pragma unroll
    for (int p = 0; p < 2; p++)    nB[p] = n0 + p * 16 + qh * 8 + li;

    for (int c = 0; c < nch; c++) {
        const int st = c % NSTG;
        if (c + 1 < nch) CP_WAIT(1); else CP_WAIT(0);
        __syncthreads();
        if (c + 2 < nch) load_chunk(c + 2);

        const uint32_t asb  = as0  + st * STAGE_B;
        const uint32_t b1sb = b1s0 + st * STAGE_B;
        const uint32_t b2sb = b2s0 + st * STAGE_B;

        #pragma unroll
        for (int ks = 0; ks < 4; ks++) {
            uint32_t a[4][4];
            #pragma unroll
            for (int mt = 0; mt < 4; mt++) {
                const int r = rA[mt];
                const int ch = (ks * 2 + qh) ^ (r & 7);
                LDSM4(a[mt][0], a[mt][1], a[mt][2], a[mt][3],
                      asb + r * RB + ch * 16);
            }
            uint32_t f1[2][4], f2[2][4];
            #pragma unroll
            for (int p = 0; p < 2; p++) {
                const int n = nB[p];
                const int ch = ((ks * 2 + ql) ^ (n & 7)) * 16;
                LDSM4(f1[p][0], f1[p][1], f1[p][2], f1[p][3], b1sb + n * RB + ch);
                LDSM4(f2[p][0], f2[p][1], f2[p][2], f2[p][3], b2sb + n * RB + ch);
            }
            #pragma unroll
            for (int nt = 0; nt < 4; nt++) {
                const int p = nt >> 1, h = (nt & 1) * 2;
                #pragma unroll
                for (int mt = 0; mt < 4; mt++) {
                    mma_bf16(acc1[mt][nt], a[mt], f1[p][h], f1[p][h + 1]);
                    mma_bf16(acc2[mt][nt], a[mt], f2[p][h], f2[p][h + 1]);
                }
            }
        }
        __syncthreads();
    }

    // ---- fused epilogue ----
    const int grp = lane >> 2;
    const int tig = lane & 3;

    #pragma unroll
    for (int mt = 0; mt < 4; mt++) {
        const int row = bm + m0 + mt * 16 + grp;
        #pragma unroll
        for (int nt = 0; nt < 4; nt++) {
            const int col = bn + n0 + nt * 8 + tig * 2;
            const float p10 = b1[col], p11 = b1[col + 1];
            const float p20 = b2[col], p21 = b2[col + 1];
            const long i0 = (long)row * U_ + col;
            const long i8 = (long)(row + 8) * U_ + col;
            float2 x0v, x8v;
            if (e2f) {
                x0v = *(const float2*)(e2f + i0);
                x8v = *(const float2*)(e2f + i8);
            } else {
                x0v = b2f(*(const bf162*)(e2b + i0));
                x8v = b2f(*(const bf162*)(e2b + i8));
            }
            float u0 = acc1[mt][nt][0] + p10, u1 = acc1[mt][nt][1] + p11;
            float u2 = acc1[mt][nt][2] + p10, u3 = acc1[mt][nt][3] + p11;
            float w0 = acc2[mt][nt][0] + p20, w1 = acc2[mt][nt][1] + p21;
            float w2 = acc2[mt][nt][2] + p20, w3 = acc2[mt][nt][3] + p21;
            if (mode == 0) {
                u0 = fmaxf(u0, 0.f); u1 = fmaxf(u1, 0.f);
                u2 = fmaxf(u2, 0.f); u3 = fmaxf(u3, 0.f);
                w0 = sigm(w0); w1 = sigm(w1); w2 = sigm(w2); w3 = sigm(w3);
                const float o0 = u0 * w0 + x0v.x * (1.f - w0);
                const float o1 = u1 * w1 + x0v.y * (1.f - w1);
                const float o2 = u2 * w2 + x8v.x * (1.f - w2);
                const float o3 = u3 * w3 + x8v.y * (1.f - w3);
                *(bf162*)(Xbout + i0) = __floats2bfloat162_rn(o0, o1);
                *(bf162*)(Xbout + i8) = __floats2bfloat162_rn(o2, o3);
            } else {
                u0 = sigm(u0); u1 = sigm(u1); u2 = sigm(u2); u3 = sigm(u3);
                w0 = sigm(w0); w1 = sigm(w1); w2 = sigm(w2); w3 = sigm(w3);
                const float o0 = w0 * x0v.x + u0 * u0;
                const float o1 = w1 * x0v.y + u1 * u1;
                const float o2 = w2 * x8v.x + u2 * u2;
                const float o3 = w3 * x8v.y + u3 * u3;
                *(float2*)(Xout + i0) = make_float2(o0, o1);
                *(float2*)(Xout + i8) = make_float2(o2, o3);
            }
        }
    }
}

// ---------------------------------------------------------------------------
// Single bf16 GEMM (scores / att):
//   acc = sum_k A[m,k]*Bt[n,k] + rowbias[m] + colbias[n] + addc; v = act(acc)
// Stores bf16 Cb (and fp32 C if non-null).
// ---------------------------------------------------------------------------
__global__ __launch_bounds__(256) void gemm_bf(
    const bf16* __restrict__ A,  long lda, long sA,
    const bf16* __restrict__ Bt, long ldb, long sB,
    float* __restrict__ C, long ldc, long sC,
    bf16* __restrict__ Cb, long ldcb, long sCb,
    int K,
    const float* __restrict__ rowbias, long srb,
    const float* __restrict__ colbias, long scb,
    const float* __restrict__ addc,
    int act)
{
    extern __shared__ char smc[];
    const uint32_t as0 = smem_u32(smc);
    const uint32_t bs0 = as0 + NSTG * STAGE_B;

    const int tid  = threadIdx.x;
    const int wid  = tid >> 5;
    const int lane = tid & 31;
    const int li   = lane & 7;
    const int q    = lane >> 3;
    const int ql   = q & 1;
    const int qh   = q >> 1;
    const int m0   = (wid >> 2) * 64;
    const int n0   = (wid & 3)  * 32;

    const int bz = blockIdx.z;
    const int bm = blockIdx.y * 128;
    const int bn = blockIdx.x * 128;

    const bf16* Ag = A  + (long)bz * sA;
    const bf16* Bg = Bt + (long)bz * sB;

    const int lrow = tid >> 1;
    const int lcb  = (tid & 1) * 4;
    const int nch  = K / KC;

    float acc[4][4][4];
    #pragma unroll
    for (int i = 0; i < 4; i++)
        #pragma unroll
        for (int j = 0; j < 4; j++)
            #pragma unroll
            for (int k = 0; k < 4; k++) acc[i][j][k] = 0.f;

    auto load_chunk = [&](int c) {
        const int st = c % NSTG;
        const bf16* ap = Ag + (long)(bm + lrow) * lda + c * KC;
        const bf16* bp = Bg + (long)(bn + lrow) * ldb + c * KC;
        const uint32_t ad = as0 + st * STAGE_B + lrow * RB;
        const uint32_t bd = bs0 + st * STAGE_B + lrow * RB;
        const int sw = lrow & 7;
        #pragma unroll
        for (int j = 0; j < 4; j++) {
            const int ch = lcb + j;
            const int cho = (ch ^ sw) * 16;
            cpasync16(ad + cho, ap + ch * 8);
            cpasync16(bd + cho, bp + ch * 8);
        }
        CP_COMMIT();
    };

    load_chunk(0);
    if (nch > 1) load_chunk(1);

    int rA[4], nB[2];
    #pragma unroll
    for (int mt = 0; mt < 4; mt++) rA[mt] = m0 + mt * 16 + li + ql * 8;
    #pragma unroll
    for (int p = 0; p < 2; p++)    nB[p] = n0 + p * 16 + qh * 8 + li;

    for (int c = 0; c < nch; c++) {
        const int st = c % NSTG;
        if (c + 1 < nch) CP_WAIT(1); else CP_WAIT(0);
        __syncthreads();
        if (c + 2 < nch) load_chunk(c + 2);

        const uint32_t asb = as0 + st * STAGE_B;
        const uint32_t bsb = bs0 + st * STAGE_B;

        #pragma unroll
        for (int ks = 0; ks < 4; ks++) {
            uint32_t a[4][4];
            #pragma unroll
            for (int mt = 0; mt < 4; mt++) {
                const int r = rA[mt];
                const int ch = (ks * 2 + qh) ^ (r & 7);
                LDSM4(a[mt][0], a[mt][1], a[mt][2], a[mt][3],
                      asb + r * RB + ch * 16);
            }
            uint32_t b[2][4];
            #pragma unroll
            for (int p = 0; p < 2; p++) {
                const int n = nB[p];
                const int ch = (ks * 2 + ql) ^ (n & 7);
                LDSM4(b[p][0], b[p][1], b[p][2], b[p][3],
                      bsb + n * RB + ch * 16);
            }
            #pragma unroll
            for (int nt = 0; nt < 4; nt++) {
                const uint32_t b0 = b[nt >> 1][(nt & 1) * 2];
                const uint32_t b1 = b[nt >> 1][(nt & 1) * 2 + 1];
                #pragma unroll
                for (int mt = 0; mt < 4; mt++)
                    mma_bf16(acc[mt][nt], a[mt], b0, b1);
            }
        }
        __syncthreads();
    }

    const int grp = lane >> 2;
    const int tig = lane & 3;
    float* Cp  = C  ? C  + (long)bz * sC  : nullptr;
    bf16*  Cbp = Cb ? Cb + (long)bz * sCb : nullptr;
    const float a0 = addc ? addc[0] : 0.f;

    #pragma unroll
    for (int mt = 0; mt < 4; mt++) {
        const int row = bm + m0 + mt * 16 + grp;
        float rb0 = a0, rb8 = a0;
        if (rowbias) {
            rb0 += rowbias[(long)bz * srb + row];
            rb8 += rowbias[(long)bz * srb + row + 8];
        }
        #pragma unroll
        for (int nt = 0; nt < 4; nt++) {
            const int col = bn + n0 + nt * 8 + tig * 2;
            float cb0 = 0.f, cb1 = 0.f;
            if (colbias) {
                cb0 = colbias[(long)bz * scb + col];
                cb1 = colbias[(long)bz * scb + col + 1];
            }
            float v0 = acc[mt][nt][0] + rb0 + cb0;
            float v1 = acc[mt][nt][1] + rb0 + cb1;
            float v2 = acc[mt][nt][2] + rb8 + cb0;
            float v3 = acc[mt][nt][3] + rb8 + cb1;
            if (act == 1) {
                v0 = fmaxf(v0, 0.f); v1 = fmaxf(v1, 0.f);
                v2 = fmaxf(v2, 0.f); v3 = fmaxf(v3, 0.f);
            } else if (act == 2) {
                v0 = sigm(v0); v1 = sigm(v1); v2 = sigm(v2); v3 = sigm(v3);
            }
            if (Cp) {
                *(float2*)(Cp + (long)row * ldc + col)       = make_float2(v0, v1);
                *(float2*)(Cp + (long)(row + 8) * ldc + col) = make_float2(v2, v3);
            }
            if (Cbp) {
                *(bf162*)(Cbp + (long)row * ldcb + col)       = __floats2bfloat162_rn(v0, v1);
                *(bf162*)(Cbp + (long)(row + 8) * ldcb + col) = __floats2bfloat162_rn(v2, v3);
            }
        }
    }
}

// ---------------------------------------------------------------------------
// Merged prologue: conv_inputs (blocks 0..8191) + 4 weight transposes
// (blocks 8192..10239, 512 each: tW, cW, ffW, frW).
// ---------------------------------------------------------------------------
__global__ __launch_bounds__(256) void prologue(
    const float* __restrict__ in, bf16* __restrict__ ib, bf16* __restrict__ cat,
    const float* __restrict__ tW, bf16* __restrict__ tWt,
    const float* __restrict__ cW, bf16* __restrict__ cWt,
    const float* __restrict__ ffW, bf16* __restrict__ ffWt,
    const float* __restrict__ frW, bf16* __restrict__ frWt)
{
    const int bid = blockIdx.x;
    if (bid < 8192) {
        const int i = bid * 256 + threadIdx.x;     // over M*U/4
        const float4 v = ((const float4*)in)[i];
        const bf162 p0 = __floats2bfloat162_rn(v.x, v.y);
        const bf162 p1 = __floats2bfloat162_rn(v.z, v.w);
        *(bf162*)(ib + (long)i * 4)     = p0;
        *(bf162*)(ib + (long)i * 4 + 2) = p1;
        const int m  = i >> 7;
        const int c4 = i & 127;
        bf16* cr = cat + (long)m * (2 * U_) + c4 * 4;
        *(bf162*)cr       = p0;
        *(bf162*)(cr + 2) = p1;
        return;
    }
    __shared__ float tile[32][33];
    const int s = bid - 8192;
    const int job = s >> 9;
    const int r   = s & 511;
    const float* src; bf16* dst; int R, Cc, r0, c0;
    if (job < 2) {
        const int layer = r >> 8, w = r & 255;
        src = (job == 0 ? tW : cW) + (long)layer * U_ * U_;
        dst = (job == 0 ? tWt : cWt) + (long)layer * U_ * U_;
        R = U_; Cc = U_; c0 = (w & 15) * 32; r0 = (w >> 4) * 32;
    } else {
        src = (job == 2 ? ffW : frW);
        dst = (job == 2 ? ffWt : frWt);
        R = 2 * U_; Cc = U_; c0 = (r & 15) * 32; r0 = (r >> 4) * 32;
    }
    const int tx = threadIdx.x & 31, ty = threadIdx.x >> 5;
    #pragma unroll
    for (int i2 = 0; i2 < 32; i2 += 8)
        tile[ty + i2][tx] = src[(long)(r0 + ty + i2) * Cc + c0 + tx];
    __syncthreads();
    #pragma unroll
    for (int i2 = 0; i2 < 32; i2 += 8)
        dst[(long)(c0 + ty + i2) * R + r0 + tx] = __float2bfloat16(tile[tx][ty + i2]);
}

// ---------------------------------------------------------------------------
// prep: s1[row], s2[row], xw3 = x1*w3 — single pass over x1b (one warp/row)
// ---------------------------------------------------------------------------
__global__ __launch_bounds__(256) void prep_kernel(
    const bf16* __restrict__ x1b, const float* __restrict__ aW,
    float* __restrict__ s1, float* __restrict__ s2, bf16* __restrict__ xw3)
{
    const int row  = blockIdx.x * 8 + (threadIdx.x >> 5);
    const int lane = threadIdx.x & 31;
    const bf16* xr = x1b + (long)row * U_;
    bf16*       yr = xw3 + (long)row * U_;
    float a = 0.f, b = 0.f;
    #pragma unroll
    for (int it = 0; it < 8; it++) {
        const int d2 = it * 32 + lane;         // bf162 index
        const float2 x = b2f(*(const bf162*)(xr + d2 * 2));
        const float2 w1 = *(const float2*)(aW + d2 * 2);
        const float2 w2 = *(const float2*)(aW + U_ + d2 * 2);
        const float2 w3 = *(const float2*)(aW + 2 * U_ + d2 * 2);
        a += x.x * w1.x + x.y * w1.y;
        b += x.x * w2.x + x.y * w2.y;
        *(bf162*)(yr + d2 * 2) = __floats2bfloat162_rn(x.x * w3.x, x.y * w3.y);
    }
    #pragma unroll
    for (int o = 16; o > 0; o >>= 1) {
        a += __shfl_xor_sync(0xffffffffu, a, o);
        b += __shfl_xor_sync(0xffffffffu, b, o);
    }
    if (lane == 0) { s1[row] = a; s2[row] = b; }
}

// ---------------------------------------------------------------------------
// bf16 -> bf16 transpose for x1t: grid (U/32, L/32, B)
// ---------------------------------------------------------------------------
__global__ __launch_bounds__(256) void transpose_bb(
    const bf16* __restrict__ src, bf16* __restrict__ dst)
{
    __shared__ bf16 tile[32][33];
    src += (long)blockIdx.z * L_ * U_;
    dst += (long)blockIdx.z * U_ * L_;
    const int c0 = blockIdx.x * 32, r0 = blockIdx.y * 32;
    const int tx = threadIdx.x & 31, ty = threadIdx.x >> 5;
    #pragma unroll
    for (int i = 0; i < 32; i += 8)
        tile[ty + i][tx] = src[(long)(r0 + ty + i) * U_ + c0 + tx];
    __syncthreads();
    #pragma unroll
    for (int i = 0; i < 32; i += 8)
        dst[(long)(c0 + ty + i) * L_ + r0 + tx] = tile[tx][ty + i];
}

// ---------------------------------------------------------------------------
// softmax: bf16 in, bf16 out (fp32 internally)
// ---------------------------------------------------------------------------
__global__ __launch_bounds__(256) void softmax_bb(
    const bf16* __restrict__ A, bf16* __restrict__ Ab)
{
    const bf16* row  = A  + (long)blockIdx.x * L_;
    bf16*       orow = Ab + (long)blockIdx.x * L_;
    const int tid = threadIdx.x;
    __shared__ float red[256];

    const uint2 u = *(const uint2*)(row + tid * 4);
    float2 v01 = b2f(*(const bf162*)&u.x);
    float2 v23 = b2f(*(const bf162*)&u.y);
    float m = fmaxf(fmaxf(v01.x, v01.y), fmaxf(v23.x, v23.y));
    red[tid] = m; __syncthreads();
    for (int s = 128; s > 0; s >>= 1) {
        if (tid < s) red[tid] = fmaxf(red[tid], red[tid + s]);
        __syncthreads();
    }
    m = red[0]; __syncthreads();

    v01.x = __expf(v01.x - m); v01.y = __expf(v01.y - m);
    v23.x = __expf(v23.x - m); v23.y = __expf(v23.y - m);
    red[tid] = v01.x + v01.y + v23.x + v23.y; __syncthreads();
    for (int s = 128; s > 0; s >>= 1) {
        if (tid < s) red[tid] += red[tid + s];
        __syncthreads();
    }
    const float inv = 1.f / red[0];
    uint2 o;
    *(bf162*)&o.x = __floats2bfloat162_rn(v01.x * inv, v01.y * inv);
    *(bf162*)&o.y = __floats2bfloat162_rn(v23.x * inv, v23.y * inv);
    *(uint2*)(orow + tid * 4) = o;
}

// ---------------------------------------------------------------------------
// Launch
// ---------------------------------------------------------------------------
#define GEMM_SMEM (2 * NSTG * STAGE_B)   // 96 KB  (single GEMM)
#define DUAL_SMEM (3 * NSTG * STAGE_B)   // 144 KB (dual GEMM)

extern "C" void kernel_launch(void* const* d_in, const int* in_sizes, int n_in,
                              void* d_out, int out_size)
{
    (void)in_sizes; (void)n_in; (void)out_size;
    const float* inputs = (const float*)d_in[0];
    const float* tW     = (const float*)d_in[1];
    const float* tb     = (const float*)d_in[2];
    const float* cW     = (const float*)d_in[3];
    const float* cb     = (const float*)d_in[4];
    const float* aW     = (const float*)d_in[5];
    const float* ab     = (const float*)d_in[6];
    const float* frW    = (const float*)d_in[7];
    const float* frb    = (const float*)d_in[8];
    const float* ffW    = (const float*)d_in[9];
    const float* ffb    = (const float*)d_in[10];
    float* out = (float*)d_out;

    float *s1, *s2;
    bf16 *ib, *x0b, *x1b, *xw3, *x1t, *cat, *As, *Ab, *tWt, *cWt, *ffWt, *frWt;
    cudaGetSymbolAddress((void**)&s1,   g_s1);
    cudaGetSymbolAddress((void**)&s2,   g_s2);
    cudaGetSymbolAddress((void**)&ib,   g_ib);
    cudaGetSymbolAddress((void**)&x0b,  g_x0b);
    cudaGetSymbolAddress((void**)&x1b,  g_x1b);
    cudaGetSymbolAddress((void**)&xw3,  g_xw3);
    cudaGetSymbolAddress((void**)&x1t,  g_x1t);
    cudaGetSymbolAddress((void**)&cat,  g_cat);
    cudaGetSymbolAddress((void**)&As,   g_As);
    cudaGetSymbolAddress((void**)&Ab,   g_Ab);
    cudaGetSymbolAddress((void**)&tWt,  g_tWt);
    cudaGetSymbolAddress((void**)&cWt,  g_cWt);
    cudaGetSymbolAddress((void**)&ffWt, g_ffWt);
    cudaGetSymbolAddress((void**)&frWt, g_frWt);

    cudaFuncSetAttribute(gemm_bf, cudaFuncAttributeMaxDynamicSharedMemorySize,
                         GEMM_SMEM);
    cudaFuncSetAttribute(gemm_dual, cudaFuncAttributeMaxDynamicSharedMemorySize,
                         DUAL_SMEM);

    // 1. merged prologue (inputs->bf16 + cat, 4 weight transposes)
    prologue<<<10240, 256>>>(inputs, ib, cat, tW, tWt, cW, cWt,
                             ffW, ffWt, frW, frWt);

    dim3 gHW(U_/128, M_/128);      // (4,128)
    // 2. highway layer 0 (dual): x0b = relu(ib@tW0+tb0)*sig(..) + inputs*(1-sig)
    gemm_dual<<<gHW, 256, DUAL_SMEM>>>(ib, U_, tWt, cWt, U_,
                                       nullptr, x0b, inputs, nullptr, U_,
                                       tb, cb, 0);
    // 3. highway layer 1 (dual), e from bf16 x0b
    gemm_dual<<<gHW, 256, DUAL_SMEM>>>(x0b, U_, tWt + U_*U_, cWt + U_*U_, U_,
                                       nullptr, x1b, nullptr, x0b, U_,
                                       tb + U_, cb + U_, 0);

    // 4. prep: s1, s2, xw3 (single pass over x1b)
    prep_kernel<<<M_/8, 256>>>(x1b, aW, s1, s2, xw3);
    // 5. x1^T (bf16 -> bf16)
    transpose_bb<<<dim3(U_/32, L_/32, B_), 256>>>(x1b, x1t);

    // 6. scores: As[b] = relu( (x1*w3) @ x1^T + s1 + s2 + ab )  (bf16 out)
    dim3 gS(L_/128, L_/128, B_);
    gemm_bf<<<gS, 256, GEMM_SMEM>>>(xw3, U_, (long)L_*U_, x1b, U_, (long)L_*U_,
                                    nullptr, 0, 0, As, L_, (long)L_*L_, U_,
                                    s1, L_, s2, L_, ab, 1);

    // 7. softmax (bf16 -> bf16)
    softmax_bb<<<M_, 256>>>(As, Ab);

    // 8. att = P @ x1 -> bf16 into cat second half
    dim3 gAtt(U_/128, L_/128, B_);
    gemm_bf<<<gAtt, 256, GEMM_SMEM>>>(Ab, L_, (long)L_*L_, x1t, L_, (long)U_*L_,
                                      nullptr, 0, 0,
                                      cat + U_, 2*U_, (long)L_*2*U_, L_,
                                      nullptr, 0, nullptr, 0, nullptr, 0);

    // 9. final dual: out = sig(cat@frW+frb)*inputs + sig(cat@ffW+ffb)^2
    gemm_dual<<<gHW, 256, DUAL_SMEM>>>(cat, 2*U_, ffWt, frWt, 2*U_,
                                       out, nullptr, inputs, nullptr, 2*U_,
                                       ffb, frb, 1);
}

// round 9
// speedup vs baseline: 1.0820x; 1.0120x over previous
#include <cuda_runtime.h>
#include <cuda_bf16.h>
#include <cstdint>

#define B_  16
#define L_  1024
#define U_  512
#define M_  (B_*L_)      // 16384

typedef __nv_bfloat16  bf16;
typedef __nv_bfloat162 bf162;

// ---------------------------------------------------------------------------
// Scratch (device globals; no allocation allowed)
// ---------------------------------------------------------------------------
__device__ float g_s1[M_];
__device__ float g_s2[M_];
__device__ float g_rs[M_];              // reciprocal row sums of exp scores

__device__ bf16 g_ib  [M_*U_];          // inputs bf16
__device__ bf16 g_x0b [M_*U_];
__device__ bf16 g_x1b [M_*U_];
__device__ bf16 g_xw3 [M_*U_];          // x1 * w3
__device__ bf16 g_x1t [M_*U_];          // per-batch [U][L]
__device__ bf16 g_cat [(size_t)M_*2*U_];
__device__ bf16 g_As  [(size_t)B_*L_*L_];  // exp(relu(scores))
__device__ bf16 g_tWt [2*U_*U_];
__device__ bf16 g_cWt [2*U_*U_];
__device__ bf16 g_ffWt[2*U_*U_];        // [512][1024]
__device__ bf16 g_frWt[2*U_*U_];        // [512][1024]

// ---------------------------------------------------------------------------
// PTX helpers (baseline PTX; compile at compute_103)
// ---------------------------------------------------------------------------
__device__ __forceinline__ uint32_t smem_u32(const void* p) {
    uint32_t a;
    asm("{ .reg .u64 t; cvta.to.shared.u64 t, %1; cvt.u32.u64 %0, t; }"
        : "=r"(a) : "l"(p));
    return a;
}
__device__ __forceinline__ void cpasync16(uint32_t dst, const void* src) {
    asm volatile("cp.async.cg.shared.global [%0], [%1], 16;"
                 :: "r"(dst), "l"(src));
}
#define CP_COMMIT() asm volatile("cp.async.commit_group;" ::: "memory")
#define CP_WAIT(n)  asm volatile("cp.async.wait_group %0;" :: "n"(n) : "memory")

#define LDSM4(r0, r1, r2, r3, addr) \
    asm volatile("ldmatrix.sync.aligned.m8n8.x4.shared.b16 {%0,%1,%2,%3}, [%4];" \
        : "=r"(r0), "=r"(r1), "=r"(r2), "=r"(r3) : "r"(addr))

__device__ __forceinline__ void mma_bf16(float* c, const uint32_t* a,
                                         uint32_t b0, uint32_t b1) {
    asm volatile(
        "mma.sync.aligned.m16n8k16.row.col.f32.bf16.bf16.f32 "
        "{%0,%1,%2,%3}, {%4,%5,%6,%7}, {%8,%9}, {%0,%1,%2,%3};"
        : "+f"(c[0]), "+f"(c[1]), "+f"(c[2]), "+f"(c[3])
        : "r"(a[0]), "r"(a[1]), "r"(a[2]), "r"(a[3]), "r"(b0), "r"(b1));
}

__device__ __forceinline__ float sigm(float v) {
    return 1.f / (1.f + __expf(-v));
}
__device__ __forceinline__ float2 b2f(bf162 p) {
    return make_float2(__bfloat162float(p.x), __bfloat162float(p.y));
}

#define KC 64
#define RB 128                 // row bytes (KC bf16)
#define STAGE_B (128*RB)       // 16 KB
#define NSTG 3
#define TPITCH 136             // bf16 pitch for transpose staging

// ---------------------------------------------------------------------------
// DUAL bf16 GEMM: two GEMMs sharing the A operand, fused combine epilogue.
//   acc1[m,n] = sum_k A[m,k]*B1[n,k] + b1[n]
//   acc2[m,n] = sum_k A[m,k]*B2[n,k] + b2[n]
// mode 0 (highway): t=relu(acc1); c=sig(acc2); o = t*c + e*(1-c) -> Xbout bf16
//     optional extras: xw3o[m][n] = o*w3[n]; x1to = per-batch transposed o.
// mode 1 (final):   z=sig(acc1);  r=sig(acc2); o = r*e2f + z*z -> Xout fp32
// ---------------------------------------------------------------------------
__global__ __launch_bounds__(256, 1) void gemm_dual(
    const bf16* __restrict__ A,  long lda,
    const bf16* __restrict__ B1, const bf16* __restrict__ B2, long ldb,
    float* __restrict__ Xout, bf16* __restrict__ Xbout,
    const float* __restrict__ e2f, const bf16* __restrict__ e2b,
    int K,
    const float* __restrict__ b1, const float* __restrict__ b2,
    int mode,
    const float* __restrict__ w3, bf16* __restrict__ xw3o,
    bf16* __restrict__ x1to)
{
    extern __shared__ char smc[];
    const uint32_t as0  = smem_u32(smc);
    const uint32_t b1s0 = as0  + NSTG * STAGE_B;
    const uint32_t b2s0 = b1s0 + NSTG * STAGE_B;

    const int tid  = threadIdx.x;
    const int wid  = tid >> 5;
    const int lane = tid & 31;
    const int li   = lane & 7;
    const int q    = lane >> 3;
    const int ql   = q & 1;
    const int qh   = q >> 1;
    const int m0   = (wid >> 2) * 64;
    const int n0   = (wid & 3)  * 32;

    const int bm = blockIdx.y * 128;
    const int bn = blockIdx.x * 128;

    const int lrow = tid >> 1;
    const int lcb  = (tid & 1) * 4;
    const int nch  = K / KC;

    float acc1[4][4][4], acc2[4][4][4];
    #pragma unroll
    for (int i = 0; i < 4; i++)
        #pragma unroll
        for (int j = 0; j < 4; j++)
            #pragma unroll
            for (int k = 0; k < 4; k++) { acc1[i][j][k] = 0.f; acc2[i][j][k] = 0.f; }

    auto load_chunk = [&](int c) {
        const int st = c % NSTG;
        const bf16* ap  = A  + (long)(bm + lrow) * lda + c * KC;
        const bf16* b1p = B1 + (long)(bn + lrow) * ldb + c * KC;
        const bf16* b2p = B2 + (long)(bn + lrow) * ldb + c * KC;
        const uint32_t ad  = as0  + st * STAGE_B + lrow * RB;
        const uint32_t bd1 = b1s0 + st * STAGE_B + lrow * RB;
        const uint32_t bd2 = b2s0 + st * STAGE_B + lrow * RB;
        const int sw = lrow & 7;
        #pragma unroll
        for (int j = 0; j < 4; j++) {
            const int ch  = lcb + j;
            const int cho = (ch ^ sw) * 16;
            cpasync16(ad  + cho, ap  + ch * 8);
            cpasync16(bd1 + cho, b1p + ch * 8);
            cpasync16(bd2 + cho, b2p + ch * 8);
        }
        CP_COMMIT();
    };

    load_chunk(0);
    if (nch > 1) load_chunk(1);

    int rA[4], nB[2];
    #pragma unroll
    for (int mt = 0; mt < 4; mt++) rA[mt] = m0 + mt * 16 + li + ql * 8;
    #pragma unroll
    for (int p = 0; p < 2; p++)    nB[p] = n0 + p * 16 + qh * 8 + li;

    for (int c = 0; c < nch; c++) {
        const int st = c % NSTG;
        if (c + 1 < nch) CP_WAIT(1); else CP_WAIT(0);
        __syncthreads();
        if (c + 2 < nch) load_chunk(c + 2);

        const uint32_t asb  = as0  + st * STAGE_B;
        const uint32_t b1sb = b1s0 + st * STAGE_B;
        const uint32_t b2sb = b2s0 + st * STAGE_B;

        #pragma unroll
        for (int ks = 0; ks < 4; ks++) {
            uint32_t a[4][4];
            #pragma unroll
            for (int mt = 0; mt < 4; mt++) {
                const int r = rA[mt];
                const int ch = (ks * 2 + qh) ^ (r & 7);
                LDSM4(a[mt][0], a[mt][1], a[mt][2], a[mt][3],
                      asb + r * RB + ch * 16);
            }
            uint32_t f1[2][4], f2[2][4];
            #pragma unroll
            for (int p = 0; p < 2; p++) {
                const int n = nB[p];
                const int ch = ((ks * 2 + ql) ^ (n & 7)) * 16;
                LDSM4(f1[p][0], f1[p][1], f1[p][2], f1[p][3], b1sb + n * RB + ch);
                LDSM4(f2[p][0], f2[p][1], f2[p][2], f2[p][3], b2sb + n * RB + ch);
            }
            #pragma unroll
            for (int nt = 0; nt < 4; nt++) {
                const int p = nt >> 1, h = (nt & 1) * 2;
                #pragma unroll
                for (int mt = 0; mt < 4; mt++) {
                    mma_bf16(acc1[mt][nt], a[mt], f1[p][h], f1[p][h + 1]);
                    mma_bf16(acc2[mt][nt], a[mt], f2[p][h], f2[p][h + 1]);
                }
            }
        }
        __syncthreads();
    }

    // ---- fused epilogue ----
    const int grp = lane >> 2;
    const int tig = lane & 3;
    bf16* stage = (bf16*)smc;     // transpose staging (mainloop smem is free)

    #pragma unroll
    for (int mt = 0; mt < 4; mt++) {
        const int rl  = m0 + mt * 16 + grp;     // local row
        const int row = bm + rl;
        #pragma unroll
        for (int nt = 0; nt < 4; nt++) {
            const int cl  = n0 + nt * 8 + tig * 2;   // local col
            const int col = bn + cl;
            const float p10 = b1[col], p11 = b1[col + 1];
            const float p20 = b2[col], p21 = b2[col + 1];
            const long i0 = (long)row * U_ + col;
            const long i8 = (long)(row + 8) * U_ + col;
            float2 x0v, x8v;
            if (e2f) {
                x0v = *(const float2*)(e2f + i0);
                x8v = *(const float2*)(e2f + i8);
            } else {
                x0v = b2f(*(const bf162*)(e2b + i0));
                x8v = b2f(*(const bf162*)(e2b + i8));
            }
            float u0 = acc1[mt][nt][0] + p10, u1 = acc1[mt][nt][1] + p11;
            float u2 = acc1[mt][nt][2] + p10, u3 = acc1[mt][nt][3] + p11;
            float w0 = acc2[mt][nt][0] + p20, w1 = acc2[mt][nt][1] + p21;
            float w2 = acc2[mt][nt][2] + p20, w3v = acc2[mt][nt][3] + p21;
            if (mode == 0) {
                u0 = fmaxf(u0, 0.f); u1 = fmaxf(u1, 0.f);
                u2 = fmaxf(u2, 0.f); u3 = fmaxf(u3, 0.f);
                w0 = sigm(w0); w1 = sigm(w1); w2 = sigm(w2); w3v = sigm(w3v);
                const float o0 = u0 * w0 + x0v.x * (1.f - w0);
                const float o1 = u1 * w1 + x0v.y * (1.f - w1);
                const float o2 = u2 * w2 + x8v.x * (1.f - w2);
                const float o3 = u3 * w3v + x8v.y * (1.f - w3v);
                *(bf162*)(Xbout + i0) = __floats2bfloat162_rn(o0, o1);
                *(bf162*)(Xbout + i8) = __floats2bfloat162_rn(o2, o3);
                if (xw3o) {
                    const float2 wv = *(const float2*)(w3 + col);
                    *(bf162*)(xw3o + i0) = __floats2bfloat162_rn(o0 * wv.x, o1 * wv.y);
                    *(bf162*)(xw3o + i8) = __floats2bfloat162_rn(o2 * wv.x, o3 * wv.y);
                }
                if (x1to) {
                    stage[cl * TPITCH + rl]           = __float2bfloat16(o0);
                    stage[(cl + 1) * TPITCH + rl]     = __float2bfloat16(o1);
                    stage[cl * TPITCH + rl + 8]       = __float2bfloat16(o2);
                    stage[(cl + 1) * TPITCH + rl + 8] = __float2bfloat16(o3);
                }
            } else {
                u0 = sigm(u0); u1 = sigm(u1); u2 = sigm(u2); u3 = sigm(u3);
                w0 = sigm(w0); w1 = sigm(w1); w2 = sigm(w2); w3v = sigm(w3v);
                const float o0 = w0 * x0v.x + u0 * u0;
                const float o1 = w1 * x0v.y + u1 * u1;
                const float o2 = w2 * x8v.x + u2 * u2;
                const float o3 = w3v * x8v.y + u3 * u3;
                *(float2*)(Xout + i0) = make_float2(o0, o1);
                *(float2*)(Xout + i8) = make_float2(o2, o3);
            }
        }
    }

    // ---- transposed write-out: x1t[b][col][l] ----
    if (mode == 0 && x1to) {
        __syncthreads();
        const int b0 = bm >> 10;         // batch (L_ = 1024)
        const int l0 = bm & 1023;
        const int cw = wid * 16;         // 16 cols per warp
        #pragma unroll
        for (int cc = 0; cc < 16; cc++) {
            const int c = cw + cc;
            const uint2 v = *(const uint2*)(stage + c * TPITCH + lane * 4);
            *(uint2*)(x1to + ((long)b0 * U_ + bn + c) * L_ + l0 + lane * 4) = v;
        }
    }
}

// ---------------------------------------------------------------------------
// Single bf16 GEMM (scores / att):
//   acc = sum_k A[m,k]*Bt[n,k] + rowbias[m] + colbias[n] + addc
// act 1: relu -> Cb.  act 3: exp(relu(.)) -> Cb (no-max softmax numerator).
// act 0: v * rowscale[row] (if given) -> Cb.
// ---------------------------------------------------------------------------
__global__ __launch_bounds__(256) void gemm_bf(
    const bf16* __restrict__ A,  long lda, long sA,
    const bf16* __restrict__ Bt, long ldb, long sB,
    bf16* __restrict__ Cb, long ldcb, long sCb,
    int K,
    const float* __restrict__ rowbias, long srb,
    const float* __restrict__ colbias, long scb,
    const float* __restrict__ addc,
    const float* __restrict__ rowscale, long srs,
    int act)
{
    extern __shared__ char smc[];
    const uint32_t as0 = smem_u32(smc);
    const uint32_t bs0 = as0 + NSTG * STAGE_B;

    const int tid  = threadIdx.x;
    const int wid  = tid >> 5;
    const int lane = tid & 31;
    const int li   = lane & 7;
    const int q    = lane >> 3;
    const int ql   = q & 1;
    const int qh   = q >> 1;
    const int m0   = (wid >> 2) * 64;
    const int n0   = (wid & 3)  * 32;

    const int bz = blockIdx.z;
    const int bm = blockIdx.y * 128;
    const int bn = blockIdx.x * 128;

    const bf16* Ag = A  + (long)bz * sA;
    const bf16* Bg = Bt + (long)bz * sB;

    const int lrow = tid >> 1;
    const int lcb  = (tid & 1) * 4;
    const int nch  = K / KC;

    float acc[4][4][4];
    #pragma unroll
    for (int i = 0; i < 4; i++)
        #pragma unroll
        for (int j = 0; j < 4; j++)
            #pragma unroll
            for (int k = 0; k < 4; k++) acc[i][j][k] = 0.f;

    auto load_chunk = [&](int c) {
        const int st = c % NSTG;
        const bf16* ap = Ag + (long)(bm + lrow) * lda + c * KC;
        const bf16* bp = Bg + (long)(bn + lrow) * ldb + c * KC;
        const uint32_t ad = as0 + st * STAGE_B + lrow * RB;
        const uint32_t bd = bs0 + st * STAGE_B + lrow * RB;
        const int sw = lrow & 7;
        #pragma unroll
        for (int j = 0; j < 4; j++) {
            const int ch = lcb + j;
            const int cho = (ch ^ sw) * 16;
            cpasync16(ad + cho, ap + ch * 8);
            cpasync16(bd + cho, bp + ch * 8);
        }
        CP_COMMIT();
    };

    load_chunk(0);
    if (nch > 1) load_chunk(1);

    int rA[4], nB[2];
    #pragma unroll
    for (int mt = 0; mt < 4; mt++) rA[mt] = m0 + mt * 16 + li + ql * 8;
    #pragma unroll
    for (int p = 0; p < 2; p++)    nB[p] = n0 + p * 16 + qh * 8 + li;

    for (int c = 0; c < nch; c++) {
        const int st = c % NSTG;
        if (c + 1 < nch) CP_WAIT(1); else CP_WAIT(0);
        __syncthreads();
        if (c + 2 < nch) load_chunk(c + 2);

        const uint32_t asb = as0 + st * STAGE_B;
        const uint32_t bsb = bs0 + st * STAGE_B;

        #pragma unroll
        for (int ks = 0; ks < 4; ks++) {
            uint32_t a[4][4];
            #pragma unroll
            for (int mt = 0; mt < 4; mt++) {
                const int r = rA[mt];
                const int ch = (ks * 2 + qh) ^ (r & 7);
                LDSM4(a[mt][0], a[mt][1], a[mt][2], a[mt][3],
                      asb + r * RB + ch * 16);
            }
            uint32_t b[2][4];
            #pragma unroll
            for (int p = 0; p < 2; p++) {
                const int n = nB[p];
                const int ch = (ks * 2 + ql) ^ (n & 7);
                LDSM4(b[p][0], b[p][1], b[p][2], b[p][3],
                      bsb + n * RB + ch * 16);
            }
            #pragma unroll
            for (int nt = 0; nt < 4; nt++) {
                const uint32_t b0 = b[nt >> 1][(nt & 1) * 2];
                const uint32_t b1 = b[nt >> 1][(nt & 1) * 2 + 1];
                #pragma unroll
                for (int mt = 0; mt < 4; mt++)
                    mma_bf16(acc[mt][nt], a[mt], b0, b1);
            }
        }
        __syncthreads();
    }

    const int grp = lane >> 2;
    const int tig = lane & 3;
    bf16* Cbp = Cb + (long)bz * sCb;
    const float a0 = addc ? addc[0] : 0.f;

    #pragma unroll
    for (int mt = 0; mt < 4; mt++) {
        const int row = bm + m0 + mt * 16 + grp;
        float rb0 = a0, rb8 = a0;
        if (rowbias) {
            rb0 += rowbias[(long)bz * srb + row];
            rb8 += rowbias[(long)bz * srb + row + 8];
        }
        float sc0 = 1.f, sc8 = 1.f;
        if (rowscale) {
            sc0 = rowscale[(long)bz * srs + row];
            sc8 = rowscale[(long)bz * srs + row + 8];
        }
        #pragma unroll
        for (int nt = 0; nt < 4; nt++) {
            const int col = bn + n0 + nt * 8 + tig * 2;
            float cb0 = 0.f, cb1 = 0.f;
            if (colbias) {
                cb0 = colbias[(long)bz * scb + col];
                cb1 = colbias[(long)bz * scb + col + 1];
            }
            float v0 = acc[mt][nt][0] + rb0 + cb0;
            float v1 = acc[mt][nt][1] + rb0 + cb1;
            float v2 = acc[mt][nt][2] + rb8 + cb0;
            float v3 = acc[mt][nt][3] + rb8 + cb1;
            if (act == 1) {
                v0 = fmaxf(v0, 0.f); v1 = fmaxf(v1, 0.f);
                v2 = fmaxf(v2, 0.f); v3 = fmaxf(v3, 0.f);
            } else if (act == 3) {
                v0 = __expf(fmaxf(v0, 0.f)); v1 = __expf(fmaxf(v1, 0.f));
                v2 = __expf(fmaxf(v2, 0.f)); v3 = __expf(fmaxf(v3, 0.f));
            } else {
                v0 *= sc0; v1 *= sc0; v2 *= sc8; v3 *= sc8;
            }
            *(bf162*)(Cbp + (long)row * ldcb + col)       = __floats2bfloat162_rn(v0, v1);
            *(bf162*)(Cbp + (long)(row + 8) * ldcb + col) = __floats2bfloat162_rn(v2, v3);
        }
    }
}

// ---------------------------------------------------------------------------
// Merged prologue: conv_inputs (blocks 0..8191) + 4 weight transposes
// ---------------------------------------------------------------------------
__global__ __launch_bounds__(256) void prologue(
    const float* __restrict__ in, bf16* __restrict__ ib, bf16* __restrict__ cat,
    const float* __restrict__ tW, bf16* __restrict__ tWt,
    const float* __restrict__ cW, bf16* __restrict__ cWt,
    const float* __restrict__ ffW, bf16* __restrict__ ffWt,
    const float* __restrict__ frW, bf16* __restrict__ frWt)
{
    const int bid = blockIdx.x;
    if (bid < 8192) {
        const int i = bid * 256 + threadIdx.x;     // over M*U/4
        const float4 v = ((const float4*)in)[i];
        const bf162 p0 = __floats2bfloat162_rn(v.x, v.y);
        const bf162 p1 = __floats2bfloat162_rn(v.z, v.w);
        *(bf162*)(ib + (long)i * 4)     = p0;
        *(bf162*)(ib + (long)i * 4 + 2) = p1;
        const int m  = i >> 7;
        const int c4 = i & 127;
        bf16* cr = cat + (long)m * (2 * U_) + c4 * 4;
        *(bf162*)cr       = p0;
        *(bf162*)(cr + 2) = p1;
        return;
    }
    __shared__ float tile[32][33];
    const int s = bid - 8192;
    const int job = s >> 9;
    const int r   = s & 511;
    const float* src; bf16* dst; int R, Cc, r0, c0;
    if (job < 2) {
        const int layer = r >> 8, w = r & 255;
        src = (job == 0 ? tW : cW) + (long)layer * U_ * U_;
        dst = (job == 0 ? tWt : cWt) + (long)layer * U_ * U_;
        R = U_; Cc = U_; c0 = (w & 15) * 32; r0 = (w >> 4) * 32;
    } else {
        src = (job == 2 ? ffW : frW);
        dst = (job == 2 ? ffWt : frWt);
        R = 2 * U_; Cc = U_; c0 = (r & 15) * 32; r0 = (r >> 4) * 32;
    }
    const int tx = threadIdx.x & 31, ty = threadIdx.x >> 5;
    #pragma unroll
    for (int i2 = 0; i2 < 32; i2 += 8)
        tile[ty + i2][tx] = src[(long)(r0 + ty + i2) * Cc + c0 + tx];
    __syncthreads();
    #pragma unroll
    for (int i2 = 0; i2 < 32; i2 += 8)
        dst[(long)(c0 + ty + i2) * R + r0 + tx] = __float2bfloat16(tile[tx][ty + i2]);
}

// ---------------------------------------------------------------------------
// s1[row] = x1·w1, s2[row] = x1·w2  (one warp per row, bf16 input)
// ---------------------------------------------------------------------------
__global__ __launch_bounds__(256) void s1s2_kernel(
    const bf16* __restrict__ x1b, const float* __restrict__ aW,
    float* __restrict__ s1, float* __restrict__ s2)
{
    const int row  = blockIdx.x * 8 + (threadIdx.x >> 5);
    const int lane = threadIdx.x & 31;
    const bf16* xr = x1b + (long)row * U_;
    float a = 0.f, b = 0.f;
    #pragma unroll
    for (int it = 0; it < 8; it++) {
        const int d2 = it * 32 + lane;
        const float2 x = b2f(*(const bf162*)(xr + d2 * 2));
        const float2 w1 = *(const float2*)(aW + d2 * 2);
        const float2 w2 = *(const float2*)(aW + U_ + d2 * 2);
        a += x.x * w1.x + x.y * w1.y;
        b += x.x * w2.x + x.y * w2.y;
    }
    #pragma unroll
    for (int o = 16; o > 0; o >>= 1) {
        a += __shfl_xor_sync(0xffffffffu, a, o);
        b += __shfl_xor_sync(0xffffffffu, b, o);
    }
    if (lane == 0) { s1[row] = a; s2[row] = b; }
}

// ---------------------------------------------------------------------------
// rowsum: rinv[row] = 1 / sum_j expA[row][j]   (one warp per row, bf16 input)
// ---------------------------------------------------------------------------
__global__ __launch_bounds__(256) void rowsum_kernel(
    const bf16* __restrict__ expA, float* __restrict__ rinv)
{
    const int row  = blockIdx.x * 8 + (threadIdx.x >> 5);
    const int lane = threadIdx.x & 31;
    const bf16* rp = expA + (long)row * L_;
    float s = 0.f;
    #pragma unroll
    for (int it = 0; it < 4; it++) {
        const int d = (it * 32 + lane) * 8;
        const uint4 u = *(const uint4*)(rp + d);
        const float2 a = b2f(*(const bf162*)&u.x);
        const float2 b = b2f(*(const bf162*)&u.y);
        const float2 c = b2f(*(const bf162*)&u.z);
        const float2 e = b2f(*(const bf162*)&u.w);
        s += (a.x + a.y) + (b.x + b.y) + (c.x + c.y) + (e.x + e.y);
    }
    #pragma unroll
    for (int o = 16; o > 0; o >>= 1)
        s += __shfl_xor_sync(0xffffffffu, s, o);
    if (lane == 0) rinv[row] = 1.f / s;
}

// ---------------------------------------------------------------------------
// Launch
// ---------------------------------------------------------------------------
#define GEMM_SMEM (2 * NSTG * STAGE_B)   // 96 KB  (single GEMM)
#define DUAL_SMEM (3 * NSTG * STAGE_B)   // 144 KB (dual GEMM)

extern "C" void kernel_launch(void* const* d_in, const int* in_sizes, int n_in,
                              void* d_out, int out_size)
{
    (void)in_sizes; (void)n_in; (void)out_size;
    const float* inputs = (const float*)d_in[0];
    const float* tW     = (const float*)d_in[1];
    const float* tb     = (const float*)d_in[2];
    const float* cW     = (const float*)d_in[3];
    const float* cb     = (const float*)d_in[4];
    const float* aW     = (const float*)d_in[5];
    const float* ab     = (const float*)d_in[6];
    const float* frW    = (const float*)d_in[7];
    const float* frb    = (const float*)d_in[8];
    const float* ffW    = (const float*)d_in[9];
    const float* ffb    = (const float*)d_in[10];
    float* out = (float*)d_out;

    float *s1, *s2, *rs;
    bf16 *ib, *x0b, *x1b, *xw3, *x1t, *cat, *As, *tWt, *cWt, *ffWt, *frWt;
    cudaGetSymbolAddress((void**)&s1,   g_s1);
    cudaGetSymbolAddress((void**)&s2,   g_s2);
    cudaGetSymbolAddress((void**)&rs,   g_rs);
    cudaGetSymbolAddress((void**)&ib,   g_ib);
    cudaGetSymbolAddress((void**)&x0b,  g_x0b);
    cudaGetSymbolAddress((void**)&x1b,  g_x1b);
    cudaGetSymbolAddress((void**)&xw3,  g_xw3);
    cudaGetSymbolAddress((void**)&x1t,  g_x1t);
    cudaGetSymbolAddress((void**)&cat,  g_cat);
    cudaGetSymbolAddress((void**)&As,   g_As);
    cudaGetSymbolAddress((void**)&tWt,  g_tWt);
    cudaGetSymbolAddress((void**)&cWt,  g_cWt);
    cudaGetSymbolAddress((void**)&ffWt, g_ffWt);
    cudaGetSymbolAddress((void**)&frWt, g_frWt);

    cudaFuncSetAttribute(gemm_bf, cudaFuncAttributeMaxDynamicSharedMemorySize,
                         GEMM_SMEM);
    cudaFuncSetAttribute(gemm_dual, cudaFuncAttributeMaxDynamicSharedMemorySize,
                         DUAL_SMEM);

    // 1. merged prologue (inputs->bf16 + cat, 4 weight transposes)
    prologue<<<10240, 256>>>(inputs, ib, cat, tW, tWt, cW, cWt,
                             ffW, ffWt, frW, frWt);

    dim3 gHW(U_/128, M_/128);      // (4,128)
    // 2. highway layer 0 (dual)
    gemm_dual<<<gHW, 256, DUAL_SMEM>>>(ib, U_, tWt, cWt, U_,
                                       nullptr, x0b, inputs, nullptr, U_,
                                       tb, cb, 0, nullptr, nullptr, nullptr);
    // 3. highway layer 1 (dual) + fused xw3 + x1^T
    gemm_dual<<<gHW, 256, DUAL_SMEM>>>(x0b, U_, tWt + U_*U_, cWt + U_*U_, U_,
                                       nullptr, x1b, nullptr, x0b, U_,
                                       tb + U_, cb + U_, 0,
                                       aW + 2*U_, xw3, x1t);

    // 4. s1, s2
    s1s2_kernel<<<M_/8, 256>>>(x1b, aW, s1, s2);

    // 5. scores: As[b] = exp(relu( xw3 @ x1^T + s1 + s2 + ab ))  (bf16 out)
    dim3 gS(L_/128, L_/128, B_);
    gemm_bf<<<gS, 256, GEMM_SMEM>>>(xw3, U_, (long)L_*U_, x1b, U_, (long)L_*U_,
                                    As, L_, (long)L_*L_, U_,
                                    s1, L_, s2, L_, ab, nullptr, 0, 3);

    // 6. reciprocal row sums
    rowsum_kernel<<<M_/8, 256>>>(As, rs);

    // 7. att = (expA @ x1) * rinv[row] -> bf16 into cat second half
    dim3 gAtt(U_/128, L_/128, B_);
    gemm_bf<<<gAtt, 256, GEMM_SMEM>>>(As, L_, (long)L_*L_, x1t, L_, (long)U_*L_,
                                      cat + U_, 2*U_, (long)L_*2*U_, L_,
                                      nullptr, 0, nullptr, 0, nullptr,
                                      rs, L_, 0);

    // 8. final dual: out = sig(cat@frW+frb)*inputs + sig(cat@ffW+ffb)^2
    gemm_dual<<<gHW, 256, DUAL_SMEM>>>(cat, 2*U_, ffWt, frWt, 2*U_,
                                       out, nullptr, inputs, nullptr, 2*U_,
                                       ffb, frb, 1, nullptr, nullptr, nullptr);
}

// round 10
// speedup vs baseline: 1.1207x; 1.0357x over previous
#include <cuda_runtime.h>
#include <cuda_bf16.h>
#include <cstdint>

#define B_  16
#define L_  1024
#define U_  512
#define M_  (B_*L_)      // 16384

typedef __nv_bfloat16  bf16;
typedef __nv_bfloat162 bf162;

// ---------------------------------------------------------------------------
// Scratch (device globals; no allocation allowed)
// ---------------------------------------------------------------------------
__device__ float g_s1[M_];
__device__ float g_s2[M_];
__device__ float g_rs[M_];              // reciprocal row sums of exp scores
__device__ float g_ps1[4*M_];           // s1 partials (per col-block)
__device__ float g_ps2[4*M_];           // s2 partials
__device__ float g_pr [8*M_];           // rowsum partials

__device__ bf16 g_ib  [M_*U_];          // inputs bf16
__device__ bf16 g_x0b [M_*U_];
__device__ bf16 g_x1b [M_*U_];
__device__ bf16 g_xw3 [M_*U_];          // x1 * w3
__device__ bf16 g_x1t [M_*U_];          // per-batch [U][L]
__device__ bf16 g_cat [(size_t)M_*2*U_];
__device__ bf16 g_As  [(size_t)B_*L_*L_];  // exp(relu(scores))
__device__ bf16 g_tWt [2*U_*U_];
__device__ bf16 g_cWt [2*U_*U_];
__device__ bf16 g_ffWt[2*U_*U_];        // [512][1024]
__device__ bf16 g_frWt[2*U_*U_];        // [512][1024]

// ---------------------------------------------------------------------------
// PTX helpers (baseline PTX; compile at compute_103)
// ---------------------------------------------------------------------------
__device__ __forceinline__ uint32_t smem_u32(const void* p) {
    uint32_t a;
    asm("{ .reg .u64 t; cvta.to.shared.u64 t, %1; cvt.u32.u64 %0, t; }"
        : "=r"(a) : "l"(p));
    return a;
}
__device__ __forceinline__ void cpasync16(uint32_t dst, const void* src) {
    asm volatile("cp.async.cg.shared.global [%0], [%1], 16;"
                 :: "r"(dst), "l"(src));
}
#define CP_COMMIT() asm volatile("cp.async.commit_group;" ::: "memory")
#define CP_WAIT(n)  asm volatile("cp.async.wait_group %0;" :: "n"(n) : "memory")

#define LDSM4(r0, r1, r2, r3, addr) \
    asm volatile("ldmatrix.sync.aligned.m8n8.x4.shared.b16 {%0,%1,%2,%3}, [%4];" \
        : "=r"(r0), "=r"(r1), "=r"(r2), "=r"(r3) : "r"(addr))

__device__ __forceinline__ void mma_bf16(float* c, const uint32_t* a,
                                         uint32_t b0, uint32_t b1) {
    asm volatile(
        "mma.sync.aligned.m16n8k16.row.col.f32.bf16.bf16.f32 "
        "{%0,%1,%2,%3}, {%4,%5,%6,%7}, {%8,%9}, {%0,%1,%2,%3};"
        : "+f"(c[0]), "+f"(c[1]), "+f"(c[2]), "+f"(c[3])
        : "r"(a[0]), "r"(a[1]), "r"(a[2]), "r"(a[3]), "r"(b0), "r"(b1));
}

__device__ __forceinline__ float sigm(float v) {
    return 1.f / (1.f + __expf(-v));
}
__device__ __forceinline__ float2 b2f(bf162 p) {
    return make_float2(__bfloat162float(p.x), __bfloat162float(p.y));
}

#define KC 64
#define RB 128                 // row bytes (KC bf16)
#define STAGE_B (128*RB)       // 16 KB
#define NSTG 3
#define TPITCH 136             // bf16 pitch for transpose staging
#define PSTAGE_OFF 36864       // byte offset of partial staging in dual smem

// ---------------------------------------------------------------------------
// DUAL bf16 GEMM: two GEMMs sharing the A operand, fused combine epilogue.
//   acc1[m,n] = sum_k A[m,k]*B1[n,k] + b1[n]
//   acc2[m,n] = sum_k A[m,k]*B2[n,k] + b2[n]
// mode 0 (highway): t=relu(acc1); c=sig(acc2); o = t*c + e*(1-c) -> Xbout bf16
//     extras: xw3o = o*w3[n]; x1to = per-batch transposed o;
//     ps1/ps2 = per-CTA partial row-dots of rounded o with w12 / w12+U.
// mode 1 (final):   z=sig(acc1);  r=sig(acc2); o = r*e2f + z*z -> Xout fp32
// ---------------------------------------------------------------------------
__global__ __launch_bounds__(256, 1) void gemm_dual(
    const bf16* __restrict__ A,  long lda,
    const bf16* __restrict__ B1, const bf16* __restrict__ B2, long ldb,
    float* __restrict__ Xout, bf16* __restrict__ Xbout,
    const float* __restrict__ e2f, const bf16* __restrict__ e2b,
    int K,
    const float* __restrict__ b1, const float* __restrict__ b2,
    int mode,
    const float* __restrict__ w3, bf16* __restrict__ xw3o,
    bf16* __restrict__ x1to,
    const float* __restrict__ w12,
    float* __restrict__ ps1, float* __restrict__ ps2)
{
    extern __shared__ char smc[];
    const uint32_t as0  = smem_u32(smc);
    const uint32_t b1s0 = as0  + NSTG * STAGE_B;
    const uint32_t b2s0 = b1s0 + NSTG * STAGE_B;

    const int tid  = threadIdx.x;
    const int wid  = tid >> 5;
    const int lane = tid & 31;
    const int li   = lane & 7;
    const int q    = lane >> 3;
    const int ql   = q & 1;
    const int qh   = q >> 1;
    const int m0   = (wid >> 2) * 64;
    const int n0   = (wid & 3)  * 32;

    const int bm = blockIdx.y * 128;
    const int bn = blockIdx.x * 128;

    const int lrow = tid >> 1;
    const int lcb  = (tid & 1) * 4;
    const int nch  = K / KC;

    float acc1[4][4][4], acc2[4][4][4];
    #pragma unroll
    for (int i = 0; i < 4; i++)
        #pragma unroll
        for (int j = 0; j < 4; j++)
            #pragma unroll
            for (int k = 0; k < 4; k++) { acc1[i][j][k] = 0.f; acc2[i][j][k] = 0.f; }

    auto load_chunk = [&](int c) {
        const int st = c % NSTG;
        const bf16* ap  = A  + (long)(bm + lrow) * lda + c * KC;
        const bf16* b1p = B1 + (long)(bn + lrow) * ldb + c * KC;
        const bf16* b2p = B2 + (long)(bn + lrow) * ldb + c * KC;
        const uint32_t ad  = as0  + st * STAGE_B + lrow * RB;
        const uint32_t bd1 = b1s0 + st * STAGE_B + lrow * RB;
        const uint32_t bd2 = b2s0 + st * STAGE_B + lrow * RB;
        const int sw = lrow & 7;
        #pragma unroll
        for (int j = 0; j < 4; j++) {
            const int ch  = lcb + j;
            const int cho = (ch ^ sw) * 16;
            cpasync16(ad  + cho, ap  + ch * 8);
            cpasync16(bd1 + cho, b1p + ch * 8);
            cpasync16(bd2 + cho, b2p + ch * 8);
        }
        CP_COMMIT();
    };

    load_chunk(0);
    if (nch > 1) load_chunk(1);

    int rA[4], nB[2];
    #pragma unroll
    for (int mt = 0; mt < 4; mt++) rA[mt] = m0 + mt * 16 + li + ql * 8;
    #pragma unroll
    for (int p = 0; p < 2; p++)    nB[p] = n0 + p * 16 + qh * 8 + li;

    for (int c = 0; c < nch; c++) {
        const int st = c % NSTG;
        if (c + 1 < nch) CP_WAIT(1); else CP_WAIT(0);
        __syncthreads();
        if (c + 2 < nch) load_chunk(c + 2);

        const uint32_t asb  = as0  + st * STAGE_B;
        const uint32_t b1sb = b1s0 + st * STAGE_B;
        const uint32_t b2sb = b2s0 + st * STAGE_B;

        #pragma unroll
        for (int ks = 0; ks < 4; ks++) {
            uint32_t a[4][4];
            #pragma unroll
            for (int mt = 0; mt < 4; mt++) {
                const int r = rA[mt];
                const int ch = (ks * 2 + qh) ^ (r & 7);
                LDSM4(a[mt][0], a[mt][1], a[mt][2], a[mt][3],
                      asb + r * RB + ch * 16);
            }
            uint32_t f1[2][4], f2[2][4];
            #pragma unroll
            for (int p = 0; p < 2; p++) {
                const int n = nB[p];
                const int ch = ((ks * 2 + ql) ^ (n & 7)) * 16;
                LDSM4(f1[p][0], f1[p][1], f1[p][2], f1[p][3], b1sb + n * RB + ch);
                LDSM4(f2[p][0], f2[p][1], f2[p][2], f2[p][3], b2sb + n * RB + ch);
            }
            #pragma unroll
            for (int nt = 0; nt < 4; nt++) {
                const int p = nt >> 1, h = (nt & 1) * 2;
                #pragma unroll
                for (int mt = 0; mt < 4; mt++) {
                    mma_bf16(acc1[mt][nt], a[mt], f1[p][h], f1[p][h + 1]);
                    mma_bf16(acc2[mt][nt], a[mt], f2[p][h], f2[p][h + 1]);
                }
            }
        }
        __syncthreads();
    }

    // ---- fused epilogue ----
    const int grp = lane >> 2;
    const int tig = lane & 3;
    bf16*  stage = (bf16*)smc;                     // transpose staging
    float* pst   = (float*)(smc + PSTAGE_OFF);     // partial staging [4][128][2]
    const int wcol = wid & 3;

    float2 w1v[4], w2v[4];
    if (mode == 0 && ps1) {
        #pragma unroll
        for (int nt = 0; nt < 4; nt++) {
            const int col = bn + n0 + nt * 8 + tig * 2;
            w1v[nt] = *(const float2*)(w12 + col);
            w2v[nt] = *(const float2*)(w12 + U_ + col);
        }
    }

    #pragma unroll
    for (int mt = 0; mt < 4; mt++) {
        const int rl  = m0 + mt * 16 + grp;     // local row
        const int row = bm + rl;
        float s1r = 0.f, s2r = 0.f, s1r8 = 0.f, s2r8 = 0.f;
        #pragma unroll
        for (int nt = 0; nt < 4; nt++) {
            const int cl  = n0 + nt * 8 + tig * 2;   // local col
            const int col = bn + cl;
            const float p10 = b1[col], p11 = b1[col + 1];
            const float p20 = b2[col], p21 = b2[col + 1];
            const long i0 = (long)row * U_ + col;
            const long i8 = (long)(row + 8) * U_ + col;
            float2 x0v, x8v;
            if (e2f) {
                x0v = *(const float2*)(e2f + i0);
                x8v = *(const float2*)(e2f + i8);
            } else {
                x0v = b2f(*(const bf162*)(e2b + i0));
                x8v = b2f(*(const bf162*)(e2b + i8));
            }
            float u0 = acc1[mt][nt][0] + p10, u1 = acc1[mt][nt][1] + p11;
            float u2 = acc1[mt][nt][2] + p10, u3 = acc1[mt][nt][3] + p11;
            float w0 = acc2[mt][nt][0] + p20, w1 = acc2[mt][nt][1] + p21;
            float w2 = acc2[mt][nt][2] + p20, w3v = acc2[mt][nt][3] + p21;
            if (mode == 0) {
                u0 = fmaxf(u0, 0.f); u1 = fmaxf(u1, 0.f);
                u2 = fmaxf(u2, 0.f); u3 = fmaxf(u3, 0.f);
                w0 = sigm(w0); w1 = sigm(w1); w2 = sigm(w2); w3v = sigm(w3v);
                const float o0 = u0 * w0 + x0v.x * (1.f - w0);
                const float o1 = u1 * w1 + x0v.y * (1.f - w1);
                const float o2 = u2 * w2 + x8v.x * (1.f - w2);
                const float o3 = u3 * w3v + x8v.y * (1.f - w3v);
                const bf162 pk0 = __floats2bfloat162_rn(o0, o1);
                const bf162 pk8 = __floats2bfloat162_rn(o2, o3);
                *(bf162*)(Xbout + i0) = pk0;
                *(bf162*)(Xbout + i8) = pk8;
                if (xw3o) {
                    const float2 wv = *(const float2*)(w3 + col);
                    *(bf162*)(xw3o + i0) = __floats2bfloat162_rn(o0 * wv.x, o1 * wv.y);
                    *(bf162*)(xw3o + i8) = __floats2bfloat162_rn(o2 * wv.x, o3 * wv.y);
                }
                if (x1to) {
                    stage[cl * TPITCH + rl]           = pk0.x;
                    stage[(cl + 1) * TPITCH + rl]     = pk0.y;
                    stage[cl * TPITCH + rl + 8]       = pk8.x;
                    stage[(cl + 1) * TPITCH + rl + 8] = pk8.y;
                }
                if (ps1) {
                    const float2 f0 = b2f(pk0), f8 = b2f(pk8);
                    s1r  += f0.x * w1v[nt].x + f0.y * w1v[nt].y;
                    s2r  += f0.x * w2v[nt].x + f0.y * w2v[nt].y;
                    s1r8 += f8.x * w1v[nt].x + f8.y * w1v[nt].y;
                    s2r8 += f8.x * w2v[nt].x + f8.y * w2v[nt].y;
                }
            } else {
                u0 = sigm(u0); u1 = sigm(u1); u2 = sigm(u2); u3 = sigm(u3);
                w0 = sigm(w0); w1 = sigm(w1); w2 = sigm(w2); w3v = sigm(w3v);
                const float o0 = w0 * x0v.x + u0 * u0;
                const float o1 = w1 * x0v.y + u1 * u1;
                const float o2 = w2 * x8v.x + u2 * u2;
                const float o3 = w3v * x8v.y + u3 * u3;
                *(float2*)(Xout + i0) = make_float2(o0, o1);
                *(float2*)(Xout + i8) = make_float2(o2, o3);
            }
        }
        if (mode == 0 && ps1) {
            #pragma unroll
            for (int msk = 1; msk <= 2; msk <<= 1) {
                s1r  += __shfl_xor_sync(0xffffffffu, s1r,  msk);
                s2r  += __shfl_xor_sync(0xffffffffu, s2r,  msk);
                s1r8 += __shfl_xor_sync(0xffffffffu, s1r8, msk);
                s2r8 += __shfl_xor_sync(0xffffffffu, s2r8, msk);
            }
            if (tig == 0) {
                pst[((wcol * 128 + rl)     << 1)]     = s1r;
                pst[((wcol * 128 + rl)     << 1) + 1] = s2r;
                pst[((wcol * 128 + rl + 8) << 1)]     = s1r8;
                pst[((wcol * 128 + rl + 8) << 1) + 1] = s2r8;
            }
        }
    }

    // ---- transposed write-out + partial reduce ----
    if (mode == 0 && (x1to || ps1)) {
        __syncthreads();
        if (x1to) {
            const int b0 = bm >> 10;         // batch (L_ = 1024)
            const int l0 = bm & 1023;
            const int cw = wid * 16;         // 16 cols per warp
            #pragma unroll
            for (int cc = 0; cc < 16; cc++) {
                const int c = cw + cc;
                const uint2 v = *(const uint2*)(stage + c * TPITCH + lane * 4);
                *(uint2*)(x1to + ((long)b0 * U_ + bn + c) * L_ + l0 + lane * 4) = v;
            }
        }
        if (ps1) {
            const int rl = tid >> 1, v = tid & 1;
            const float s = pst[((0 * 128 + rl) << 1) + v]
                          + pst[((1 * 128 + rl) << 1) + v]
                          + pst[((2 * 128 + rl) << 1) + v]
                          + pst[((3 * 128 + rl) << 1) + v];
            (v ? ps2 : ps1)[blockIdx.x * M_ + bm + rl] = s;
        }
    }
}

// ---------------------------------------------------------------------------
// Single bf16 GEMM (scores / att):
//   acc = sum_k A[m,k]*Bt[n,k] + rowbias[m] + colbias[n] + addc
// act 3: exp(relu(.)) -> Cb, plus per-CTA partial row sums to prow.
// act 0: v * rowscale[row] -> Cb.
// ---------------------------------------------------------------------------
__global__ __launch_bounds__(256) void gemm_bf(
    const bf16* __restrict__ A,  long lda, long sA,
    const bf16* __restrict__ Bt, long ldb, long sB,
    bf16* __restrict__ Cb, long ldcb, long sCb,
    int K,
    const float* __restrict__ rowbias, long srb,
    const float* __restrict__ colbias, long scb,
    const float* __restrict__ addc,
    const float* __restrict__ rowscale, long srs,
    int act,
    float* __restrict__ prow)
{
    extern __shared__ char smc[];
    const uint32_t as0 = smem_u32(smc);
    const uint32_t bs0 = as0 + NSTG * STAGE_B;

    const int tid  = threadIdx.x;
    const int wid  = tid >> 5;
    const int lane = tid & 31;
    const int li   = lane & 7;
    const int q    = lane >> 3;
    const int ql   = q & 1;
    const int qh   = q >> 1;
    const int m0   = (wid >> 2) * 64;
    const int n0   = (wid & 3)  * 32;

    const int bz = blockIdx.z;
    const int bm = blockIdx.y * 128;
    const int bn = blockIdx.x * 128;

    const bf16* Ag = A  + (long)bz * sA;
    const bf16* Bg = Bt + (long)bz * sB;

    const int lrow = tid >> 1;
    const int lcb  = (tid & 1) * 4;
    const int nch  = K / KC;

    float acc[4][4][4];
    #pragma unroll
    for (int i = 0; i < 4; i++)
        #pragma unroll
        for (int j = 0; j < 4; j++)
            #pragma unroll
            for (int k = 0; k < 4; k++) acc[i][j][k] = 0.f;

    auto load_chunk = [&](int c) {
        const int st = c % NSTG;
        const bf16* ap = Ag + (long)(bm + lrow) * lda + c * KC;
        const bf16* bp = Bg + (long)(bn + lrow) * ldb + c * KC;
        const uint32_t ad = as0 + st * STAGE_B + lrow * RB;
        const uint32_t bd = bs0 + st * STAGE_B + lrow * RB;
        const int sw = lrow & 7;
        #pragma unroll
        for (int j = 0; j < 4; j++) {
            const int ch = lcb + j;
            const int cho = (ch ^ sw) * 16;
            cpasync16(ad + cho, ap + ch * 8);
            cpasync16(bd + cho, bp + ch * 8);
        }
        CP_COMMIT();
    };

    load_chunk(0);
    if (nch > 1) load_chunk(1);

    int rA[4], nB[2];
    #pragma unroll
    for (int mt = 0; mt < 4; mt++) rA[mt] = m0 + mt * 16 + li + ql * 8;
    #pragma unroll
    for (int p = 0; p < 2; p++)    nB[p] = n0 + p * 16 + qh * 8 + li;

    for (int c = 0; c < nch; c++) {
        const int st = c % NSTG;
        if (c + 1 < nch) CP_WAIT(1); else CP_WAIT(0);
        __syncthreads();
        if (c + 2 < nch) load_chunk(c + 2);

        const uint32_t asb = as0 + st * STAGE_B;
        const uint32_t bsb = bs0 + st * STAGE_B;

        #pragma unroll
        for (int ks = 0; ks < 4; ks++) {
            uint32_t a[4][4];
            #pragma unroll
            for (int mt = 0; mt < 4; mt++) {
                const int r = rA[mt];
                const int ch = (ks * 2 + qh) ^ (r & 7);
                LDSM4(a[mt][0], a[mt][1], a[mt][2], a[mt][3],
                      asb + r * RB + ch * 16);
            }
            uint32_t b[2][4];
            #pragma unroll
            for (int p = 0; p < 2; p++) {
                const int n = nB[p];
                const int ch = (ks * 2 + ql) ^ (n & 7);
                LDSM4(b[p][0], b[p][1], b[p][2], b[p][3],
                      bsb + n * RB + ch * 16);
            }
            #pragma unroll
            for (int nt = 0; nt < 4; nt++) {
                const uint32_t b0 = b[nt >> 1][(nt & 1) * 2];
                const uint32_t b1 = b[nt >> 1][(nt & 1) * 2 + 1];
                #pragma unroll
                for (int mt = 0; mt < 4; mt++)
                    mma_bf16(acc[mt][nt], a[mt], b0, b1);
            }
        }
        __syncthreads();
    }

    const int grp = lane >> 2;
    const int tig = lane & 3;
    const int wcol = wid & 3;
    bf16* Cbp = Cb + (long)bz * sCb;
    float* pst = (float*)smc;                // [4][128] partial staging
    const float a0 = addc ? addc[0] : 0.f;

    #pragma unroll
    for (int mt = 0; mt < 4; mt++) {
        const int rl  = m0 + mt * 16 + grp;
        const int row = bm + rl;
        float rb0 = a0, rb8 = a0;
        if (rowbias) {
            rb0 += rowbias[(long)bz * srb + row];
            rb8 += rowbias[(long)bz * srb + row + 8];
        }
        float sc0 = 1.f, sc8 = 1.f;
        if (rowscale) {
            sc0 = rowscale[(long)bz * srs + row];
            sc8 = rowscale[(long)bz * srs + row + 8];
        }
        float sr = 0.f, sr8 = 0.f;
        #pragma unroll
        for (int nt = 0; nt < 4; nt++) {
            const int col = bn + n0 + nt * 8 + tig * 2;
            float cb0 = 0.f, cb1 = 0.f;
            if (colbias) {
                cb0 = colbias[(long)bz * scb + col];
                cb1 = colbias[(long)bz * scb + col + 1];
            }
            float v0 = acc[mt][nt][0] + rb0 + cb0;
            float v1 = acc[mt][nt][1] + rb0 + cb1;
            float v2 = acc[mt][nt][2] + rb8 + cb0;
            float v3 = acc[mt][nt][3] + rb8 + cb1;
            if (act == 3) {
                v0 = __expf(fmaxf(v0, 0.f)); v1 = __expf(fmaxf(v1, 0.f));
                v2 = __expf(fmaxf(v2, 0.f)); v3 = __expf(fmaxf(v3, 0.f));
            } else {
                v0 *= sc0; v1 *= sc0; v2 *= sc8; v3 *= sc8;
            }
            const bf162 pk0 = __floats2bfloat162_rn(v0, v1);
            const bf162 pk8 = __floats2bfloat162_rn(v2, v3);
            *(bf162*)(Cbp + (long)row * ldcb + col)       = pk0;
            *(bf162*)(Cbp + (long)(row + 8) * ldcb + col) = pk8;
            if (act == 3 && prow) {
                const float2 f0 = b2f(pk0), f8 = b2f(pk8);
                sr  += f0.x + f0.y;
                sr8 += f8.x + f8.y;
            }
        }
        if (act == 3 && prow) {
            #pragma unroll
            for (int msk = 1; msk <= 2; msk <<= 1) {
                sr  += __shfl_xor_sync(0xffffffffu, sr,  msk);
                sr8 += __shfl_xor_sync(0xffffffffu, sr8, msk);
            }
            if (tig == 0) {
                pst[wcol * 128 + rl]     = sr;
                pst[wcol * 128 + rl + 8] = sr8;
            }
        }
    }

    if (act == 3 && prow) {
        __syncthreads();
        if (tid < 128) {
            const float s = pst[tid] + pst[128 + tid]
                          + pst[256 + tid] + pst[384 + tid];
            prow[(long)blockIdx.x * M_ + (long)bz * L_ + bm + tid] = s;
        }
    }
}

// ---------------------------------------------------------------------------
// Merged prologue: conv_inputs (blocks 0..8191) + 4 weight transposes
// ---------------------------------------------------------------------------
__global__ __launch_bounds__(256) void prologue(
    const float* __restrict__ in, bf16* __restrict__ ib, bf16* __restrict__ cat,
    const float* __restrict__ tW, bf16* __restrict__ tWt,
    const float* __restrict__ cW, bf16* __restrict__ cWt,
    const float* __restrict__ ffW, bf16* __restrict__ ffWt,
    const float* __restrict__ frW, bf16* __restrict__ frWt)
{
    const int bid = blockIdx.x;
    if (bid < 8192) {
        const int i = bid * 256 + threadIdx.x;     // over M*U/4
        const float4 v = ((const float4*)in)[i];
        const bf162 p0 = __floats2bfloat162_rn(v.x, v.y);
        const bf162 p1 = __floats2bfloat162_rn(v.z, v.w);
        *(bf162*)(ib + (long)i * 4)     = p0;
        *(bf162*)(ib + (long)i * 4 + 2) = p1;
        const int m  = i >> 7;
        const int c4 = i & 127;
        bf16* cr = cat + (long)m * (2 * U_) + c4 * 4;
        *(bf162*)cr       = p0;
        *(bf162*)(cr + 2) = p1;
        return;
    }
    __shared__ float tile[32][33];
    const int s = bid - 8192;
    const int job = s >> 9;
    const int r   = s & 511;
    const float* src; bf16* dst; int R, Cc, r0, c0;
    if (job < 2) {
        const int layer = r >> 8, w = r & 255;
        src = (job == 0 ? tW : cW) + (long)layer * U_ * U_;
        dst = (job == 0 ? tWt : cWt) + (long)layer * U_ * U_;
        R = U_; Cc = U_; c0 = (w & 15) * 32; r0 = (w >> 4) * 32;
    } else {
        src = (job == 2 ? ffW : frW);
        dst = (job == 2 ? ffWt : frWt);
        R = 2 * U_; Cc = U_; c0 = (r & 15) * 32; r0 = (r >> 4) * 32;
    }
    const int tx = threadIdx.x & 31, ty = threadIdx.x >> 5;
    #pragma unroll
    for (int i2 = 0; i2 < 32; i2 += 8)
        tile[ty + i2][tx] = src[(long)(r0 + ty + i2) * Cc + c0 + tx];
    __syncthreads();
    #pragma unroll
    for (int i2 = 0; i2 < 32; i2 += 8)
        dst[(long)(c0 + ty + i2) * R + r0 + tx] = __float2bfloat16(tile[tx][ty + i2]);
}

// ---------------------------------------------------------------------------
// reduce_s: s1[r] = sum_j ps1[j][r] (+ same for s2)
// ---------------------------------------------------------------------------
__global__ __launch_bounds__(256) void reduce_s(
    const float* __restrict__ ps1, const float* __restrict__ ps2,
    float* __restrict__ s1, float* __restrict__ s2)
{
    const int r = blockIdx.x * 256 + threadIdx.x;
    float a = 0.f, b = 0.f;
    #pragma unroll
    for (int j = 0; j < 4; j++) {
        a += ps1[(long)j * M_ + r];
        b += ps2[(long)j * M_ + r];
    }
    s1[r] = a;
    s2[r] = b;
}

// ---------------------------------------------------------------------------
// reduce_r: rinv[r] = 1 / sum_j pr[j][r]
// ---------------------------------------------------------------------------
__global__ __launch_bounds__(256) void reduce_r(
    const float* __restrict__ pr, float* __restrict__ rinv)
{
    const int r = blockIdx.x * 256 + threadIdx.x;
    float s = 0.f;
    #pragma unroll
    for (int j = 0; j < 8; j++)
        s += pr[(long)j * M_ + r];
    rinv[r] = 1.f / s;
}

// ---------------------------------------------------------------------------
// Launch
// ---------------------------------------------------------------------------
#define GEMM_SMEM (2 * NSTG * STAGE_B)   // 96 KB  (single GEMM)
#define DUAL_SMEM (3 * NSTG * STAGE_B)   // 144 KB (dual GEMM)

extern "C" void kernel_launch(void* const* d_in, const int* in_sizes, int n_in,
                              void* d_out, int out_size)
{
    (void)in_sizes; (void)n_in; (void)out_size;
    const float* inputs = (const float*)d_in[0];
    const float* tW     = (const float*)d_in[1];
    const float* tb     = (const float*)d_in[2];
    const float* cW     = (const float*)d_in[3];
    const float* cb     = (const float*)d_in[4];
    const float* aW     = (const float*)d_in[5];
    const float* ab     = (const float*)d_in[6];
    const float* frW    = (const float*)d_in[7];
    const float* frb    = (const float*)d_in[8];
    const float* ffW    = (const float*)d_in[9];
    const float* ffb    = (const float*)d_in[10];
    float* out = (float*)d_out;

    float *s1, *s2, *rs, *ps1, *ps2, *pr;
    bf16 *ib, *x0b, *x1b, *xw3, *x1t, *cat, *As, *tWt, *cWt, *ffWt, *frWt;
    cudaGetSymbolAddress((void**)&s1,   g_s1);
    cudaGetSymbolAddress((void**)&s2,   g_s2);
    cudaGetSymbolAddress((void**)&rs,   g_rs);
    cudaGetSymbolAddress((void**)&ps1,  g_ps1);
    cudaGetSymbolAddress((void**)&ps2,  g_ps2);
    cudaGetSymbolAddress((void**)&pr,   g_pr);
    cudaGetSymbolAddress((void**)&ib,   g_ib);
    cudaGetSymbolAddress((void**)&x0b,  g_x0b);
    cudaGetSymbolAddress((void**)&x1b,  g_x1b);
    cudaGetSymbolAddress((void**)&xw3,  g_xw3);
    cudaGetSymbolAddress((void**)&x1t,  g_x1t);
    cudaGetSymbolAddress((void**)&cat,  g_cat);
    cudaGetSymbolAddress((void**)&As,   g_As);
    cudaGetSymbolAddress((void**)&tWt,  g_tWt);
    cudaGetSymbolAddress((void**)&cWt,  g_cWt);
    cudaGetSymbolAddress((void**)&ffWt, g_ffWt);
    cudaGetSymbolAddress((void**)&frWt, g_frWt);

    cudaFuncSetAttribute(gemm_bf, cudaFuncAttributeMaxDynamicSharedMemorySize,
                         GEMM_SMEM);
    cudaFuncSetAttribute(gemm_dual, cudaFuncAttributeMaxDynamicSharedMemorySize,
                         DUAL_SMEM);

    // 1. merged prologue (inputs->bf16 + cat, 4 weight transposes)
    prologue<<<10240, 256>>>(inputs, ib, cat, tW, tWt, cW, cWt,
                             ffW, ffWt, frW, frWt);

    dim3 gHW(U_/128, M_/128);      // (4,128)
    // 2. highway layer 0 (dual)
    gemm_dual<<<gHW, 256, DUAL_SMEM>>>(ib, U_, tWt, cWt, U_,
                                       nullptr, x0b, inputs, nullptr, U_,
                                       tb, cb, 0, nullptr, nullptr, nullptr,
                                       nullptr, nullptr, nullptr);
    // 3. highway layer 1 (dual) + fused xw3, x1^T, s1/s2 partials
    gemm_dual<<<gHW, 256, DUAL_SMEM>>>(x0b, U_, tWt + U_*U_, cWt + U_*U_, U_,
                                       nullptr, x1b, nullptr, x0b, U_,
                                       tb + U_, cb + U_, 0,
                                       aW + 2*U_, xw3, x1t,
                                       aW, ps1, ps2);

    // 4. reduce s1/s2 partials
    reduce_s<<<M_/256, 256>>>(ps1, ps2, s1, s2);

    // 5. scores: As[b] = exp(relu( xw3 @ x1^T + s1 + s2 + ab )) + rowsum partials
    dim3 gS(L_/128, L_/128, B_);
    gemm_bf<<<gS, 256, GEMM_SMEM>>>(xw3, U_, (long)L_*U_, x1b, U_, (long)L_*U_,
                                    As, L_, (long)L_*L_, U_,
                                    s1, L_, s2, L_, ab, nullptr, 0, 3, pr);

    // 6. reciprocal row sums from partials
    reduce_r<<<M_/256, 256>>>(pr, rs);

    // 7. att = (expA @ x1) * rinv[row] -> bf16 into cat second half
    dim3 gAtt(U_/128, L_/128, B_);
    gemm_bf<<<gAtt, 256, GEMM_SMEM>>>(As, L_, (long)L_*L_, x1t, L_, (long)U_*L_,
                                      cat + U_, 2*U_, (long)L_*2*U_, L_,
                                      nullptr, 0, nullptr, 0, nullptr,
                                      rs, L_, 0, nullptr);

    // 8. final dual: out = sig(cat@frW+frb)*inputs + sig(cat@ffW+ffb)^2
    gemm_dual<<<gHW, 256, DUAL_SMEM>>>(cat, 2*U_, ffWt, frWt, 2*U_,
                                       out, nullptr, inputs, nullptr, 2*U_,
                                       ffb, frb, 1, nullptr, nullptr, nullptr,
                                       nullptr, nullptr, nullptr);
}

// round 11
// speedup vs baseline: 1.1293x; 1.0077x over previous
#include <cuda_runtime.h>
#include <cuda_bf16.h>
#include <cstdint>

#define B_  16
#define L_  1024
#define U_  512
#define M_  (B_*L_)      // 16384

typedef __nv_bfloat16  bf16;
typedef __nv_bfloat162 bf162;

// ---------------------------------------------------------------------------
// Scratch (device globals; no allocation allowed)
// ---------------------------------------------------------------------------
__device__ float g_ps1[4*M_];           // s1 partials (per col-block)
__device__ float g_ps2[4*M_];           // s2 partials
__device__ float g_pr [8*M_];           // rowsum partials

__device__ bf16 g_ib  [M_*U_];          // inputs bf16
__device__ bf16 g_x0b [M_*U_];
__device__ bf16 g_x1b [M_*U_];
__device__ bf16 g_xw3 [M_*U_];          // x1 * w3
__device__ bf16 g_x1t [M_*U_];          // per-batch [U][L]
__device__ bf16 g_cat [(size_t)M_*2*U_];
__device__ bf16 g_As  [(size_t)B_*L_*L_];  // exp(relu(scores))
__device__ bf16 g_tWt [2*U_*U_];
__device__ bf16 g_cWt [2*U_*U_];
__device__ bf16 g_ffWt[2*U_*U_];        // [512][1024]
__device__ bf16 g_frWt[2*U_*U_];        // [512][1024]

// ---------------------------------------------------------------------------
// PTX helpers (baseline PTX; compile at compute_103)
// ---------------------------------------------------------------------------
__device__ __forceinline__ uint32_t smem_u32(const void* p) {
    uint32_t a;
    asm("{ .reg .u64 t; cvta.to.shared.u64 t, %1; cvt.u32.u64 %0, t; }"
        : "=r"(a) : "l"(p));
    return a;
}
__device__ __forceinline__ void cpasync16(uint32_t dst, const void* src) {
    asm volatile("cp.async.cg.shared.global [%0], [%1], 16;"
                 :: "r"(dst), "l"(src));
}
#define CP_COMMIT() asm volatile("cp.async.commit_group;" ::: "memory")
#define CP_WAIT(n)  asm volatile("cp.async.wait_group %0;" :: "n"(n) : "memory")

#define LDSM4(r0, r1, r2, r3, addr) \
    asm volatile("ldmatrix.sync.aligned.m8n8.x4.shared.b16 {%0,%1,%2,%3}, [%4];" \
        : "=r"(r0), "=r"(r1), "=r"(r2), "=r"(r3) : "r"(addr))

__device__ __forceinline__ void mma_bf16(float* c, const uint32_t* a,
                                         uint32_t b0, uint32_t b1) {
    asm volatile(
        "mma.sync.aligned.m16n8k16.row.col.f32.bf16.bf16.f32 "
        "{%0,%1,%2,%3}, {%4,%5,%6,%7}, {%8,%9}, {%0,%1,%2,%3};"
        : "+f"(c[0]), "+f"(c[1]), "+f"(c[2]), "+f"(c[3])
        : "r"(a[0]), "r"(a[1]), "r"(a[2]), "r"(a[3]), "r"(b0), "r"(b1));
}

__device__ __forceinline__ float sigm(float v) {
    return 1.f / (1.f + __expf(-v));
}
__device__ __forceinline__ float2 b2f(bf162 p) {
    return make_float2(__bfloat162float(p.x), __bfloat162float(p.y));
}

#define KC 64
#define RB 128                 // row bytes (KC bf16)
#define STAGE_B (128*RB)       // 16 KB
#define NSTG 3
#define TPITCH 136             // bf16 pitch for transpose staging
#define PSTAGE_OFF 36864       // byte offset of partial staging in dual smem

// ---------------------------------------------------------------------------
// DUAL bf16 GEMM: two GEMMs sharing the A operand, fused combine epilogue.
//   acc1[m,n] = sum_k A[m,k]*B1[n,k] + b1[n]
//   acc2[m,n] = sum_k A[m,k]*B2[n,k] + b2[n]
// mode 0 (highway): t=relu(acc1); c=sig(acc2); o = t*c + e*(1-c) -> Xbout bf16
//     extras: xw3o = o*w3[n]; x1to = per-batch transposed o;
//     ps1/ps2 = per-CTA partial row-dots of rounded o with w12 / w12+U.
// mode 1 (final):   z=sig(acc1);  r=sig(acc2); o = r*e2f + z*z -> Xout fp32
// ---------------------------------------------------------------------------
__global__ __launch_bounds__(256, 1) void gemm_dual(
    const bf16* __restrict__ A,  long lda,
    const bf16* __restrict__ B1, const bf16* __restrict__ B2, long ldb,
    float* __restrict__ Xout, bf16* __restrict__ Xbout,
    const float* __restrict__ e2f, const bf16* __restrict__ e2b,
    int K,
    const float* __restrict__ b1, const float* __restrict__ b2,
    int mode,
    const float* __restrict__ w3, bf16* __restrict__ xw3o,
    bf16* __restrict__ x1to,
    const float* __restrict__ w12,
    float* __restrict__ ps1, float* __restrict__ ps2)
{
    extern __shared__ char smc[];
    const uint32_t as0  = smem_u32(smc);
    const uint32_t b1s0 = as0  + NSTG * STAGE_B;
    const uint32_t b2s0 = b1s0 + NSTG * STAGE_B;

    const int tid  = threadIdx.x;
    const int wid  = tid >> 5;
    const int lane = tid & 31;
    const int li   = lane & 7;
    const int q    = lane >> 3;
    const int ql   = q & 1;
    const int qh   = q >> 1;
    const int m0   = (wid >> 2) * 64;
    const int n0   = (wid & 3)  * 32;

    const int bm = blockIdx.y * 128;
    const int bn = blockIdx.x * 128;

    const int lrow = tid >> 1;
    const int lcb  = (tid & 1) * 4;
    const int nch  = K / KC;

    float acc1[4][4][4], acc2[4][4][4];
    #pragma unroll
    for (int i = 0; i < 4; i++)
        #pragma unroll
        for (int j = 0; j < 4; j++)
            #pragma unroll
            for (int k = 0; k < 4; k++) { acc1[i][j][k] = 0.f; acc2[i][j][k] = 0.f; }

    auto load_chunk = [&](int c) {
        const int st = c % NSTG;
        const bf16* ap  = A  + (long)(bm + lrow) * lda + c * KC;
        const bf16* b1p = B1 + (long)(bn + lrow) * ldb + c * KC;
        const bf16* b2p = B2 + (long)(bn + lrow) * ldb + c * KC;
        const uint32_t ad  = as0  + st * STAGE_B + lrow * RB;
        const uint32_t bd1 = b1s0 + st * STAGE_B + lrow * RB;
        const uint32_t bd2 = b2s0 + st * STAGE_B + lrow * RB;
        const int sw = lrow & 7;
        #pragma unroll
        for (int j = 0; j < 4; j++) {
            const int ch  = lcb + j;
            const int cho = (ch ^ sw) * 16;
            cpasync16(ad  + cho, ap  + ch * 8);
            cpasync16(bd1 + cho, b1p + ch * 8);
            cpasync16(bd2 + cho, b2p + ch * 8);
        }
        CP_COMMIT();
    };

    load_chunk(0);
    if (nch > 1) load_chunk(1);

    int rA[4], nB[2];
    #pragma unroll
    for (int mt = 0; mt < 4; mt++) rA[mt] = m0 + mt * 16 + li + ql * 8;
    #pragma unroll
    for (int p = 0; p < 2; p++)    nB[p] = n0 + p * 16 + qh * 8 + li;

    for (int c = 0; c < nch; c++) {
        const int st = c % NSTG;
        if (c + 1 < nch) CP_WAIT(1); else CP_WAIT(0);
        __syncthreads();
        if (c + 2 < nch) load_chunk(c + 2);

        const uint32_t asb  = as0  + st * STAGE_B;
        const uint32_t b1sb = b1s0 + st * STAGE_B;
        const uint32_t b2sb = b2s0 + st * STAGE_B;

        #pragma unroll
        for (int ks = 0; ks < 4; ks++) {
            uint32_t a[4][4];
            #pragma unroll
            for (int mt = 0; mt < 4; mt++) {
                const int r = rA[mt];
                const int ch = (ks * 2 + qh) ^ (r & 7);
                LDSM4(a[mt][0], a[mt][1], a[mt][2], a[mt][3],
                      asb + r * RB + ch * 16);
            }
            uint32_t f1[2][4], f2[2][4];
            #pragma unroll
            for (int p = 0; p < 2; p++) {
                const int n = nB[p];
                const int ch = ((ks * 2 + ql) ^ (n & 7)) * 16;
                LDSM4(f1[p][0], f1[p][1], f1[p][2], f1[p][3], b1sb + n * RB + ch);
                LDSM4(f2[p][0], f2[p][1], f2[p][2], f2[p][3], b2sb + n * RB + ch);
            }
            #pragma unroll
            for (int nt = 0; nt < 4; nt++) {
                const int p = nt >> 1, h = (nt & 1) * 2;
                #pragma unroll
                for (int mt = 0; mt < 4; mt++) {
                    mma_bf16(acc1[mt][nt], a[mt], f1[p][h], f1[p][h + 1]);
                    mma_bf16(acc2[mt][nt], a[mt], f2[p][h], f2[p][h + 1]);
                }
            }
        }
        __syncthreads();
    }

    // ---- fused epilogue ----
    const int grp = lane >> 2;
    const int tig = lane & 3;
    bf16*  stage = (bf16*)smc;                     // transpose staging
    float* pst   = (float*)(smc + PSTAGE_OFF);     // partial staging [4][128][2]
    const int wcol = wid & 3;

    float2 w1v[4], w2v[4];
    if (mode == 0 && ps1) {
        #pragma unroll
        for (int nt = 0; nt < 4; nt++) {
            const int col = bn + n0 + nt * 8 + tig * 2;
            w1v[nt] = *(const float2*)(w12 + col);
            w2v[nt] = *(const float2*)(w12 + U_ + col);
        }
    }

    #pragma unroll
    for (int mt = 0; mt < 4; mt++) {
        const int rl  = m0 + mt * 16 + grp;     // local row
        const int row = bm + rl;
        float s1r = 0.f, s2r = 0.f, s1r8 = 0.f, s2r8 = 0.f;
        #pragma unroll
        for (int nt = 0; nt < 4; nt++) {
            const int cl  = n0 + nt * 8 + tig * 2;   // local col
            const int col = bn + cl;
            const float p10 = b1[col], p11 = b1[col + 1];
            const float p20 = b2[col], p21 = b2[col + 1];
            const long i0 = (long)row * U_ + col;
            const long i8 = (long)(row + 8) * U_ + col;
            float2 x0v, x8v;
            if (e2f) {
                x0v = *(const float2*)(e2f + i0);
                x8v = *(const float2*)(e2f + i8);
            } else {
                x0v = b2f(*(const bf162*)(e2b + i0));
                x8v = b2f(*(const bf162*)(e2b + i8));
            }
            float u0 = acc1[mt][nt][0] + p10, u1 = acc1[mt][nt][1] + p11;
            float u2 = acc1[mt][nt][2] + p10, u3 = acc1[mt][nt][3] + p11;
            float w0 = acc2[mt][nt][0] + p20, w1 = acc2[mt][nt][1] + p21;
            float w2 = acc2[mt][nt][2] + p20, w3v = acc2[mt][nt][3] + p21;
            if (mode == 0) {
                u0 = fmaxf(u0, 0.f); u1 = fmaxf(u1, 0.f);
                u2 = fmaxf(u2, 0.f); u3 = fmaxf(u3, 0.f);
                w0 = sigm(w0); w1 = sigm(w1); w2 = sigm(w2); w3v = sigm(w3v);
                const float o0 = u0 * w0 + x0v.x * (1.f - w0);
                const float o1 = u1 * w1 + x0v.y * (1.f - w1);
                const float o2 = u2 * w2 + x8v.x * (1.f - w2);
                const float o3 = u3 * w3v + x8v.y * (1.f - w3v);
                const bf162 pk0 = __floats2bfloat162_rn(o0, o1);
                const bf162 pk8 = __floats2bfloat162_rn(o2, o3);
                *(bf162*)(Xbout + i0) = pk0;
                *(bf162*)(Xbout + i8) = pk8;
                if (xw3o) {
                    const float2 wv = *(const float2*)(w3 + col);
                    *(bf162*)(xw3o + i0) = __floats2bfloat162_rn(o0 * wv.x, o1 * wv.y);
                    *(bf162*)(xw3o + i8) = __floats2bfloat162_rn(o2 * wv.x, o3 * wv.y);
                }
                if (x1to) {
                    stage[cl * TPITCH + rl]           = pk0.x;
                    stage[(cl + 1) * TPITCH + rl]     = pk0.y;
                    stage[cl * TPITCH + rl + 8]       = pk8.x;
                    stage[(cl + 1) * TPITCH + rl + 8] = pk8.y;
                }
                if (ps1) {
                    const float2 f0 = b2f(pk0), f8 = b2f(pk8);
                    s1r  += f0.x * w1v[nt].x + f0.y * w1v[nt].y;
                    s2r  += f0.x * w2v[nt].x + f0.y * w2v[nt].y;
                    s1r8 += f8.x * w1v[nt].x + f8.y * w1v[nt].y;
                    s2r8 += f8.x * w2v[nt].x + f8.y * w2v[nt].y;
                }
            } else {
                u0 = sigm(u0); u1 = sigm(u1); u2 = sigm(u2); u3 = sigm(u3);
                w0 = sigm(w0); w1 = sigm(w1); w2 = sigm(w2); w3v = sigm(w3v);
                const float o0 = w0 * x0v.x + u0 * u0;
                const float o1 = w1 * x0v.y + u1 * u1;
                const float o2 = w2 * x8v.x + u2 * u2;
                const float o3 = w3v * x8v.y + u3 * u3;
                *(float2*)(Xout + i0) = make_float2(o0, o1);
                *(float2*)(Xout + i8) = make_float2(o2, o3);
            }
        }
        if (mode == 0 && ps1) {
            #pragma unroll
            for (int msk = 1; msk <= 2; msk <<= 1) {
                s1r  += __shfl_xor_sync(0xffffffffu, s1r,  msk);
                s2r  += __shfl_xor_sync(0xffffffffu, s2r,  msk);
                s1r8 += __shfl_xor_sync(0xffffffffu, s1r8, msk);
                s2r8 += __shfl_xor_sync(0xffffffffu, s2r8, msk);
            }
            if (tig == 0) {
                pst[((wcol * 128 + rl)     << 1)]     = s1r;
                pst[((wcol * 128 + rl)     << 1) + 1] = s2r;
                pst[((wcol * 128 + rl + 8) << 1)]     = s1r8;
                pst[((wcol * 128 + rl + 8) << 1) + 1] = s2r8;
            }
        }
    }

    // ---- transposed write-out + partial reduce ----
    if (mode == 0 && (x1to || ps1)) {
        __syncthreads();
        if (x1to) {
            const int b0 = bm >> 10;         // batch (L_ = 1024)
            const int l0 = bm & 1023;
            const int cw = wid * 16;         // 16 cols per warp
            #pragma unroll
            for (int cc = 0; cc < 16; cc++) {
                const int c = cw + cc;
                const uint2 v = *(const uint2*)(stage + c * TPITCH + lane * 4);
                *(uint2*)(x1to + ((long)b0 * U_ + bn + c) * L_ + l0 + lane * 4) = v;
            }
        }
        if (ps1) {
            const int rl = tid >> 1, v = tid & 1;
            const float s = pst[((0 * 128 + rl) << 1) + v]
                          + pst[((1 * 128 + rl) << 1) + v]
                          + pst[((2 * 128 + rl) << 1) + v]
                          + pst[((3 * 128 + rl) << 1) + v];
            (v ? ps2 : ps1)[blockIdx.x * M_ + bm + rl] = s;
        }
    }
}

// ---------------------------------------------------------------------------
// Single bf16 GEMM (scores / att):
//   acc = sum_k A[m,k]*Bt[n,k] + rowbias[m] + colbias[n] + addc
// rbn/cbn: number of partials (stride M_) summed inline for rowbias/colbias.
// rsn: if >0, rowscale value = 1/sum of rsn partials (stride M_).
// act 3: exp(relu(.)) -> Cb, plus per-CTA partial row sums to prow.
// act 0: v * rowscale -> Cb.
// ---------------------------------------------------------------------------
__global__ __launch_bounds__(256) void gemm_bf(
    const bf16* __restrict__ A,  long lda, long sA,
    const bf16* __restrict__ Bt, long ldb, long sB,
    bf16* __restrict__ Cb, long ldcb, long sCb,
    int K,
    const float* __restrict__ rowbias, long srb, int rbn,
    const float* __restrict__ colbias, long scb, int cbn,
    const float* __restrict__ addc,
    const float* __restrict__ rowscale, long srs, int rsn,
    int act,
    float* __restrict__ prow)
{
    extern __shared__ char smc[];
    const uint32_t as0 = smem_u32(smc);
    const uint32_t bs0 = as0 + NSTG * STAGE_B;

    const int tid  = threadIdx.x;
    const int wid  = tid >> 5;
    const int lane = tid & 31;
    const int li   = lane & 7;
    const int q    = lane >> 3;
    const int ql   = q & 1;
    const int qh   = q >> 1;
    const int m0   = (wid >> 2) * 64;
    const int n0   = (wid & 3)  * 32;

    const int bz = blockIdx.z;
    const int bm = blockIdx.y * 128;
    const int bn = blockIdx.x * 128;

    const bf16* Ag = A  + (long)bz * sA;
    const bf16* Bg = Bt + (long)bz * sB;

    const int lrow = tid >> 1;
    const int lcb  = (tid & 1) * 4;
    const int nch  = K / KC;

    float acc[4][4][4];
    #pragma unroll
    for (int i = 0; i < 4; i++)
        #pragma unroll
        for (int j = 0; j < 4; j++)
            #pragma unroll
            for (int k = 0; k < 4; k++) acc[i][j][k] = 0.f;

    auto load_chunk = [&](int c) {
        const int st = c % NSTG;
        const bf16* ap = Ag + (long)(bm + lrow) * lda + c * KC;
        const bf16* bp = Bg + (long)(bn + lrow) * ldb + c * KC;
        const uint32_t ad = as0 + st * STAGE_B + lrow * RB;
        const uint32_t bd = bs0 + st * STAGE_B + lrow * RB;
        const int sw = lrow & 7;
        #pragma unroll
        for (int j = 0; j < 4; j++) {
            const int ch = lcb + j;
            const int cho = (ch ^ sw) * 16;
            cpasync16(ad + cho, ap + ch * 8);
            cpasync16(bd + cho, bp + ch * 8);
        }
        CP_COMMIT();
    };

    load_chunk(0);
    if (nch > 1) load_chunk(1);

    int rA[4], nB[2];
    #pragma unroll
    for (int mt = 0; mt < 4; mt++) rA[mt] = m0 + mt * 16 + li + ql * 8;
    #pragma unroll
    for (int p = 0; p < 2; p++)    nB[p] = n0 + p * 16 + qh * 8 + li;

    for (int c = 0; c < nch; c++) {
        const int st = c % NSTG;
        if (c + 1 < nch) CP_WAIT(1); else CP_WAIT(0);
        __syncthreads();
        if (c + 2 < nch) load_chunk(c + 2);

        const uint32_t asb = as0 + st * STAGE_B;
        const uint32_t bsb = bs0 + st * STAGE_B;

        #pragma unroll
        for (int ks = 0; ks < 4; ks++) {
            uint32_t a[4][4];
            #pragma unroll
            for (int mt = 0; mt < 4; mt++) {
                const int r = rA[mt];
                const int ch = (ks * 2 + qh) ^ (r & 7);
                LDSM4(a[mt][0], a[mt][1], a[mt][2], a[mt][3],
                      asb + r * RB + ch * 16);
            }
            uint32_t b[2][4];
            #pragma unroll
            for (int p = 0; p < 2; p++) {
                const int n = nB[p];
                const int ch = (ks * 2 + ql) ^ (n & 7);
                LDSM4(b[p][0], b[p][1], b[p][2], b[p][3],
                      bsb + n * RB + ch * 16);
            }
            #pragma unroll
            for (int nt = 0; nt < 4; nt++) {
                const uint32_t b0 = b[nt >> 1][(nt & 1) * 2];
                const uint32_t b1 = b[nt >> 1][(nt & 1) * 2 + 1];
                #pragma unroll
                for (int mt = 0; mt < 4; mt++)
                    mma_bf16(acc[mt][nt], a[mt], b0, b1);
            }
        }
        __syncthreads();
    }

    const int grp = lane >> 2;
    const int tig = lane & 3;
    const int wcol = wid & 3;
    bf16* Cbp = Cb + (long)bz * sCb;
    float* pst = (float*)smc;                // [4][128] partial staging
    const float a0 = addc ? addc[0] : 0.f;

    // colbias precompute (independent of mt); inline partial-sum if cbn>1
    float cbv[4][2];
    #pragma unroll
    for (int nt = 0; nt < 4; nt++) {
        cbv[nt][0] = 0.f; cbv[nt][1] = 0.f;
        if (colbias) {
            const int col = bn + n0 + nt * 8 + tig * 2;
            const long base = (long)bz * scb + col;
            #pragma unroll
            for (int j = 0; j < 8; j++) {
                if (j < cbn) {
                    cbv[nt][0] += colbias[(long)j * M_ + base];
                    cbv[nt][1] += colbias[(long)j * M_ + base + 1];
                }
            }
        }
    }

    #pragma unroll
    for (int mt = 0; mt < 4; mt++) {
        const int rl  = m0 + mt * 16 + grp;
        const int row = bm + rl;
        float rb0 = a0, rb8 = a0;
        if (rowbias) {
            const long base = (long)bz * srb + row;
            #pragma unroll
            for (int j = 0; j < 8; j++) {
                if (j < rbn) {
                    rb0 += rowbias[(long)j * M_ + base];
                    rb8 += rowbias[(long)j * M_ + base + 8];
                }
            }
        }
        float sc0 = 1.f, sc8 = 1.f;
        if (rowscale) {
            const long base = (long)bz * srs + row;
            float t0 = 0.f, t8 = 0.f;
            #pragma unroll
            for (int j = 0; j < 8; j++) {
                if (j < rsn) {
                    t0 += rowscale[(long)j * M_ + base];
                    t8 += rowscale[(long)j * M_ + base + 8];
                }
            }
            sc0 = 1.f / t0;
            sc8 = 1.f / t8;
        }
        float sr = 0.f, sr8 = 0.f;
        #pragma unroll
        for (int nt = 0; nt < 4; nt++) {
            const int col = bn + n0 + nt * 8 + tig * 2;
            float v0 = acc[mt][nt][0] + rb0 + cbv[nt][0];
            float v1 = acc[mt][nt][1] + rb0 + cbv[nt][1];
            float v2 = acc[mt][nt][2] + rb8 + cbv[nt][0];
            float v3 = acc[mt][nt][3] + rb8 + cbv[nt][1];
            if (act == 3) {
                v0 = __expf(fmaxf(v0, 0.f)); v1 = __expf(fmaxf(v1, 0.f));
                v2 = __expf(fmaxf(v2, 0.f)); v3 = __expf(fmaxf(v3, 0.f));
            } else {
                v0 *= sc0; v1 *= sc0; v2 *= sc8; v3 *= sc8;
            }
            const bf162 pk0 = __floats2bfloat162_rn(v0, v1);
            const bf162 pk8 = __floats2bfloat162_rn(v2, v3);
            *(bf162*)(Cbp + (long)row * ldcb + col)       = pk0;
            *(bf162*)(Cbp + (long)(row + 8) * ldcb + col) = pk8;
            if (act == 3 && prow) {
                const float2 f0 = b2f(pk0), f8 = b2f(pk8);
                sr  += f0.x + f0.y;
                sr8 += f8.x + f8.y;
            }
        }
        if (act == 3 && prow) {
            #pragma unroll
            for (int msk = 1; msk <= 2; msk <<= 1) {
                sr  += __shfl_xor_sync(0xffffffffu, sr,  msk);
                sr8 += __shfl_xor_sync(0xffffffffu, sr8, msk);
            }
            if (tig == 0) {
                pst[wcol * 128 + rl]     = sr;
                pst[wcol * 128 + rl + 8] = sr8;
            }
        }
    }

    if (act == 3 && prow) {
        __syncthreads();
        if (tid < 128) {
            const float s = pst[tid] + pst[128 + tid]
                          + pst[256 + tid] + pst[384 + tid];
            prow[(long)blockIdx.x * M_ + (long)bz * L_ + bm + tid] = s;
        }
    }
}

// ---------------------------------------------------------------------------
// Merged prologue: conv_inputs (blocks 0..8191) + 4 weight transposes
// ---------------------------------------------------------------------------
__global__ __launch_bounds__(256) void prologue(
    const float* __restrict__ in, bf16* __restrict__ ib, bf16* __restrict__ cat,
    const float* __restrict__ tW, bf16* __restrict__ tWt,
    const float* __restrict__ cW, bf16* __restrict__ cWt,
    const float* __restrict__ ffW, bf16* __restrict__ ffWt,
    const float* __restrict__ frW, bf16* __restrict__ frWt)
{
    const int bid = blockIdx.x;
    if (bid < 8192) {
        const int i = bid * 256 + threadIdx.x;     // over M*U/4
        const float4 v = ((const float4*)in)[i];
        const bf162 p0 = __floats2bfloat162_rn(v.x, v.y);
        const bf162 p1 = __floats2bfloat162_rn(v.z, v.w);
        *(bf162*)(ib + (long)i * 4)     = p0;
        *(bf162*)(ib + (long)i * 4 + 2) = p1;
        const int m  = i >> 7;
        const int c4 = i & 127;
        bf16* cr = cat + (long)m * (2 * U_) + c4 * 4;
        *(bf162*)cr       = p0;
        *(bf162*)(cr + 2) = p1;
        return;
    }
    __shared__ float tile[32][33];
    const int s = bid - 8192;
    const int job = s >> 9;
    const int r   = s & 511;
    const float* src; bf16* dst; int R, Cc, r0, c0;
    if (job < 2) {
        const int layer = r >> 8, w = r & 255;
        src = (job == 0 ? tW : cW) + (long)layer * U_ * U_;
        dst = (job == 0 ? tWt : cWt) + (long)layer * U_ * U_;
        R = U_; Cc = U_; c0 = (w & 15) * 32; r0 = (w >> 4) * 32;
    } else {
        src = (job == 2 ? ffW : frW);
        dst = (job == 2 ? ffWt : frWt);
        R = 2 * U_; Cc = U_; c0 = (r & 15) * 32; r0 = (r >> 4) * 32;
    }
    const int tx = threadIdx.x & 31, ty = threadIdx.x >> 5;
    #pragma unroll
    for (int i2 = 0; i2 < 32; i2 += 8)
        tile[ty + i2][tx] = src[(long)(r0 + ty + i2) * Cc + c0 + tx];
    __syncthreads();
    #pragma unroll
    for (int i2 = 0; i2 < 32; i2 += 8)
        dst[(long)(c0 + ty + i2) * R + r0 + tx] = __float2bfloat16(tile[tx][ty + i2]);
}

// ---------------------------------------------------------------------------
// Launch
// ---------------------------------------------------------------------------
#define GEMM_SMEM (2 * NSTG * STAGE_B)   // 96 KB  (single GEMM)
#define DUAL_SMEM (3 * NSTG * STAGE_B)   // 144 KB (dual GEMM)

extern "C" void kernel_launch(void* const* d_in, const int* in_sizes, int n_in,
                              void* d_out, int out_size)
{
    (void)in_sizes; (void)n_in; (void)out_size;
    const float* inputs = (const float*)d_in[0];
    const float* tW     = (const float*)d_in[1];
    const float* tb     = (const float*)d_in[2];
    const float* cW     = (const float*)d_in[3];
    const float* cb     = (const float*)d_in[4];
    const float* aW     = (const float*)d_in[5];
    const float* ab     = (const float*)d_in[6];
    const float* frW    = (const float*)d_in[7];
    const float* frb    = (const float*)d_in[8];
    const float* ffW    = (const float*)d_in[9];
    const float* ffb    = (const float*)d_in[10];
    float* out = (float*)d_out;

    float *ps1, *ps2, *pr;
    bf16 *ib, *x0b, *x1b, *xw3, *x1t, *cat, *As, *tWt, *cWt, *ffWt, *frWt;
    cudaGetSymbolAddress((void**)&ps1,  g_ps1);
    cudaGetSymbolAddress((void**)&ps2,  g_ps2);
    cudaGetSymbolAddress((void**)&pr,   g_pr);
    cudaGetSymbolAddress((void**)&ib,   g_ib);
    cudaGetSymbolAddress((void**)&x0b,  g_x0b);
    cudaGetSymbolAddress((void**)&x1b,  g_x1b);
    cudaGetSymbolAddress((void**)&xw3,  g_xw3);
    cudaGetSymbolAddress((void**)&x1t,  g_x1t);
    cudaGetSymbolAddress((void**)&cat,  g_cat);
    cudaGetSymbolAddress((void**)&As,   g_As);
    cudaGetSymbolAddress((void**)&tWt,  g_tWt);
    cudaGetSymbolAddress((void**)&cWt,  g_cWt);
    cudaGetSymbolAddress((void**)&ffWt, g_ffWt);
    cudaGetSymbolAddress((void**)&frWt, g_frWt);

    cudaFuncSetAttribute(gemm_bf, cudaFuncAttributeMaxDynamicSharedMemorySize,
                         GEMM_SMEM);
    cudaFuncSetAttribute(gemm_dual, cudaFuncAttributeMaxDynamicSharedMemorySize,
                         DUAL_SMEM);

    // 1. merged prologue (inputs->bf16 + cat, 4 weight transposes)
    prologue<<<10240, 256>>>(inputs, ib, cat, tW, tWt, cW, cWt,
                             ffW, ffWt, frW, frWt);

    dim3 gHW(U_/128, M_/128);      // (4,128)
    // 2. highway layer 0 (dual)
    gemm_dual<<<gHW, 256, DUAL_SMEM>>>(ib, U_, tWt, cWt, U_,
                                       nullptr, x0b, inputs, nullptr, U_,
                                       tb, cb, 0, nullptr, nullptr, nullptr,
                                       nullptr, nullptr, nullptr);
    // 3. highway layer 1 (dual) + fused xw3, x1^T, s1/s2 partials
    gemm_dual<<<gHW, 256, DUAL_SMEM>>>(x0b, U_, tWt + U_*U_, cWt + U_*U_, U_,
                                       nullptr, x1b, nullptr, x0b, U_,
                                       tb + U_, cb + U_, 0,
                                       aW + 2*U_, xw3, x1t,
                                       aW, ps1, ps2);

    // 4. scores: As[b] = exp(relu( xw3 @ x1^T + Σps1 + Σps2 + ab )) + rowsum partials
    dim3 gS(L_/128, L_/128, B_);
    gemm_bf<<<gS, 256, GEMM_SMEM>>>(xw3, U_, (long)L_*U_, x1b, U_, (long)L_*U_,
                                    As, L_, (long)L_*L_, U_,
                                    ps1, L_, 4, ps2, L_, 4, ab,
                                    nullptr, 0, 0, 3, pr);

    // 5. att = (expA @ x1) * (1/Σpr)[row] -> bf16 into cat second half
    dim3 gAtt(U_/128, L_/128, B_);
    gemm_bf<<<gAtt, 256, GEMM_SMEM>>>(As, L_, (long)L_*L_, x1t, L_, (long)U_*L_,
                                      cat + U_, 2*U_, (long)L_*2*U_, L_,
                                      nullptr, 0, 0, nullptr, 0, 0, nullptr,
                                      pr, L_, 8, 0, nullptr);

    // 6. final dual: out = sig(cat@frW+frb)*inputs + sig(cat@ffW+ffb)^2
    gemm_dual<<<gHW, 256, DUAL_SMEM>>>(cat, 2*U_, ffWt, frWt, 2*U_,
                                       out, nullptr, inputs, nullptr, 2*U_,
                                       ffb, frb, 1, nullptr, nullptr, nullptr,
                                       nullptr, nullptr, nullptr);
}

// round 12
// speedup vs baseline: 1.1320x; 1.0024x over previous
#include <cuda_runtime.h>
#include <cuda_bf16.h>
#include <cstdint>

#define B_  16
#define L_  1024
#define U_  512
#define M_  (B_*L_)      // 16384

typedef __nv_bfloat16  bf16;
typedef __nv_bfloat162 bf162;

// ---------------------------------------------------------------------------
// Scratch (device globals; no allocation allowed)
// ---------------------------------------------------------------------------
__device__ float g_ps1[4*M_];           // s1 partials (per col-block)
__device__ float g_ps2[4*M_];           // s2 partials
__device__ float g_pr [8*M_];           // rowsum partials

__device__ bf16 g_ib  [M_*U_];          // inputs bf16
__device__ bf16 g_x0b [M_*U_];
__device__ bf16 g_x1b [M_*U_];
__device__ bf16 g_xw3 [M_*U_];          // x1 * w3
__device__ bf16 g_x1t [M_*U_];          // per-batch [U][L]
__device__ bf16 g_cat [(size_t)M_*2*U_];
__device__ bf16 g_As  [(size_t)B_*L_*L_];  // exp(relu(scores))
__device__ bf16 g_tWt [2*U_*U_];
__device__ bf16 g_cWt [2*U_*U_];
__device__ bf16 g_ffWt[2*U_*U_];        // [512][1024]
__device__ bf16 g_frWt[2*U_*U_];        // [512][1024]

// ---------------------------------------------------------------------------
// PTX helpers (baseline PTX; compile at compute_103)
// ---------------------------------------------------------------------------
__device__ __forceinline__ uint32_t smem_u32(const void* p) {
    uint32_t a;
    asm("{ .reg .u64 t; cvta.to.shared.u64 t, %1; cvt.u32.u64 %0, t; }"
        : "=r"(a) : "l"(p));
    return a;
}
__device__ __forceinline__ void cpasync16(uint32_t dst, const void* src) {
    asm volatile("cp.async.cg.shared.global [%0], [%1], 16;"
                 :: "r"(dst), "l"(src));
}
#define CP_COMMIT() asm volatile("cp.async.commit_group;" ::: "memory")
#define CP_WAIT(n)  asm volatile("cp.async.wait_group %0;" :: "n"(n) : "memory")

#define LDSM4(r0, r1, r2, r3, addr) \
    asm volatile("ldmatrix.sync.aligned.m8n8.x4.shared.b16 {%0,%1,%2,%3}, [%4];" \
        : "=r"(r0), "=r"(r1), "=r"(r2), "=r"(r3) : "r"(addr))

__device__ __forceinline__ void mma_bf16(float* c, const uint32_t* a,
                                         uint32_t b0, uint32_t b1) {
    asm volatile(
        "mma.sync.aligned.m16n8k16.row.col.f32.bf16.bf16.f32 "
        "{%0,%1,%2,%3}, {%4,%5,%6,%7}, {%8,%9}, {%0,%1,%2,%3};"
        : "+f"(c[0]), "+f"(c[1]), "+f"(c[2]), "+f"(c[3])
        : "r"(a[0]), "r"(a[1]), "r"(a[2]), "r"(a[3]), "r"(b0), "r"(b1));
}

__device__ __forceinline__ float sigm(float v) {
    return 1.f / (1.f + __expf(-v));
}
__device__ __forceinline__ float2 b2f(bf162 p) {
    return make_float2(__bfloat162float(p.x), __bfloat162float(p.y));
}

#define KC 64
#define RB 128                 // row bytes (KC bf16)
#define STAGE_B (128*RB)       // 16 KB
#define NSTG 3
#define TPITCH 136             // bf16 pitch for transpose staging
#define PSTAGE_OFF 36864       // byte offset of partial staging in dual smem

// ---------------------------------------------------------------------------
// DUAL bf16 GEMM: two GEMMs sharing the A operand, fused combine epilogue.
// Fragment double-buffered inner loop: LDSMs for ks+1 issue before MMAs of ks.
// ---------------------------------------------------------------------------
__global__ __launch_bounds__(256, 1) void gemm_dual(
    const bf16* __restrict__ A,  long lda,
    const bf16* __restrict__ B1, const bf16* __restrict__ B2, long ldb,
    float* __restrict__ Xout, bf16* __restrict__ Xbout,
    const float* __restrict__ e2f, const bf16* __restrict__ e2b,
    int K,
    const float* __restrict__ b1, const float* __restrict__ b2,
    int mode,
    const float* __restrict__ w3, bf16* __restrict__ xw3o,
    bf16* __restrict__ x1to,
    const float* __restrict__ w12,
    float* __restrict__ ps1, float* __restrict__ ps2)
{
    extern __shared__ char smc[];
    const uint32_t as0  = smem_u32(smc);
    const uint32_t b1s0 = as0  + NSTG * STAGE_B;
    const uint32_t b2s0 = b1s0 + NSTG * STAGE_B;

    const int tid  = threadIdx.x;
    const int wid  = tid >> 5;
    const int lane = tid & 31;
    const int li   = lane & 7;
    const int q    = lane >> 3;
    const int ql   = q & 1;
    const int qh   = q >> 1;
    const int m0   = (wid >> 2) * 64;
    const int n0   = (wid & 3)  * 32;

    const int bm = blockIdx.y * 128;
    const int bn = blockIdx.x * 128;

    const int lrow = tid >> 1;
    const int lcb  = (tid & 1) * 4;
    const int nch  = K / KC;

    float acc1[4][4][4], acc2[4][4][4];
    #pragma unroll
    for (int i = 0; i < 4; i++)
        #pragma unroll
        for (int j = 0; j < 4; j++)
            #pragma unroll
            for (int k = 0; k < 4; k++) { acc1[i][j][k] = 0.f; acc2[i][j][k] = 0.f; }

    auto load_chunk = [&](int c) {
        const int st = c % NSTG;
        const bf16* ap  = A  + (long)(bm + lrow) * lda + c * KC;
        const bf16* b1p = B1 + (long)(bn + lrow) * ldb + c * KC;
        const bf16* b2p = B2 + (long)(bn + lrow) * ldb + c * KC;
        const uint32_t ad  = as0  + st * STAGE_B + lrow * RB;
        const uint32_t bd1 = b1s0 + st * STAGE_B + lrow * RB;
        const uint32_t bd2 = b2s0 + st * STAGE_B + lrow * RB;
        const int sw = lrow & 7;
        #pragma unroll
        for (int j = 0; j < 4; j++) {
            const int ch  = lcb + j;
            const int cho = (ch ^ sw) * 16;
            cpasync16(ad  + cho, ap  + ch * 8);
            cpasync16(bd1 + cho, b1p + ch * 8);
            cpasync16(bd2 + cho, b2p + ch * 8);
        }
        CP_COMMIT();
    };

    load_chunk(0);
    if (nch > 1) load_chunk(1);

    int rA[4], nB[2];
    #pragma unroll
    for (int mt = 0; mt < 4; mt++) rA[mt] = m0 + mt * 16 + li + ql * 8;
    #pragma unroll
    for (int p = 0; p < 2; p++)    nB[p] = n0 + p * 16 + qh * 8 + li;

    for (int c = 0; c < nch; c++) {
        const int st = c % NSTG;
        if (c + 1 < nch) CP_WAIT(1); else CP_WAIT(0);
        __syncthreads();
        if (c + 2 < nch) load_chunk(c + 2);

        const uint32_t asb  = as0  + st * STAGE_B;
        const uint32_t b1sb = b1s0 + st * STAGE_B;
        const uint32_t b2sb = b2s0 + st * STAGE_B;

        uint32_t afr[2][4][4], f1r[2][2][4], f2r[2][2][4];
        auto ld_frags = [&](int ks, int bu) {
            #pragma unroll
            for (int mt = 0; mt < 4; mt++) {
                const int r = rA[mt];
                const int ch = (ks * 2 + qh) ^ (r & 7);
                LDSM4(afr[bu][mt][0], afr[bu][mt][1], afr[bu][mt][2], afr[bu][mt][3],
                      asb + r * RB + ch * 16);
            }
            #pragma unroll
            for (int p = 0; p < 2; p++) {
                const int n = nB[p];
                const int ch = ((ks * 2 + ql) ^ (n & 7)) * 16;
                LDSM4(f1r[bu][p][0], f1r[bu][p][1], f1r[bu][p][2], f1r[bu][p][3],
                      b1sb + n * RB + ch);
                LDSM4(f2r[bu][p][0], f2r[bu][p][1], f2r[bu][p][2], f2r[bu][p][3],
                      b2sb + n * RB + ch);
            }
        };

        ld_frags(0, 0);
        #pragma unroll
        for (int ks = 0; ks < 4; ks++) {
            const int cur = ks & 1;
            if (ks < 3) ld_frags(ks + 1, cur ^ 1);
            #pragma unroll
            for (int nt = 0; nt < 4; nt++) {
                const int p = nt >> 1, h = (nt & 1) * 2;
                #pragma unroll
                for (int mt = 0; mt < 4; mt++) {
                    mma_bf16(acc1[mt][nt], afr[cur][mt],
                             f1r[cur][p][h], f1r[cur][p][h + 1]);
                    mma_bf16(acc2[mt][nt], afr[cur][mt],
                             f2r[cur][p][h], f2r[cur][p][h + 1]);
                }
            }
        }
    }

    // ---- fused epilogue ----
    const int grp = lane >> 2;
    const int tig = lane & 3;
    bf16*  stage = (bf16*)smc;                     // transpose staging
    float* pst   = (float*)(smc + PSTAGE_OFF);     // partial staging [4][128][2]
    const int wcol = wid & 3;

    float2 w1v[4], w2v[4];
    if (mode == 0 && ps1) {
        #pragma unroll
        for (int nt = 0; nt < 4; nt++) {
            const int col = bn + n0 + nt * 8 + tig * 2;
            w1v[nt] = *(const float2*)(w12 + col);
            w2v[nt] = *(const float2*)(w12 + U_ + col);
        }
    }

    __syncthreads();   // ensure all mainloop smem reads done before staging reuse

    #pragma unroll
    for (int mt = 0; mt < 4; mt++) {
        const int rl  = m0 + mt * 16 + grp;     // local row
        const int row = bm + rl;
        float s1r = 0.f, s2r = 0.f, s1r8 = 0.f, s2r8 = 0.f;
        #pragma unroll
        for (int nt = 0; nt < 4; nt++) {
            const int cl  = n0 + nt * 8 + tig * 2;   // local col
            const int col = bn + cl;
            const float p10 = b1[col], p11 = b1[col + 1];
            const float p20 = b2[col], p21 = b2[col + 1];
            const long i0 = (long)row * U_ + col;
            const long i8 = (long)(row + 8) * U_ + col;
            float2 x0v, x8v;
            if (e2f) {
                x0v = *(const float2*)(e2f + i0);
                x8v = *(const float2*)(e2f + i8);
            } else {
                x0v = b2f(*(const bf162*)(e2b + i0));
                x8v = b2f(*(const bf162*)(e2b + i8));
            }
            float u0 = acc1[mt][nt][0] + p10, u1 = acc1[mt][nt][1] + p11;
            float u2 = acc1[mt][nt][2] + p10, u3 = acc1[mt][nt][3] + p11;
            float w0 = acc2[mt][nt][0] + p20, w1 = acc2[mt][nt][1] + p21;
            float w2 = acc2[mt][nt][2] + p20, w3v = acc2[mt][nt][3] + p21;
            if (mode == 0) {
                u0 = fmaxf(u0, 0.f); u1 = fmaxf(u1, 0.f);
                u2 = fmaxf(u2, 0.f); u3 = fmaxf(u3, 0.f);
                w0 = sigm(w0); w1 = sigm(w1); w2 = sigm(w2); w3v = sigm(w3v);
                const float o0 = u0 * w0 + x0v.x * (1.f - w0);
                const float o1 = u1 * w1 + x0v.y * (1.f - w1);
                const float o2 = u2 * w2 + x8v.x * (1.f - w2);
                const float o3 = u3 * w3v + x8v.y * (1.f - w3v);
                const bf162 pk0 = __floats2bfloat162_rn(o0, o1);
                const bf162 pk8 = __floats2bfloat162_rn(o2, o3);
                *(bf162*)(Xbout + i0) = pk0;
                *(bf162*)(Xbout + i8) = pk8;
                if (xw3o) {
                    const float2 wv = *(const float2*)(w3 + col);
                    *(bf162*)(xw3o + i0) = __floats2bfloat162_rn(o0 * wv.x, o1 * wv.y);
                    *(bf162*)(xw3o + i8) = __floats2bfloat162_rn(o2 * wv.x, o3 * wv.y);
                }
                if (x1to) {
                    stage[cl * TPITCH + rl]           = pk0.x;
                    stage[(cl + 1) * TPITCH + rl]     = pk0.y;
                    stage[cl * TPITCH + rl + 8]       = pk8.x;
                    stage[(cl + 1) * TPITCH + rl + 8] = pk8.y;
                }
                if (ps1) {
                    const float2 f0 = b2f(pk0), f8 = b2f(pk8);
                    s1r  += f0.x * w1v[nt].x + f0.y * w1v[nt].y;
                    s2r  += f0.x * w2v[nt].x + f0.y * w2v[nt].y;
                    s1r8 += f8.x * w1v[nt].x + f8.y * w1v[nt].y;
                    s2r8 += f8.x * w2v[nt].x + f8.y * w2v[nt].y;
                }
            } else {
                u0 = sigm(u0); u1 = sigm(u1); u2 = sigm(u2); u3 = sigm(u3);
                w0 = sigm(w0); w1 = sigm(w1); w2 = sigm(w2); w3v = sigm(w3v);
                const float o0 = w0 * x0v.x + u0 * u0;
                const float o1 = w1 * x0v.y + u1 * u1;
                const float o2 = w2 * x8v.x + u2 * u2;
                const float o3 = w3v * x8v.y + u3 * u3;
                *(float2*)(Xout + i0) = make_float2(o0, o1);
                *(float2*)(Xout + i8) = make_float2(o2, o3);
            }
        }
        if (mode == 0 && ps1) {
            #pragma unroll
            for (int msk = 1; msk <= 2; msk <<= 1) {
                s1r  += __shfl_xor_sync(0xffffffffu, s1r,  msk);
                s2r  += __shfl_xor_sync(0xffffffffu, s2r,  msk);
                s1r8 += __shfl_xor_sync(0xffffffffu, s1r8, msk);
                s2r8 += __shfl_xor_sync(0xffffffffu, s2r8, msk);
            }
            if (tig == 0) {
                pst[((wcol * 128 + rl)     << 1)]     = s1r;
                pst[((wcol * 128 + rl)     << 1) + 1] = s2r;
                pst[((wcol * 128 + rl + 8) << 1)]     = s1r8;
                pst[((wcol * 128 + rl + 8) << 1) + 1] = s2r8;
            }
        }
    }

    // ---- transposed write-out + partial reduce ----
    if (mode == 0 && (x1to || ps1)) {
        __syncthreads();
        if (x1to) {
            const int b0 = bm >> 10;         // batch (L_ = 1024)
            const int l0 = bm & 1023;
            const int cw = wid * 16;         // 16 cols per warp
            #pragma unroll
            for (int cc = 0; cc < 16; cc++) {
                const int c = cw + cc;
                const uint2 v = *(const uint2*)(stage + c * TPITCH + lane * 4);
                *(uint2*)(x1to + ((long)b0 * U_ + bn + c) * L_ + l0 + lane * 4) = v;
            }
        }
        if (ps1) {
            const int rl = tid >> 1, v = tid & 1;
            const float s = pst[((0 * 128 + rl) << 1) + v]
                          + pst[((1 * 128 + rl) << 1) + v]
                          + pst[((2 * 128 + rl) << 1) + v]
                          + pst[((3 * 128 + rl) << 1) + v];
            (v ? ps2 : ps1)[blockIdx.x * M_ + bm + rl] = s;
        }
    }
}

// ---------------------------------------------------------------------------
// Single bf16 GEMM (scores / att) with fragment double-buffering.
// ---------------------------------------------------------------------------
__global__ __launch_bounds__(256) void gemm_bf(
    const bf16* __restrict__ A,  long lda, long sA,
    const bf16* __restrict__ Bt, long ldb, long sB,
    bf16* __restrict__ Cb, long ldcb, long sCb,
    int K,
    const float* __restrict__ rowbias, long srb, int rbn,
    const float* __restrict__ colbias, long scb, int cbn,
    const float* __restrict__ addc,
    const float* __restrict__ rowscale, long srs, int rsn,
    int act,
    float* __restrict__ prow)
{
    extern __shared__ char smc[];
    const uint32_t as0 = smem_u32(smc);
    const uint32_t bs0 = as0 + NSTG * STAGE_B;

    const int tid  = threadIdx.x;
    const int wid  = tid >> 5;
    const int lane = tid & 31;
    const int li   = lane & 7;
    const int q    = lane >> 3;
    const int ql   = q & 1;
    const int qh   = q >> 1;
    const int m0   = (wid >> 2) * 64;
    const int n0   = (wid & 3)  * 32;

    const int bz = blockIdx.z;
    const int bm = blockIdx.y * 128;
    const int bn = blockIdx.x * 128;

    const bf16* Ag = A  + (long)bz * sA;
    const bf16* Bg = Bt + (long)bz * sB;

    const int lrow = tid >> 1;
    const int lcb  = (tid & 1) * 4;
    const int nch  = K / KC;

    float acc[4][4][4];
    #pragma unroll
    for (int i = 0; i < 4; i++)
        #pragma unroll
        for (int j = 0; j < 4; j++)
            #pragma unroll
            for (int k = 0; k < 4; k++) acc[i][j][k] = 0.f;

    auto load_chunk = [&](int c) {
        const int st = c % NSTG;
        const bf16* ap = Ag + (long)(bm + lrow) * lda + c * KC;
        const bf16* bp = Bg + (long)(bn + lrow) * ldb + c * KC;
        const uint32_t ad = as0 + st * STAGE_B + lrow * RB;
        const uint32_t bd = bs0 + st * STAGE_B + lrow * RB;
        const int sw = lrow & 7;
        #pragma unroll
        for (int j = 0; j < 4; j++) {
            const int ch = lcb + j;
            const int cho = (ch ^ sw) * 16;
            cpasync16(ad + cho, ap + ch * 8);
            cpasync16(bd + cho, bp + ch * 8);
        }
        CP_COMMIT();
    };

    load_chunk(0);
    if (nch > 1) load_chunk(1);

    int rA[4], nB[2];
    #pragma unroll
    for (int mt = 0; mt < 4; mt++) rA[mt] = m0 + mt * 16 + li + ql * 8;
    #pragma unroll
    for (int p = 0; p < 2; p++)    nB[p] = n0 + p * 16 + qh * 8 + li;

    for (int c = 0; c < nch; c++) {
        const int st = c % NSTG;
        if (c + 1 < nch) CP_WAIT(1); else CP_WAIT(0);
        __syncthreads();
        if (c + 2 < nch) load_chunk(c + 2);

        const uint32_t asb = as0 + st * STAGE_B;
        const uint32_t bsb = bs0 + st * STAGE_B;

        uint32_t afr[2][4][4], bfr[2][2][4];
        auto ld_frags = [&](int ks, int bu) {
            #pragma unroll
            for (int mt = 0; mt < 4; mt++) {
                const int r = rA[mt];
                const int ch = (ks * 2 + qh) ^ (r & 7);
                LDSM4(afr[bu][mt][0], afr[bu][mt][1], afr[bu][mt][2], afr[bu][mt][3],
                      asb + r * RB + ch * 16);
            }
            #pragma unroll
            for (int p = 0; p < 2; p++) {
                const int n = nB[p];
                const int ch = (ks * 2 + ql) ^ (n & 7);
                LDSM4(bfr[bu][p][0], bfr[bu][p][1], bfr[bu][p][2], bfr[bu][p][3],
                      bsb + n * RB + ch * 16);
            }
        };

        ld_frags(0, 0);
        #pragma unroll
        for (int ks = 0; ks < 4; ks++) {
            const int cur = ks & 1;
            if (ks < 3) ld_frags(ks + 1, cur ^ 1);
            #pragma unroll
            for (int nt = 0; nt < 4; nt++) {
                const uint32_t b0 = bfr[cur][nt >> 1][(nt & 1) * 2];
                const uint32_t b1 = bfr[cur][nt >> 1][(nt & 1) * 2 + 1];
                #pragma unroll
                for (int mt = 0; mt < 4; mt++)
                    mma_bf16(acc[mt][nt], afr[cur][mt], b0, b1);
            }
        }
    }

    const int grp = lane >> 2;
    const int tig = lane & 3;
    const int wcol = wid & 3;
    bf16* Cbp = Cb + (long)bz * sCb;
    float* pst = (float*)smc;                // [4][128] partial staging
    const float a0 = addc ? addc[0] : 0.f;

    // colbias precompute (independent of mt); inline partial-sum if cbn>1
    float cbv[4][2];
    #pragma unroll
    for (int nt = 0; nt < 4; nt++) {
        cbv[nt][0] = 0.f; cbv[nt][1] = 0.f;
        if (colbias) {
            const int col = bn + n0 + nt * 8 + tig * 2;
            const long base = (long)bz * scb + col;
            #pragma unroll
            for (int j = 0; j < 8; j++) {
                if (j < cbn) {
                    cbv[nt][0] += colbias[(long)j * M_ + base];
                    cbv[nt][1] += colbias[(long)j * M_ + base + 1];
                }
            }
        }
    }

    __syncthreads();   // mainloop smem reads done before pst reuse

    #pragma unroll
    for (int mt = 0; mt < 4; mt++) {
        const int rl  = m0 + mt * 16 + grp;
        const int row = bm + rl;
        float rb0 = a0, rb8 = a0;
        if (rowbias) {
            const long base = (long)bz * srb + row;
            #pragma unroll
            for (int j = 0; j < 8; j++) {
                if (j < rbn) {
                    rb0 += rowbias[(long)j * M_ + base];
                    rb8 += rowbias[(long)j * M_ + base + 8];
                }
            }
        }
        float sc0 = 1.f, sc8 = 1.f;
        if (rowscale) {
            const long base = (long)bz * srs + row;
            float t0 = 0.f, t8 = 0.f;
            #pragma unroll
            for (int j = 0; j < 8; j++) {
                if (j < rsn) {
                    t0 += rowscale[(long)j * M_ + base];
                    t8 += rowscale[(long)j * M_ + base + 8];
                }
            }
            sc0 = 1.f / t0;
            sc8 = 1.f / t8;
        }
        float sr = 0.f, sr8 = 0.f;
        #pragma unroll
        for (int nt = 0; nt < 4; nt++) {
            const int col = bn + n0 + nt * 8 + tig * 2;
            float v0 = acc[mt][nt][0] + rb0 + cbv[nt][0];
            float v1 = acc[mt][nt][1] + rb0 + cbv[nt][1];
            float v2 = acc[mt][nt][2] + rb8 + cbv[nt][0];
            float v3 = acc[mt][nt][3] + rb8 + cbv[nt][1];
            if (act == 3) {
                v0 = __expf(fmaxf(v0, 0.f)); v1 = __expf(fmaxf(v1, 0.f));
                v2 = __expf(fmaxf(v2, 0.f)); v3 = __expf(fmaxf(v3, 0.f));
            } else {
                v0 *= sc0; v1 *= sc0; v2 *= sc8; v3 *= sc8;
            }
            const bf162 pk0 = __floats2bfloat162_rn(v0, v1);
            const bf162 pk8 = __floats2bfloat162_rn(v2, v3);
            *(bf162*)(Cbp + (long)row * ldcb + col)       = pk0;
            *(bf162*)(Cbp + (long)(row + 8) * ldcb + col) = pk8;
            if (act == 3 && prow) {
                const float2 f0 = b2f(pk0), f8 = b2f(pk8);
                sr  += f0.x + f0.y;
                sr8 += f8.x + f8.y;
            }
        }
        if (act == 3 && prow) {
            #pragma unroll
            for (int msk = 1; msk <= 2; msk <<= 1) {
                sr  += __shfl_xor_sync(0xffffffffu, sr,  msk);
                sr8 += __shfl_xor_sync(0xffffffffu, sr8, msk);
            }
            if (tig == 0) {
                pst[wcol * 128 + rl]     = sr;
                pst[wcol * 128 + rl + 8] = sr8;
            }
        }
    }

    if (act == 3 && prow) {
        __syncthreads();
        if (tid < 128) {
            const float s = pst[tid] + pst[128 + tid]
                          + pst[256 + tid] + pst[384 + tid];
            prow[(long)blockIdx.x * M_ + (long)bz * L_ + bm + tid] = s;
        }
    }
}

// ---------------------------------------------------------------------------
// Merged prologue: conv_inputs (blocks 0..8191) + 4 weight transposes
// ---------------------------------------------------------------------------
__global__ __launch_bounds__(256) void prologue(
    const float* __restrict__ in, bf16* __restrict__ ib, bf16* __restrict__ cat,
    const float* __restrict__ tW, bf16* __restrict__ tWt,
    const float* __restrict__ cW, bf16* __restrict__ cWt,
    const float* __restrict__ ffW, bf16* __restrict__ ffWt,
    const float* __restrict__ frW, bf16* __restrict__ frWt)
{
    const int bid = blockIdx.x;
    if (bid < 8192) {
        const int i = bid * 256 + threadIdx.x;     // over M*U/4
        const float4 v = ((const float4*)in)[i];
        const bf162 p0 = __floats2bfloat162_rn(v.x, v.y);
        const bf162 p1 = __floats2bfloat162_rn(v.z, v.w);
        *(bf162*)(ib + (long)i * 4)     = p0;
        *(bf162*)(ib + (long)i * 4 + 2) = p1;
        const int m  = i >> 7;
        const int c4 = i & 127;
        bf16* cr = cat + (long)m * (2 * U_) + c4 * 4;
        *(bf162*)cr       = p0;
        *(bf162*)(cr + 2) = p1;
        return;
    }
    __shared__ float tile[32][33];
    const int s = bid - 8192;
    const int job = s >> 9;
    const int r   = s & 511;
    const float* src; bf16* dst; int R, Cc, r0, c0;
    if (job < 2) {
        const int layer = r >> 8, w = r & 255;
        src = (job == 0 ? tW : cW) + (long)layer * U_ * U_;
        dst = (job == 0 ? tWt : cWt) + (long)layer * U_ * U_;
        R = U_; Cc = U_; c0 = (w & 15) * 32; r0 = (w >> 4) * 32;
    } else {
        src = (job == 2 ? ffW : frW);
        dst = (job == 2 ? ffWt : frWt);
        R = 2 * U_; Cc = U_; c0 = (r & 15) * 32; r0 = (r >> 4) * 32;
    }
    const int tx = threadIdx.x & 31, ty = threadIdx.x >> 5;
    #pragma unroll
    for (int i2 = 0; i2 < 32; i2 += 8)
        tile[ty + i2][tx] = src[(long)(r0 + ty + i2) * Cc + c0 + tx];
    __syncthreads();
    #pragma unroll
    for (int i2 = 0; i2 < 32; i2 += 8)
        dst[(long)(c0 + ty + i2) * R + r0 + tx] = __float2bfloat16(tile[tx][ty + i2]);
}

// ---------------------------------------------------------------------------
// Launch
// ---------------------------------------------------------------------------
#define GEMM_SMEM (2 * NSTG * STAGE_B)   // 96 KB  (single GEMM)
#define DUAL_SMEM (3 * NSTG * STAGE_B)   // 144 KB (dual GEMM)

extern "C" void kernel_launch(void* const* d_in, const int* in_sizes, int n_in,
                              void* d_out, int out_size)
{
    (void)in_sizes; (void)n_in; (void)out_size;
    const float* inputs = (const float*)d_in[0];
    const float* tW     = (const float*)d_in[1];
    const float* tb     = (const float*)d_in[2];
    const float* cW     = (const float*)d_in[3];
    const float* cb     = (const float*)d_in[4];
    const float* aW     = (const float*)d_in[5];
    const float* ab     = (const float*)d_in[6];
    const float* frW    = (const float*)d_in[7];
    const float* frb    = (const float*)d_in[8];
    const float* ffW    = (const float*)d_in[9];
    const float* ffb    = (const float*)d_in[10];
    float* out = (float*)d_out;

    float *ps1, *ps2, *pr;
    bf16 *ib, *x0b, *x1b, *xw3, *x1t, *cat, *As, *tWt, *cWt, *ffWt, *frWt;
    cudaGetSymbolAddress((void**)&ps1,  g_ps1);
    cudaGetSymbolAddress((void**)&ps2,  g_ps2);
    cudaGetSymbolAddress((void**)&pr,   g_pr);
    cudaGetSymbolAddress((void**)&ib,   g_ib);
    cudaGetSymbolAddress((void**)&x0b,  g_x0b);
    cudaGetSymbolAddress((void**)&x1b,  g_x1b);
    cudaGetSymbolAddress((void**)&xw3,  g_xw3);
    cudaGetSymbolAddress((void**)&x1t,  g_x1t);
    cudaGetSymbolAddress((void**)&cat,  g_cat);
    cudaGetSymbolAddress((void**)&As,   g_As);
    cudaGetSymbolAddress((void**)&tWt,  g_tWt);
    cudaGetSymbolAddress((void**)&cWt,  g_cWt);
    cudaGetSymbolAddress((void**)&ffWt, g_ffWt);
    cudaGetSymbolAddress((void**)&frWt, g_frWt);

    cudaFuncSetAttribute(gemm_bf, cudaFuncAttributeMaxDynamicSharedMemorySize,
                         GEMM_SMEM);
    cudaFuncSetAttribute(gemm_dual, cudaFuncAttributeMaxDynamicSharedMemorySize,
                         DUAL_SMEM);

    // 1. merged prologue (inputs->bf16 + cat, 4 weight transposes)
    prologue<<<10240, 256>>>(inputs, ib, cat, tW, tWt, cW, cWt,
                             ffW, ffWt, frW, frWt);

    dim3 gHW(U_/128, M_/128);      // (4,128)
    // 2. highway layer 0 (dual)
    gemm_dual<<<gHW, 256, DUAL_SMEM>>>(ib, U_, tWt, cWt, U_,
                                       nullptr, x0b, inputs, nullptr, U_,
                                       tb, cb, 0, nullptr, nullptr, nullptr,
                                       nullptr, nullptr, nullptr);
    // 3. highway layer 1 (dual) + fused xw3, x1^T, s1/s2 partials
    gemm_dual<<<gHW, 256, DUAL_SMEM>>>(x0b, U_, tWt + U_*U_, cWt + U_*U_, U_,
                                       nullptr, x1b, nullptr, x0b, U_,
                                       tb + U_, cb + U_, 0,
                                       aW + 2*U_, xw3, x1t,
                                       aW, ps1, ps2);

    // 4. scores: As[b] = exp(relu( xw3 @ x1^T + Σps1 + Σps2 + ab )) + rowsum partials
    dim3 gS(L_/128, L_/128, B_);
    gemm_bf<<<gS, 256, GEMM_SMEM>>>(xw3, U_, (long)L_*U_, x1b, U_, (long)L_*U_,
                                    As, L_, (long)L_*L_, U_,
                                    ps1, L_, 4, ps2, L_, 4, ab,
                                    nullptr, 0, 0, 3, pr);

    // 5. att = (expA @ x1) * (1/Σpr)[row] -> bf16 into cat second half
    dim3 gAtt(U_/128, L_/128, B_);
    gemm_bf<<<gAtt, 256, GEMM_SMEM>>>(As, L_, (long)L_*L_, x1t, L_, (long)U_*L_,
                                      cat + U_, 2*U_, (long)L_*2*U_, L_,
                                      nullptr, 0, 0, nullptr, 0, 0, nullptr,
                                      pr, L_, 8, 0, nullptr);

    // 6. final dual: out = sig(cat@frW+frb)*inputs + sig(cat@ffW+ffb)^2
    gemm_dual<<<gHW, 256, DUAL_SMEM>>>(cat, 2*U_, ffWt, frWt, 2*U_,
                                       out, nullptr, inputs, nullptr, 2*U_,
                                       ffb, frb, 1, nullptr, nullptr, nullptr,
                                       nullptr, nullptr, nullptr);
}

// round 13
// speedup vs baseline: 1.1351x; 1.0027x over previous
#include <cuda_runtime.h>
#include <cuda_bf16.h>
#include <cstdint>

#define B_  16
#define L_  1024
#define U_  512
#define M_  (B_*L_)      // 16384

typedef __nv_bfloat16  bf16;
typedef __nv_bfloat162 bf162;

// ---------------------------------------------------------------------------
// Scratch (device globals; no allocation allowed)
// ---------------------------------------------------------------------------
__device__ float g_ps1[4*M_];           // s1 partials (per col-block)
__device__ float g_ps2[4*M_];           // s2 partials
__device__ float g_pr [8*M_];           // rowsum partials

__device__ bf16 g_ib  [M_*U_];          // inputs bf16
__device__ bf16 g_x0b [M_*U_];
__device__ bf16 g_x1b [M_*U_];
__device__ bf16 g_xw3 [M_*U_];          // x1 * w3
__device__ bf16 g_x1t [M_*U_];          // per-batch [U][L]
__device__ bf16 g_att [M_*U_];          // attention output
__device__ bf16 g_As  [(size_t)B_*L_*L_];  // exp(relu(scores))
__device__ bf16 g_tWt [2*U_*U_];
__device__ bf16 g_cWt [2*U_*U_];
__device__ bf16 g_ffWt[2*U_*U_];        // [512][1024]
__device__ bf16 g_frWt[2*U_*U_];        // [512][1024]

// ---------------------------------------------------------------------------
// PTX helpers (baseline PTX; compile at compute_103)
// ---------------------------------------------------------------------------
__device__ __forceinline__ uint32_t smem_u32(const void* p) {
    uint32_t a;
    asm("{ .reg .u64 t; cvta.to.shared.u64 t, %1; cvt.u32.u64 %0, t; }"
        : "=r"(a) : "l"(p));
    return a;
}
__device__ __forceinline__ void cpasync16(uint32_t dst, const void* src) {
    asm volatile("cp.async.cg.shared.global [%0], [%1], 16;"
                 :: "r"(dst), "l"(src));
}
#define CP_COMMIT() asm volatile("cp.async.commit_group;" ::: "memory")
#define CP_WAIT(n)  asm volatile("cp.async.wait_group %0;" :: "n"(n) : "memory")

#define LDSM4(r0, r1, r2, r3, addr) \
    asm volatile("ldmatrix.sync.aligned.m8n8.x4.shared.b16 {%0,%1,%2,%3}, [%4];" \
        : "=r"(r0), "=r"(r1), "=r"(r2), "=r"(r3) : "r"(addr))

__device__ __forceinline__ void mma_bf16(float* c, const uint32_t* a,
                                         uint32_t b0, uint32_t b1) {
    asm volatile(
        "mma.sync.aligned.m16n8k16.row.col.f32.bf16.bf16.f32 "
        "{%0,%1,%2,%3}, {%4,%5,%6,%7}, {%8,%9}, {%0,%1,%2,%3};"
        : "+f"(c[0]), "+f"(c[1]), "+f"(c[2]), "+f"(c[3])
        : "r"(a[0]), "r"(a[1]), "r"(a[2]), "r"(a[3]), "r"(b0), "r"(b1));
}

__device__ __forceinline__ float sigm(float v) {
    return 1.f / (1.f + __expf(-v));
}
__device__ __forceinline__ float2 b2f(bf162 p) {
    return make_float2(__bfloat162float(p.x), __bfloat162float(p.y));
}

#define KC 64
#define RB 128                 // row bytes (KC bf16)
#define STAGE_B (128*RB)       // 16 KB
#define NSTG 3
#define TPITCH 136             // bf16 pitch for transpose staging
#define PSTAGE_OFF 36864       // byte offset of partial staging in dual smem

// ---------------------------------------------------------------------------
// DUAL bf16 GEMM: two GEMMs sharing the A operand, fused combine epilogue.
// A operand split: chunks [0, csplit) stream from A, [csplit, nch) from A2
// (both row-major [M, U_]) — implements the implicit concat without a buffer.
// mode 0 (highway): t=relu(acc1); c=sig(acc2); o = t*c + e*(1-c) -> Xbout bf16
//     extras: xw3o = o*w3[n]; x1to = per-batch transposed o;
//     ps1/ps2 = per-CTA partial row-dots of rounded o with w12 / w12+U.
// mode 1 (final):   z=sig(acc1);  r=sig(acc2); o = r*e2f + z*z -> Xout fp32
// ---------------------------------------------------------------------------
__global__ __launch_bounds__(256, 1) void gemm_dual(
    const bf16* __restrict__ A, const bf16* __restrict__ A2, int csplit,
    const bf16* __restrict__ B1, const bf16* __restrict__ B2, long ldb,
    float* __restrict__ Xout, bf16* __restrict__ Xbout,
    const float* __restrict__ e2f, const bf16* __restrict__ e2b,
    int K,
    const float* __restrict__ b1, const float* __restrict__ b2,
    int mode,
    const float* __restrict__ w3, bf16* __restrict__ xw3o,
    bf16* __restrict__ x1to,
    const float* __restrict__ w12,
    float* __restrict__ ps1, float* __restrict__ ps2)
{
    extern __shared__ char smc[];
    const uint32_t as0  = smem_u32(smc);
    const uint32_t b1s0 = as0  + NSTG * STAGE_B;
    const uint32_t b2s0 = b1s0 + NSTG * STAGE_B;

    const int tid  = threadIdx.x;
    const int wid  = tid >> 5;
    const int lane = tid & 31;
    const int li   = lane & 7;
    const int q    = lane >> 3;
    const int ql   = q & 1;
    const int qh   = q >> 1;
    const int m0   = (wid >> 2) * 64;
    const int n0   = (wid & 3)  * 32;

    const int bm = blockIdx.y * 128;
    const int bn = blockIdx.x * 128;

    const int lrow = tid >> 1;
    const int lcb  = (tid & 1) * 4;
    const int nch  = K / KC;

    float acc1[4][4][4], acc2[4][4][4];
    #pragma unroll
    for (int i = 0; i < 4; i++)
        #pragma unroll
        for (int j = 0; j < 4; j++)
            #pragma unroll
            for (int k = 0; k < 4; k++) { acc1[i][j][k] = 0.f; acc2[i][j][k] = 0.f; }

    auto load_chunk = [&](int c) {
        const int st = c % NSTG;
        const bf16* ap = (c < csplit)
            ? A  + (long)(bm + lrow) * U_ + c * KC
            : A2 + (long)(bm + lrow) * U_ + (c - csplit) * KC;
        const bf16* b1p = B1 + (long)(bn + lrow) * ldb + c * KC;
        const bf16* b2p = B2 + (long)(bn + lrow) * ldb + c * KC;
        const uint32_t ad  = as0  + st * STAGE_B + lrow * RB;
        const uint32_t bd1 = b1s0 + st * STAGE_B + lrow * RB;
        const uint32_t bd2 = b2s0 + st * STAGE_B + lrow * RB;
        const int sw = lrow & 7;
        #pragma unroll
        for (int j = 0; j < 4; j++) {
            const int ch  = lcb + j;
            const int cho = (ch ^ sw) * 16;
            cpasync16(ad  + cho, ap  + ch * 8);
            cpasync16(bd1 + cho, b1p + ch * 8);
            cpasync16(bd2 + cho, b2p + ch * 8);
        }
        CP_COMMIT();
    };

    load_chunk(0);
    if (nch > 1) load_chunk(1);

    int rA[4], nB[2];
    #pragma unroll
    for (int mt = 0; mt < 4; mt++) rA[mt] = m0 + mt * 16 + li + ql * 8;
    #pragma unroll
    for (int p = 0; p < 2; p++)    nB[p] = n0 + p * 16 + qh * 8 + li;

    for (int c = 0; c < nch; c++) {
        const int st = c % NSTG;
        if (c + 1 < nch) CP_WAIT(1); else CP_WAIT(0);
        __syncthreads();
        if (c + 2 < nch) load_chunk(c + 2);

        const uint32_t asb  = as0  + st * STAGE_B;
        const uint32_t b1sb = b1s0 + st * STAGE_B;
        const uint32_t b2sb = b2s0 + st * STAGE_B;

        uint32_t afr[2][4][4], f1r[2][2][4], f2r[2][2][4];
        auto ld_frags = [&](int ks, int bu) {
            #pragma unroll
            for (int mt = 0; mt < 4; mt++) {
                const int r = rA[mt];
                const int ch = (ks * 2 + qh) ^ (r & 7);
                LDSM4(afr[bu][mt][0], afr[bu][mt][1], afr[bu][mt][2], afr[bu][mt][3],
                      asb + r * RB + ch * 16);
            }
            #pragma unroll
            for (int p = 0; p < 2; p++) {
                const int n = nB[p];
                const int ch = ((ks * 2 + ql) ^ (n & 7)) * 16;
                LDSM4(f1r[bu][p][0], f1r[bu][p][1], f1r[bu][p][2], f1r[bu][p][3],
                      b1sb + n * RB + ch);
                LDSM4(f2r[bu][p][0], f2r[bu][p][1], f2r[bu][p][2], f2r[bu][p][3],
                      b2sb + n * RB + ch);
            }
        };

        ld_frags(0, 0);
        #pragma unroll
        for (int ks = 0; ks < 4; ks++) {
            const int cur = ks & 1;
            if (ks < 3) ld_frags(ks + 1, cur ^ 1);
            #pragma unroll
            for (int nt = 0; nt < 4; nt++) {
                const int p = nt >> 1, h = (nt & 1) * 2;
                #pragma unroll
                for (int mt = 0; mt < 4; mt++) {
                    mma_bf16(acc1[mt][nt], afr[cur][mt],
                             f1r[cur][p][h], f1r[cur][p][h + 1]);
                    mma_bf16(acc2[mt][nt], afr[cur][mt],
                             f2r[cur][p][h], f2r[cur][p][h + 1]);
                }
            }
        }
    }

    // ---- fused epilogue ----
    const int grp = lane >> 2;
    const int tig = lane & 3;
    bf16*  stage = (bf16*)smc;                     // transpose staging
    float* pst   = (float*)(smc + PSTAGE_OFF);     // partial staging [4][128][2]
    const int wcol = wid & 3;

    float2 w1v[4], w2v[4];
    if (mode == 0 && ps1) {
        #pragma unroll
        for (int nt = 0; nt < 4; nt++) {
            const int col = bn + n0 + nt * 8 + tig * 2;
            w1v[nt] = *(const float2*)(w12 + col);
            w2v[nt] = *(const float2*)(w12 + U_ + col);
        }
    }

    __syncthreads();   // mainloop smem reads done before staging reuse

    #pragma unroll
    for (int mt = 0; mt < 4; mt++) {
        const int rl  = m0 + mt * 16 + grp;     // local row
        const int row = bm + rl;
        float s1r = 0.f, s2r = 0.f, s1r8 = 0.f, s2r8 = 0.f;
        #pragma unroll
        for (int nt = 0; nt < 4; nt++) {
            const int cl  = n0 + nt * 8 + tig * 2;   // local col
            const int col = bn + cl;
            const float p10 = b1[col], p11 = b1[col + 1];
            const float p20 = b2[col], p21 = b2[col + 1];
            const long i0 = (long)row * U_ + col;
            const long i8 = (long)(row + 8) * U_ + col;
            float2 x0v, x8v;
            if (e2f) {
                x0v = *(const float2*)(e2f + i0);
                x8v = *(const float2*)(e2f + i8);
            } else {
                x0v = b2f(*(const bf162*)(e2b + i0));
                x8v = b2f(*(const bf162*)(e2b + i8));
            }
            float u0 = acc1[mt][nt][0] + p10, u1 = acc1[mt][nt][1] + p11;
            float u2 = acc1[mt][nt][2] + p10, u3 = acc1[mt][nt][3] + p11;
            float w0 = acc2[mt][nt][0] + p20, w1 = acc2[mt][nt][1] + p21;
            float w2 = acc2[mt][nt][2] + p20, w3v = acc2[mt][nt][3] + p21;
            if (mode == 0) {
                u0 = fmaxf(u0, 0.f); u1 = fmaxf(u1, 0.f);
                u2 = fmaxf(u2, 0.f); u3 = fmaxf(u3, 0.f);
                w0 = sigm(w0); w1 = sigm(w1); w2 = sigm(w2); w3v = sigm(w3v);
                const float o0 = u0 * w0 + x0v.x * (1.f - w0);
                const float o1 = u1 * w1 + x0v.y * (1.f - w1);
                const float o2 = u2 * w2 + x8v.x * (1.f - w2);
                const float o3 = u3 * w3v + x8v.y * (1.f - w3v);
                const bf162 pk0 = __floats2bfloat162_rn(o0, o1);
                const bf162 pk8 = __floats2bfloat162_rn(o2, o3);
                *(bf162*)(Xbout + i0) = pk0;
                *(bf162*)(Xbout + i8) = pk8;
                if (xw3o) {
                    const float2 wv = *(const float2*)(w3 + col);
                    *(bf162*)(xw3o + i0) = __floats2bfloat162_rn(o0 * wv.x, o1 * wv.y);
                    *(bf162*)(xw3o + i8) = __floats2bfloat162_rn(o2 * wv.x, o3 * wv.y);
                }
                if (x1to) {
                    stage[cl * TPITCH + rl]           = pk0.x;
                    stage[(cl + 1) * TPITCH + rl]     = pk0.y;
                    stage[cl * TPITCH + rl + 8]       = pk8.x;
                    stage[(cl + 1) * TPITCH + rl + 8] = pk8.y;
                }
                if (ps1) {
                    const float2 f0 = b2f(pk0), f8 = b2f(pk8);
                    s1r  += f0.x * w1v[nt].x + f0.y * w1v[nt].y;
                    s2r  += f0.x * w2v[nt].x + f0.y * w2v[nt].y;
                    s1r8 += f8.x * w1v[nt].x + f8.y * w1v[nt].y;
                    s2r8 += f8.x * w2v[nt].x + f8.y * w2v[nt].y;
                }
            } else {
                u0 = sigm(u0); u1 = sigm(u1); u2 = sigm(u2); u3 = sigm(u3);
                w0 = sigm(w0); w1 = sigm(w1); w2 = sigm(w2); w3v = sigm(w3v);
                const float o0 = w0 * x0v.x + u0 * u0;
                const float o1 = w1 * x0v.y + u1 * u1;
                const float o2 = w2 * x8v.x + u2 * u2;
                const float o3 = w3v * x8v.y + u3 * u3;
                *(float2*)(Xout + i0) = make_float2(o0, o1);
                *(float2*)(Xout + i8) = make_float2(o2, o3);
            }
        }
        if (mode == 0 && ps1) {
            #pragma unroll
            for (int msk = 1; msk <= 2; msk <<= 1) {
                s1r  += __shfl_xor_sync(0xffffffffu, s1r,  msk);
                s2r  += __shfl_xor_sync(0xffffffffu, s2r,  msk);
                s1r8 += __shfl_xor_sync(0xffffffffu, s1r8, msk);
                s2r8 += __shfl_xor_sync(0xffffffffu, s2r8, msk);
            }
            if (tig == 0) {
                pst[((wcol * 128 + rl)     << 1)]     = s1r;
                pst[((wcol * 128 + rl)     << 1) + 1] = s2r;
                pst[((wcol * 128 + rl + 8) << 1)]     = s1r8;
                pst[((wcol * 128 + rl + 8) << 1) + 1] = s2r8;
            }
        }
    }

    // ---- transposed write-out + partial reduce ----
    if (mode == 0 && (x1to || ps1)) {
        __syncthreads();
        if (x1to) {
            const int b0 = bm >> 10;         // batch (L_ = 1024)
            const int l0 = bm & 1023;
            const int cw = wid * 16;         // 16 cols per warp
            #pragma unroll
            for (int cc = 0; cc < 16; cc++) {
                const int c = cw + cc;
                const uint2 v = *(const uint2*)(stage + c * TPITCH + lane * 4);
                *(uint2*)(x1to + ((long)b0 * U_ + bn + c) * L_ + l0 + lane * 4) = v;
            }
        }
        if (ps1) {
            const int rl = tid >> 1, v = tid & 1;
            const float s = pst[((0 * 128 + rl) << 1) + v]
                          + pst[((1 * 128 + rl) << 1) + v]
                          + pst[((2 * 128 + rl) << 1) + v]
                          + pst[((3 * 128 + rl) << 1) + v];
            (v ? ps2 : ps1)[blockIdx.x * M_ + bm + rl] = s;
        }
    }
}

// ---------------------------------------------------------------------------
// Single bf16 GEMM (scores / att) with fragment double-buffering.
// ---------------------------------------------------------------------------
__global__ __launch_bounds__(256) void gemm_bf(
    const bf16* __restrict__ A,  long lda, long sA,
    const bf16* __restrict__ Bt, long ldb, long sB,
    bf16* __restrict__ Cb, long ldcb, long sCb,
    int K,
    const float* __restrict__ rowbias, long srb, int rbn,
    const float* __restrict__ colbias, long scb, int cbn,
    const float* __restrict__ addc,
    const float* __restrict__ rowscale, long srs, int rsn,
    int act,
    float* __restrict__ prow)
{
    extern __shared__ char smc[];
    const uint32_t as0 = smem_u32(smc);
    const uint32_t bs0 = as0 + NSTG * STAGE_B;

    const int tid  = threadIdx.x;
    const int wid  = tid >> 5;
    const int lane = tid & 31;
    const int li   = lane & 7;
    const int q    = lane >> 3;
    const int ql   = q & 1;
    const int qh   = q >> 1;
    const int m0   = (wid >> 2) * 64;
    const int n0   = (wid & 3)  * 32;

    const int bz = blockIdx.z;
    const int bm = blockIdx.y * 128;
    const int bn = blockIdx.x * 128;

    const bf16* Ag = A  + (long)bz * sA;
    const bf16* Bg = Bt + (long)bz * sB;

    const int lrow = tid >> 1;
    const int lcb  = (tid & 1) * 4;
    const int nch  = K / KC;

    float acc[4][4][4];
    #pragma unroll
    for (int i = 0; i < 4; i++)
        #pragma unroll
        for (int j = 0; j < 4; j++)
            #pragma unroll
            for (int k = 0; k < 4; k++) acc[i][j][k] = 0.f;

    auto load_chunk = [&](int c) {
        const int st = c % NSTG;
        const bf16* ap = Ag + (long)(bm + lrow) * lda + c * KC;
        const bf16* bp = Bg + (long)(bn + lrow) * ldb + c * KC;
        const uint32_t ad = as0 + st * STAGE_B + lrow * RB;
        const uint32_t bd = bs0 + st * STAGE_B + lrow * RB;
        const int sw = lrow & 7;
        #pragma unroll
        for (int j = 0; j < 4; j++) {
            const int ch = lcb + j;
            const int cho = (ch ^ sw) * 16;
            cpasync16(ad + cho, ap + ch * 8);
            cpasync16(bd + cho, bp + ch * 8);
        }
        CP_COMMIT();
    };

    load_chunk(0);
    if (nch > 1) load_chunk(1);

    int rA[4], nB[2];
    #pragma unroll
    for (int mt = 0; mt < 4; mt++) rA[mt] = m0 + mt * 16 + li + ql * 8;
    #pragma unroll
    for (int p = 0; p < 2; p++)    nB[p] = n0 + p * 16 + qh * 8 + li;

    for (int c = 0; c < nch; c++) {
        const int st = c % NSTG;
        if (c + 1 < nch) CP_WAIT(1); else CP_WAIT(0);
        __syncthreads();
        if (c + 2 < nch) load_chunk(c + 2);

        const uint32_t asb = as0 + st * STAGE_B;
        const uint32_t bsb = bs0 + st * STAGE_B;

        uint32_t afr[2][4][4], bfr[2][2][4];
        auto ld_frags = [&](int ks, int bu) {
            #pragma unroll
            for (int mt = 0; mt < 4; mt++) {
                const int r = rA[mt];
                const int ch = (ks * 2 + qh) ^ (r & 7);
                LDSM4(afr[bu][mt][0], afr[bu][mt][1], afr[bu][mt][2], afr[bu][mt][3],
                      asb + r * RB + ch * 16);
            }
            #pragma unroll
            for (int p = 0; p < 2; p++) {
                const int n = nB[p];
                const int ch = (ks * 2 + ql) ^ (n & 7);
                LDSM4(bfr[bu][p][0], bfr[bu][p][1], bfr[bu][p][2], bfr[bu][p][3],
                      bsb + n * RB + ch * 16);
            }
        };

        ld_frags(0, 0);
        #pragma unroll
        for (int ks = 0; ks < 4; ks++) {
            const int cur = ks & 1;
            if (ks < 3) ld_frags(ks + 1, cur ^ 1);
            #pragma unroll
            for (int nt = 0; nt < 4; nt++) {
                const uint32_t b0 = bfr[cur][nt >> 1][(nt & 1) * 2];
                const uint32_t b1 = bfr[cur][nt >> 1][(nt & 1) * 2 + 1];
                #pragma unroll
                for (int mt = 0; mt < 4; mt++)
                    mma_bf16(acc[mt][nt], afr[cur][mt], b0, b1);
            }
        }
    }

    const int grp = lane >> 2;
    const int tig = lane & 3;
    const int wcol = wid & 3;
    bf16* Cbp = Cb + (long)bz * sCb;
    float* pst = (float*)smc;                // [4][128] partial staging
    const float a0 = addc ? addc[0] : 0.f;

    // colbias precompute (independent of mt); inline partial-sum if cbn>1
    float cbv[4][2];
    #pragma unroll
    for (int nt = 0; nt < 4; nt++) {
        cbv[nt][0] = 0.f; cbv[nt][1] = 0.f;
        if (colbias) {
            const int col = bn + n0 + nt * 8 + tig * 2;
            const long base = (long)bz * scb + col;
            #pragma unroll
            for (int j = 0; j < 8; j++) {
                if (j < cbn) {
                    cbv[nt][0] += colbias[(long)j * M_ + base];
                    cbv[nt][1] += colbias[(long)j * M_ + base + 1];
                }
            }
        }
    }

    __syncthreads();   // mainloop smem reads done before pst reuse

    #pragma unroll
    for (int mt = 0; mt < 4; mt++) {
        const int rl  = m0 + mt * 16 + grp;
        const int row = bm + rl;
        float rb0 = a0, rb8 = a0;
        if (rowbias) {
            const long base = (long)bz * srb + row;
            #pragma unroll
            for (int j = 0; j < 8; j++) {
                if (j < rbn) {
                    rb0 += rowbias[(long)j * M_ + base];
                    rb8 += rowbias[(long)j * M_ + base + 8];
                }
            }
        }
        float sc0 = 1.f, sc8 = 1.f;
        if (rowscale) {
            const long base = (long)bz * srs + row;
            float t0 = 0.f, t8 = 0.f;
            #pragma unroll
            for (int j = 0; j < 8; j++) {
                if (j < rsn) {
                    t0 += rowscale[(long)j * M_ + base];
                    t8 += rowscale[(long)j * M_ + base + 8];
                }
            }
            sc0 = 1.f / t0;
            sc8 = 1.f / t8;
        }
        float sr = 0.f, sr8 = 0.f;
        #pragma unroll
        for (int nt = 0; nt < 4; nt++) {
            const int col = bn + n0 + nt * 8 + tig * 2;
            float v0 = acc[mt][nt][0] + rb0 + cbv[nt][0];
            float v1 = acc[mt][nt][1] + rb0 + cbv[nt][1];
            float v2 = acc[mt][nt][2] + rb8 + cbv[nt][0];
            float v3 = acc[mt][nt][3] + rb8 + cbv[nt][1];
            if (act == 3) {
                v0 = __expf(fmaxf(v0, 0.f)); v1 = __expf(fmaxf(v1, 0.f));
                v2 = __expf(fmaxf(v2, 0.f)); v3 = __expf(fmaxf(v3, 0.f));
            } else {
                v0 *= sc0; v1 *= sc0; v2 *= sc8; v3 *= sc8;
            }
            const bf162 pk0 = __floats2bfloat162_rn(v0, v1);
            const bf162 pk8 = __floats2bfloat162_rn(v2, v3);
            *(bf162*)(Cbp + (long)row * ldcb + col)       = pk0;
            *(bf162*)(Cbp + (long)(row + 8) * ldcb + col) = pk8;
            if (act == 3 && prow) {
                const float2 f0 = b2f(pk0), f8 = b2f(pk8);
                sr  += f0.x + f0.y;
                sr8 += f8.x + f8.y;
            }
        }
        if (act == 3 && prow) {
            #pragma unroll
            for (int msk = 1; msk <= 2; msk <<= 1) {
                sr  += __shfl_xor_sync(0xffffffffu, sr,  msk);
                sr8 += __shfl_xor_sync(0xffffffffu, sr8, msk);
            }
            if (tig == 0) {
                pst[wcol * 128 + rl]     = sr;
                pst[wcol * 128 + rl + 8] = sr8;
            }
        }
    }

    if (act == 3 && prow) {
        __syncthreads();
        if (tid < 128) {
            const float s = pst[tid] + pst[128 + tid]
                          + pst[256 + tid] + pst[384 + tid];
            prow[(long)blockIdx.x * M_ + (long)bz * L_ + bm + tid] = s;
        }
    }
}

// ---------------------------------------------------------------------------
// Merged prologue: conv_inputs (blocks 0..8191) + 4 weight transposes
// ---------------------------------------------------------------------------
__global__ __launch_bounds__(256) void prologue(
    const float* __restrict__ in, bf16* __restrict__ ib,
    const float* __restrict__ tW, bf16* __restrict__ tWt,
    const float* __restrict__ cW, bf16* __restrict__ cWt,
    const float* __restrict__ ffW, bf16* __restrict__ ffWt,
    const float* __restrict__ frW, bf16* __restrict__ frWt)
{
    const int bid = blockIdx.x;
    if (bid < 8192) {
        const int i = bid * 256 + threadIdx.x;     // over M*U/4
        const float4 v = ((const float4*)in)[i];
        *(bf162*)(ib + (long)i * 4)     = __floats2bfloat162_rn(v.x, v.y);
        *(bf162*)(ib + (long)i * 4 + 2) = __floats2bfloat162_rn(v.z, v.w);
        return;
    }
    __shared__ float tile[32][33];
    const int s = bid - 8192;
    const int job = s >> 9;
    const int r   = s & 511;
    const float* src; bf16* dst; int R, Cc, r0, c0;
    if (job < 2) {
        const int layer = r >> 8, w = r & 255;
        src = (job == 0 ? tW : cW) + (long)layer * U_ * U_;
        dst = (job == 0 ? tWt : cWt) + (long)layer * U_ * U_;
        R = U_; Cc = U_; c0 = (w & 15) * 32; r0 = (w >> 4) * 32;
    } else {
        src = (job == 2 ? ffW : frW);
        dst = (job == 2 ? ffWt : frWt);
        R = 2 * U_; Cc = U_; c0 = (r & 15) * 32; r0 = (r >> 4) * 32;
    }
    const int tx = threadIdx.x & 31, ty = threadIdx.x >> 5;
    #pragma unroll
    for (int i2 = 0; i2 < 32; i2 += 8)
        tile[ty + i2][tx] = src[(long)(r0 + ty + i2) * Cc + c0 + tx];
    __syncthreads();
    #pragma unroll
    for (int i2 = 0; i2 < 32; i2 += 8)
        dst[(long)(c0 + ty + i2) * R + r0 + tx] = __float2bfloat16(tile[tx][ty + i2]);
}

// ---------------------------------------------------------------------------
// Launch
// ---------------------------------------------------------------------------
#define GEMM_SMEM (2 * NSTG * STAGE_B)   // 96 KB  (single GEMM)
#define DUAL_SMEM (3 * NSTG * STAGE_B)   // 144 KB (dual GEMM)

extern "C" void kernel_launch(void* const* d_in, const int* in_sizes, int n_in,
                              void* d_out, int out_size)
{
    (void)in_sizes; (void)n_in; (void)out_size;
    const float* inputs = (const float*)d_in[0];
    const float* tW     = (const float*)d_in[1];
    const float* tb     = (const float*)d_in[2];
    const float* cW     = (const float*)d_in[3];
    const float* cb     = (const float*)d_in[4];
    const float* aW     = (const float*)d_in[5];
    const float* ab     = (const float*)d_in[6];
    const float* frW    = (const float*)d_in[7];
    const float* frb    = (const float*)d_in[8];
    const float* ffW    = (const float*)d_in[9];
    const float* ffb    = (const float*)d_in[10];
    float* out = (float*)d_out;

    float *ps1, *ps2, *pr;
    bf16 *ib, *x0b, *x1b, *xw3, *x1t, *att, *As, *tWt, *cWt, *ffWt, *frWt;
    cudaGetSymbolAddress((void**)&ps1,  g_ps1);
    cudaGetSymbolAddress((void**)&ps2,  g_ps2);
    cudaGetSymbolAddress((void**)&pr,   g_pr);
    cudaGetSymbolAddress((void**)&ib,   g_ib);
    cudaGetSymbolAddress((void**)&x0b,  g_x0b);
    cudaGetSymbolAddress((void**)&x1b,  g_x1b);
    cudaGetSymbolAddress((void**)&xw3,  g_xw3);
    cudaGetSymbolAddress((void**)&x1t,  g_x1t);
    cudaGetSymbolAddress((void**)&att,  g_att);
    cudaGetSymbolAddress((void**)&As,   g_As);
    cudaGetSymbolAddress((void**)&tWt,  g_tWt);
    cudaGetSymbolAddress((void**)&cWt,  g_cWt);
    cudaGetSymbolAddress((void**)&ffWt, g_ffWt);
    cudaGetSymbolAddress((void**)&frWt, g_frWt);

    cudaFuncSetAttribute(gemm_bf, cudaFuncAttributeMaxDynamicSharedMemorySize,
                         GEMM_SMEM);
    cudaFuncSetAttribute(gemm_dual, cudaFuncAttributeMaxDynamicSharedMemorySize,
                         DUAL_SMEM);

    // 1. merged prologue (inputs->bf16, 4 weight transposes)
    prologue<<<10240, 256>>>(inputs, ib, tW, tWt, cW, cWt,
                             ffW, ffWt, frW, frWt);

    dim3 gHW(U_/128, M_/128);      // (4,128)
    // 2. highway layer 0 (dual)
    gemm_dual<<<gHW, 256, DUAL_SMEM>>>(ib, nullptr, 64, tWt, cWt, U_,
                                       nullptr, x0b, inputs, nullptr, U_,
                                       tb, cb, 0, nullptr, nullptr, nullptr,
                                       nullptr, nullptr, nullptr);
    // 3. highway layer 1 (dual) + fused xw3, x1^T, s1/s2 partials
    gemm_dual<<<gHW, 256, DUAL_SMEM>>>(x0b, nullptr, 64, tWt + U_*U_, cWt + U_*U_, U_,
                                       nullptr, x1b, nullptr, x0b, U_,
                                       tb + U_, cb + U_, 0,
                                       aW + 2*U_, xw3, x1t,
                                       aW, ps1, ps2);

    // 4. scores: As[b] = exp(relu( xw3 @ x1^T + Σps1 + Σps2 + ab )) + rowsum partials
    dim3 gS(L_/128, L_/128, B_);
    gemm_bf<<<gS, 256, GEMM_SMEM>>>(xw3, U_, (long)L_*U_, x1b, U_, (long)L_*U_,
                                    As, L_, (long)L_*L_, U_,
                                    ps1, L_, 4, ps2, L_, 4, ab,
                                    nullptr, 0, 0, 3, pr);

    // 5. att = (expA @ x1) * (1/Σpr)[row] -> bf16 att [M,512]
    dim3 gAtt(U_/128, L_/128, B_);
    gemm_bf<<<gAtt, 256, GEMM_SMEM>>>(As, L_, (long)L_*L_, x1t, L_, (long)U_*L_,
                                      att, U_, (long)L_*U_, L_,
                                      nullptr, 0, 0, nullptr, 0, 0, nullptr,
                                      pr, L_, 8, 0, nullptr);

    // 6. final dual over implicit concat [ib | att]:
    //    out = sig(.@frW+frb)*inputs + sig(.@ffW+ffb)^2
    gemm_dual<<<gHW, 256, DUAL_SMEM>>>(ib, att, 8, ffWt, frWt, 2*U_,
                                       out, nullptr, inputs, nullptr, 2*U_,
                                       ffb, frb, 1, nullptr, nullptr, nullptr,
                                       nullptr, nullptr, nullptr);
}